// round 2
// baseline (speedup 1.0000x reference)
#include <cuda_runtime.h>
#include <math.h>

// ---------------------------------------------------------------------------
// BolmoLocalLayer: xLSTM mixer + SwiGLU MLP block.  B=2, S=2048, D=2048, H=8.
// Round 1: full fp32 implementation (correctness baseline + ncu roofline).
// ---------------------------------------------------------------------------

#define Bv   2
#define Sv   2048
#define Dv   2048
#define Hv   8
#define QKv  1024
#define DQK  128
#define DVv  256
#define FFv  8192
#define Mv   (Bv*Sv)      // 4096
#define BHv  (Bv*Hv)      // 16

// ----------------------------- scratch ------------------------------------
// One big static device buffer; offsets in floats.
#define OFF_HIN    ((size_t)0)
#define OFF_Q      (OFF_HIN   + (size_t)Mv*Dv)     // 8M
#define OFF_K      (OFF_Q     + (size_t)Mv*QKv)
#define OFF_V      (OFF_K     + (size_t)Mv*QKv)
#define OFF_OPRE   (OFF_V     + (size_t)Mv*Dv)
#define OFF_H      (OFF_OPRE  + (size_t)Mv*Dv)
#define OFF_HOUT   (OFF_H     + (size_t)Mv*Dv)
#define OFF_X1     (OFF_HOUT  + (size_t)Mv*Dv)
#define OFF_H2     (OFF_X1    + (size_t)Mv*Dv)
#define OFF_GATE   (OFF_H2    + (size_t)Mv*Dv)
#define OFF_ACT    (OFF_GATE  + (size_t)Mv*FFv)
#define OFF_IPRE   (OFF_ACT   + (size_t)Mv*FFv)
#define OFF_FPRE   (OFF_IPRE  + (size_t)BHv*Sv)
#define OFF_A      (OFF_FPRE  + (size_t)BHv*Sv)
#define OFF_G      (OFF_A     + (size_t)BHv*Sv)
#define OFF_NFL    (OFF_G     + (size_t)BHv*Sv)
#define SCRATCH_FLOATS (OFF_NFL + (size_t)BHv*Sv)

__device__ float g_scratch[SCRATCH_FLOATS];

// --------------------------- RMSNorm --------------------------------------
__global__ void rmsnorm_kernel(const float* __restrict__ x,
                               const float* __restrict__ w,
                               float* __restrict__ out)
{
    int row = blockIdx.x;
    int tid = threadIdx.x;
    const float4* xr = (const float4*)(x + (size_t)row * Dv);
    float4 v0 = xr[tid];
    float4 v1 = xr[tid + 256];
    float ss = v0.x*v0.x + v0.y*v0.y + v0.z*v0.z + v0.w*v0.w
             + v1.x*v1.x + v1.y*v1.y + v1.z*v1.z + v1.w*v1.w;
    #pragma unroll
    for (int o = 16; o > 0; o >>= 1) ss += __shfl_xor_sync(0xffffffffu, ss, o);
    __shared__ float red[8];
    int wp = tid >> 5, lane = tid & 31;
    if (lane == 0) red[wp] = ss;
    __syncthreads();
    float tot = 0.f;
    #pragma unroll
    for (int i = 0; i < 8; i++) tot += red[i];
    float inv = rsqrtf(tot * (1.f / Dv) + 1e-6f);
    const float4* wr = (const float4*)w;
    float4* o4 = (float4*)(out + (size_t)row * Dv);
    float4 w0 = wr[tid], w1 = wr[tid + 256];
    float4 r0 = make_float4(v0.x*inv*w0.x, v0.y*inv*w0.y, v0.z*inv*w0.z, v0.w*inv*w0.w);
    float4 r1 = make_float4(v1.x*inv*w1.x, v1.y*inv*w1.y, v1.z*inv*w1.z, v1.w*inv*w1.w);
    o4[tid] = r0;
    o4[tid + 256] = r1;
}

// --------------------------- SGEMM ----------------------------------------
// C[M,N] = epilogue(A[M,K] @ B[K,N]); A,B,C row-major. M%128==0, N%128==0, K%16==0.
// EPI: 0 none, 1 C = aux + AB, 2 C = silu(aux) * AB
template<int EPI>
__global__ void __launch_bounds__(256) sgemm_kernel(
    const float* __restrict__ A, const float* __restrict__ B,
    const float* __restrict__ aux, float* __restrict__ C,
    int M, int N, int K)
{
    __shared__ float As[16][128];
    __shared__ float Bs[16][128];
    int tid = threadIdx.x;
    int tx = tid & 15, ty = tid >> 4;
    int brow = blockIdx.y * 128, bcol = blockIdx.x * 128;
    const float* Ab = A + (size_t)brow * K;
    const float* Bb = B + bcol;

    float acc[8][8];
    #pragma unroll
    for (int i = 0; i < 8; i++)
        #pragma unroll
        for (int j = 0; j < 8; j++) acc[i][j] = 0.f;

    int a_r = tid >> 1;           // 0..127
    int a_c = (tid & 1) * 2;      // float4 col base {0,2}

    for (int kt = 0; kt < K; kt += 16) {
        #pragma unroll
        for (int i = 0; i < 2; i++) {
            float4 av = *(const float4*)(Ab + (size_t)a_r * K + kt + (a_c + i) * 4);
            As[(a_c + i) * 4 + 0][a_r] = av.x;
            As[(a_c + i) * 4 + 1][a_r] = av.y;
            As[(a_c + i) * 4 + 2][a_r] = av.z;
            As[(a_c + i) * 4 + 3][a_r] = av.w;
        }
        #pragma unroll
        for (int i = 0; i < 2; i++) {
            int f4 = tid * 2 + i;
            int br = f4 >> 5, bc = (f4 & 31) * 4;
            *(float4*)&Bs[br][bc] = *(const float4*)(Bb + (size_t)(kt + br) * N + bc);
        }
        __syncthreads();
        #pragma unroll
        for (int k = 0; k < 16; k++) {
            float ar[8], br_[8];
            *(float4*)&ar[0]  = *(float4*)&As[k][ty * 4];
            *(float4*)&ar[4]  = *(float4*)&As[k][64 + ty * 4];
            *(float4*)&br_[0] = *(float4*)&Bs[k][tx * 4];
            *(float4*)&br_[4] = *(float4*)&Bs[k][64 + tx * 4];
            #pragma unroll
            for (int i = 0; i < 8; i++)
                #pragma unroll
                for (int j = 0; j < 8; j++)
                    acc[i][j] += ar[i] * br_[j];
        }
        __syncthreads();
    }

    #pragma unroll
    for (int i = 0; i < 8; i++) {
        int r = brow + ((i < 4) ? (ty * 4 + i) : (64 + ty * 4 + i - 4));
        #pragma unroll
        for (int jh = 0; jh < 2; jh++) {
            int c = bcol + jh * 64 + tx * 4;
            size_t idx = (size_t)r * N + c;
            float4 o;
            o.x = acc[i][jh * 4 + 0];
            o.y = acc[i][jh * 4 + 1];
            o.z = acc[i][jh * 4 + 2];
            o.w = acc[i][jh * 4 + 3];
            if (EPI == 1) {
                float4 a4 = *(const float4*)(aux + idx);
                o.x += a4.x; o.y += a4.y; o.z += a4.z; o.w += a4.w;
            } else if (EPI == 2) {
                float4 g4 = *(const float4*)(aux + idx);
                o.x *= g4.x / (1.f + __expf(-g4.x));
                o.y *= g4.y / (1.f + __expf(-g4.y));
                o.z *= g4.z / (1.f + __expf(-g4.z));
                o.w *= g4.w / (1.f + __expf(-g4.w));
            }
            *(float4*)(C + idx) = o;
        }
    }
}

// --------------------------- i/f gate projections --------------------------
__device__ __forceinline__ float softcap15(float x) {
    return 15.f * tanhf(x * (1.f / 15.f));
}

__global__ void gates_kernel(const float* __restrict__ hin,
                             const float* __restrict__ w_ig, const float* __restrict__ b_ig,
                             const float* __restrict__ w_fg, const float* __restrict__ b_fg,
                             float* __restrict__ ipre, float* __restrict__ fpre)
{
    int row = blockIdx.x;            // 0..Mv-1
    int tid = threadIdx.x;           // 256
    float pi[8], pf[8];
    #pragma unroll
    for (int h = 0; h < 8; h++) { pi[h] = 0.f; pf[h] = 0.f; }
    const float* xr = hin + (size_t)row * Dv;
    for (int d = tid; d < Dv; d += 256) {
        float xv = xr[d];
        #pragma unroll
        for (int h = 0; h < 8; h++) {
            pi[h] += xv * w_ig[d * 8 + h];
            pf[h] += xv * w_fg[d * 8 + h];
        }
    }
    #pragma unroll
    for (int h = 0; h < 8; h++) {
        #pragma unroll
        for (int o = 16; o > 0; o >>= 1) {
            pi[h] += __shfl_xor_sync(0xffffffffu, pi[h], o);
            pf[h] += __shfl_xor_sync(0xffffffffu, pf[h], o);
        }
    }
    __shared__ float sred[8][16];
    int wp = tid >> 5, lane = tid & 31;
    if (lane == 0) {
        #pragma unroll
        for (int h = 0; h < 8; h++) { sred[wp][h] = pi[h]; sred[wp][8 + h] = pf[h]; }
    }
    __syncthreads();
    if (tid < 16) {
        float s = 0.f;
        #pragma unroll
        for (int w8 = 0; w8 < 8; w8++) s += sred[w8][tid];
        int h = tid & 7;
        bool isf = (tid >= 8);
        float bias = isf ? b_fg[h] : b_ig[h];
        float val = softcap15(s + bias);
        int b = row >> 11;           // / Sv
        int sp = row & (Sv - 1);
        int bh = b * Hv + h;
        (isf ? fpre : ipre)[bh * Sv + sp] = val;
    }
}

// --------------------------- gate scans ------------------------------------
// Per (b,h): Fcum = cumsum(logsigmoid(f)); a = i - Fcum; G = cummax(a);
// nfloor = exp(-(Fcum+G)) = exp(-m).
__global__ void scan_kernel(const float* __restrict__ ipre, const float* __restrict__ fpre,
                            float* __restrict__ aout, float* __restrict__ Gout,
                            float* __restrict__ nflout)
{
    int bh = blockIdx.x;
    int tid = threadIdx.x;           // 1024
    __shared__ float bufA[2048], bufB[2048], fc[2048];

    for (int i = tid; i < 2048; i += 1024) {
        float f = fpre[bh * Sv + i];
        bufA[i] = fminf(f, 0.f) - log1pf(expf(-fabsf(f)));   // log sigmoid
    }
    __syncthreads();
    float* src = bufA; float* dst = bufB;
    for (int off = 1; off < 2048; off <<= 1) {
        for (int i = tid; i < 2048; i += 1024)
            dst[i] = src[i] + ((i >= off) ? src[i - off] : 0.f);
        __syncthreads();
        float* t = src; src = dst; dst = t;
    }
    for (int i = tid; i < 2048; i += 1024) fc[i] = src[i];
    __syncthreads();
    for (int i = tid; i < 2048; i += 1024) {
        float a = ipre[bh * Sv + i] - fc[i];
        aout[bh * Sv + i] = a;
        dst[i] = a;                       // dst is the free buffer
    }
    __syncthreads();
    { float* t = src; src = dst; dst = t; }   // src now holds 'a'
    for (int off = 1; off < 2048; off <<= 1) {
        for (int i = tid; i < 2048; i += 1024)
            dst[i] = fmaxf(src[i], (i >= off) ? src[i - off] : -1e30f);
        __syncthreads();
        float* t = src; src = dst; dst = t;
    }
    for (int i = tid; i < 2048; i += 1024) {
        float G = src[i];
        Gout[bh * Sv + i] = G;
        nflout[bh * Sv + i] = expf(-(fc[i] + G));
    }
}

// --------------------------- mLSTM attention -------------------------------
// One block per (bh, 64-row tile). weight(t,s) = exp(a[s]-G[t]); scores already
// max-stabilized, so single pass, no rescale. h = P.V / max(|rowsum|, exp(-m)).
#define ATT_SMEM_FLOATS (64*129 + 64*129 + 64*260 + 64*72 + 4*64)
#define ATT_SMEM_BYTES  (ATT_SMEM_FLOATS * 4)

__global__ void __launch_bounds__(256, 1) attn_kernel(
    const float* __restrict__ q, const float* __restrict__ k, const float* __restrict__ v,
    const float* __restrict__ av, const float* __restrict__ Gv, const float* __restrict__ nfv,
    float* __restrict__ hout)
{
    extern __shared__ float sm[];
    float* qs     = sm;                 // [64][129]
    float* ks     = qs + 64 * 129;      // [64][129]
    float* vs     = ks + 64 * 129;      // [64][260]
    float* sct    = vs + 64 * 260;      // [64][72] transposed scores
    float* rowsum = sct + 64 * 72;      // [64]
    float* Gt     = rowsum + 64;        // [64]
    float* nfl    = Gt + 64;            // [64]
    float* aly    = nfl + 64;           // [64]

    int bh = blockIdx.y;
    int bb = bh >> 3, hh = bh & 7;
    int t0 = blockIdx.x * 64;
    int tid = threadIdx.x, tx = tid & 15, ty = tid >> 4;

    // load Q tile (row-major, padded)
    const float* qbase = q + ((size_t)(bb * Sv + t0)) * QKv + hh * DQK;
    #pragma unroll
    for (int j = 0; j < 8; j++) {
        int f4 = tid + 256 * j;
        int r = f4 >> 5, d4 = f4 & 31;
        float4 qv = *(const float4*)(qbase + (size_t)r * QKv + d4 * 4);
        float* dst = &qs[r * 129 + d4 * 4];
        dst[0] = qv.x; dst[1] = qv.y; dst[2] = qv.z; dst[3] = qv.w;
    }
    if (tid < 64) {
        rowsum[tid] = 0.f;
        Gt[tid]  = Gv[bh * Sv + t0 + tid];
        nfl[tid] = nfv[bh * Sv + t0 + tid];
    }

    float acc[4][16];
    #pragma unroll
    for (int i = 0; i < 4; i++)
        #pragma unroll
        for (int j = 0; j < 16; j++) acc[i][j] = 0.f;

    int nst = (t0 >> 6) + 1;
    for (int st = 0; st < nst; st++) {
        int s0 = st << 6;
        __syncthreads();
        const float* kbase = k + ((size_t)(bb * Sv + s0)) * QKv + hh * DQK;
        #pragma unroll
        for (int j = 0; j < 8; j++) {
            int f4 = tid + 256 * j;
            int r = f4 >> 5, d4 = f4 & 31;
            float4 kv4 = *(const float4*)(kbase + (size_t)r * QKv + d4 * 4);
            float* dst = &ks[r * 129 + d4 * 4];
            dst[0] = kv4.x; dst[1] = kv4.y; dst[2] = kv4.z; dst[3] = kv4.w;
        }
        const float* vbase = v + ((size_t)(bb * Sv + s0)) * Dv + hh * DVv;
        #pragma unroll
        for (int j = 0; j < 16; j++) {
            int f4 = tid + 256 * j;
            int r = f4 >> 6, c4 = f4 & 63;
            *(float4*)&vs[r * 260 + c4 * 4] = *(const float4*)(vbase + (size_t)r * Dv + c4 * 4);
        }
        if (tid < 64) aly[tid] = av[bh * Sv + s0 + tid];
        __syncthreads();

        // scores: 4x4 microtile per thread
        float sc[4][4];
        #pragma unroll
        for (int i = 0; i < 4; i++)
            #pragma unroll
            for (int j = 0; j < 4; j++) sc[i][j] = 0.f;
        const float* qrow = &qs[(ty * 4) * 129];
        const float* krow = &ks[(tx * 4) * 129];
        #pragma unroll 4
        for (int kk = 0; kk < 128; kk++) {
            float a0 = qrow[kk], a1 = qrow[129 + kk], a2 = qrow[258 + kk], a3 = qrow[387 + kk];
            float b0 = krow[kk], b1 = krow[129 + kk], b2 = krow[258 + kk], b3 = krow[387 + kk];
            sc[0][0] += a0 * b0; sc[0][1] += a0 * b1; sc[0][2] += a0 * b2; sc[0][3] += a0 * b3;
            sc[1][0] += a1 * b0; sc[1][1] += a1 * b1; sc[1][2] += a1 * b2; sc[1][3] += a1 * b3;
            sc[2][0] += a2 * b0; sc[2][1] += a2 * b1; sc[2][2] += a2 * b2; sc[2][3] += a2 * b3;
            sc[3][0] += a3 * b0; sc[3][1] += a3 * b1; sc[3][2] += a3 * b2; sc[3][3] += a3 * b3;
        }
        bool diag = (st == nst - 1);
        const float invsq = 0.08838834764831845f;  // 1/sqrt(128)
        #pragma unroll
        for (int i = 0; i < 4; i++) {
            int rloc = ty * 4 + i;
            int tg = t0 + rloc;
            float gt = Gt[rloc];
            float rs = 0.f;
            #pragma unroll
            for (int j = 0; j < 4; j++) {
                int sg = s0 + tx * 4 + j;
                float val;
                if (!diag || sg <= tg) {
                    float w = __expf(aly[tx * 4 + j] - gt) * invsq;
                    val = sc[i][j] * w;
                } else {
                    val = 0.f;
                }
                sc[i][j] = val;
                rs += val;
            }
            atomicAdd(&rowsum[rloc], rs);
        }
        #pragma unroll
        for (int j = 0; j < 4; j++) {
            float4 t4 = make_float4(sc[0][j], sc[1][j], sc[2][j], sc[3][j]);
            *(float4*)&sct[(tx * 4 + j) * 72 + ty * 4] = t4;
        }
        __syncthreads();

        // acc += P @ V  (rows 4*ty.., cols tx*4 + 64*jg)
        #pragma unroll 4
        for (int s = 0; s < 64; s++) {
            float4 p = *(float4*)&sct[s * 72 + ty * 4];
            float pr[4] = {p.x, p.y, p.z, p.w};
            #pragma unroll
            for (int jg = 0; jg < 4; jg++) {
                float4 vv = *(float4*)&vs[s * 260 + jg * 64 + tx * 4];
                #pragma unroll
                for (int i = 0; i < 4; i++) {
                    acc[i][jg * 4 + 0] += pr[i] * vv.x;
                    acc[i][jg * 4 + 1] += pr[i] * vv.y;
                    acc[i][jg * 4 + 2] += pr[i] * vv.z;
                    acc[i][jg * 4 + 3] += pr[i] * vv.w;
                }
            }
        }
    }
    __syncthreads();

    float* ho = hout + ((size_t)(bb * Sv + t0)) * Dv + hh * DVv;
    #pragma unroll
    for (int i = 0; i < 4; i++) {
        int r = ty * 4 + i;
        float n = fmaxf(fabsf(rowsum[r]), nfl[r]);
        float inv = 1.f / n;
        #pragma unroll
        for (int jg = 0; jg < 4; jg++) {
            float4 o = make_float4(acc[i][jg * 4 + 0] * inv, acc[i][jg * 4 + 1] * inv,
                                   acc[i][jg * 4 + 2] * inv, acc[i][jg * 4 + 3] * inv);
            *(float4*)(ho + (size_t)r * Dv + jg * 64 + tx * 4) = o;
        }
    }
}

// --------------------- per-head RMSNorm + output gate -----------------------
__global__ void headnorm_kernel(const float* __restrict__ h, const float* __restrict__ opre,
                                const float* __restrict__ mh_w, float* __restrict__ hout)
{
    int row = blockIdx.x;
    int tid = threadIdx.x;
    int wp = tid >> 5, lane = tid & 31;       // warp = head
    const float* hr = h + (size_t)row * Dv + wp * DVv;
    float vv[8];
    float ss = 0.f;
    #pragma unroll
    for (int j = 0; j < 8; j++) { vv[j] = hr[lane + 32 * j]; ss += vv[j] * vv[j]; }
    #pragma unroll
    for (int o = 16; o > 0; o >>= 1) ss += __shfl_xor_sync(0xffffffffu, ss, o);
    float inv = rsqrtf(ss * (1.f / DVv) + 1e-6f);
    const float* op = opre + (size_t)row * Dv + wp * DVv;
    const float* mw = mh_w + wp * DVv;
    float* outp = hout + (size_t)row * Dv + wp * DVv;
    #pragma unroll
    for (int j = 0; j < 8; j++) {
        int c = lane + 32 * j;
        float o = op[c];
        float sg = 1.f / (1.f + expf(-o));
        outp[c] = sg * vv[j] * inv * mw[c];
    }
}

// --------------------------- launch ----------------------------------------
extern "C" void kernel_launch(void* const* d_in, const int* in_sizes, int n_in,
                              void* d_out, int out_size)
{
    const float* x       = (const float*)d_in[0];
    const float* norm1_w = (const float*)d_in[1];
    const float* wq      = (const float*)d_in[2];
    const float* wk      = (const float*)d_in[3];
    const float* wv      = (const float*)d_in[4];
    const float* w_ig    = (const float*)d_in[5];
    const float* b_ig    = (const float*)d_in[6];
    const float* w_fg    = (const float*)d_in[7];
    const float* b_fg    = (const float*)d_in[8];
    const float* w_og    = (const float*)d_in[9];
    const float* mh_w    = (const float*)d_in[10];
    const float* w_out   = (const float*)d_in[11];
    const float* norm2_w = (const float*)d_in[12];
    const float* w_gate  = (const float*)d_in[13];
    const float* w_up    = (const float*)d_in[14];
    const float* w_down  = (const float*)d_in[15];
    float* out = (float*)d_out;

    void* sp = nullptr;
    cudaGetSymbolAddress(&sp, g_scratch);
    float* S = (float*)sp;
    float* hin  = S + OFF_HIN;
    float* qb   = S + OFF_Q;
    float* kb   = S + OFF_K;
    float* vb   = S + OFF_V;
    float* opre = S + OFF_OPRE;
    float* hb   = S + OFF_H;
    float* houtb= S + OFF_HOUT;
    float* x1   = S + OFF_X1;
    float* h2   = S + OFF_H2;
    float* gate = S + OFF_GATE;
    float* act  = S + OFF_ACT;
    float* ipre = S + OFF_IPRE;
    float* fpre = S + OFF_FPRE;
    float* ab   = S + OFF_A;
    float* Gb   = S + OFF_G;
    float* nfl  = S + OFF_NFL;

    cudaFuncSetAttribute(attn_kernel, cudaFuncAttributeMaxDynamicSharedMemorySize,
                         ATT_SMEM_BYTES);

    // 1. pre-norm
    rmsnorm_kernel<<<Mv, 256>>>(x, norm1_w, hin);
    // 2-5. projections
    sgemm_kernel<0><<<dim3(QKv/128, Mv/128), 256>>>(hin, wq, nullptr, qb, Mv, QKv, Dv);
    sgemm_kernel<0><<<dim3(QKv/128, Mv/128), 256>>>(hin, wk, nullptr, kb, Mv, QKv, Dv);
    sgemm_kernel<0><<<dim3(Dv/128,  Mv/128), 256>>>(hin, wv, nullptr, vb, Mv, Dv,  Dv);
    sgemm_kernel<0><<<dim3(Dv/128,  Mv/128), 256>>>(hin, w_og, nullptr, opre, Mv, Dv, Dv);
    // 6. input/forget gate pre-activations (+softcap)
    gates_kernel<<<Mv, 256>>>(hin, w_ig, b_ig, w_fg, b_fg, ipre, fpre);
    // 7. per-(b,h) scans: Fcum, a, G, exp(-m)
    scan_kernel<<<BHv, 1024>>>(ipre, fpre, ab, Gb, nfl);
    // 8. mLSTM attention
    attn_kernel<<<dim3(Sv/64, BHv), 256, ATT_SMEM_BYTES>>>(qb, kb, vb, ab, Gb, nfl, hb);
    // 9. per-head norm + output gate
    headnorm_kernel<<<Mv, 256>>>(hb, opre, mh_w, houtb);
    // 10. x1 = x + h_out @ w_out
    sgemm_kernel<1><<<dim3(Dv/128, Mv/128), 256>>>(houtb, w_out, x, x1, Mv, Dv, Dv);
    // 11. second pre-norm
    rmsnorm_kernel<<<Mv, 256>>>(x1, norm2_w, h2);
    // 12. gate branch
    sgemm_kernel<0><<<dim3(FFv/128, Mv/128), 256>>>(h2, w_gate, nullptr, gate, Mv, FFv, Dv);
    // 13. up branch fused with silu(gate)*up
    sgemm_kernel<2><<<dim3(FFv/128, Mv/128), 256>>>(h2, w_up, gate, act, Mv, FFv, Dv);
    // 14. out = x1 + act @ w_down
    sgemm_kernel<1><<<dim3(Dv/128, Mv/128), 256>>>(act, w_down, x1, out, Mv, Dv, FFv);

    (void)in_sizes; (void)n_in; (void)out_size;
}

// round 4
// speedup vs baseline: 2.0560x; 2.0560x over previous
#include <cuda_runtime.h>
#include <cuda_fp16.h>
#include <math.h>
#include <stdint.h>

// ---------------------------------------------------------------------------
// BolmoLocalLayer: xLSTM mixer + SwiGLU MLP.  B=2, S=2048, D=2048, H=8.
// Round 3: dense GEMMs on mma.sync HMMA (fp16 hi/lo split, 3 products, fp32
// accum).  tcgen05 unavailable: harness PTX target is plain sm_103.
// ---------------------------------------------------------------------------

#define Bv   2
#define Sv   2048
#define Dv   2048
#define Hv   8
#define QKv  1024
#define DQK  128
#define DVv  256
#define FFv  8192
#define Mv   (Bv*Sv)      // 4096
#define BHv  (Bv*Hv)      // 16

// ----------------------------- fp32 scratch --------------------------------
#define F_HIN   ((size_t)0)
#define F_Q     (F_HIN  + (size_t)Mv*Dv)
#define F_K     (F_Q    + (size_t)Mv*QKv)
#define F_V     (F_K    + (size_t)Mv*QKv)
#define F_OPRE  (F_V    + (size_t)Mv*Dv)
#define F_H     (F_OPRE + (size_t)Mv*Dv)
#define F_X1    (F_H    + (size_t)Mv*Dv)
#define F_GATE  (F_X1   + (size_t)Mv*Dv)
#define F_IPRE  (F_GATE + (size_t)Mv*FFv)
#define F_FPRE  (F_IPRE + (size_t)BHv*Sv)
#define F_A     (F_FPRE + (size_t)BHv*Sv)
#define F_G     (F_A    + (size_t)BHv*Sv)
#define F_NFL   (F_G    + (size_t)BHv*Sv)
#define F_TOTAL (F_NFL  + (size_t)BHv*Sv)
__device__ float g_f32[F_TOTAL];

// ----------------------------- fp16 scratch --------------------------------
#define P_HINH  ((size_t)0)
#define P_HINL  (P_HINH  + (size_t)Mv*Dv)
#define P_HOUTH (P_HINL  + (size_t)Mv*Dv)
#define P_HOUTL (P_HOUTH + (size_t)Mv*Dv)
#define P_H2H   (P_HOUTL + (size_t)Mv*Dv)
#define P_H2L   (P_H2H   + (size_t)Mv*Dv)
#define P_ACTH  (P_H2L   + (size_t)Mv*Dv)
#define P_ACTL  (P_ACTH  + (size_t)Mv*FFv)
#define P_WQH   (P_ACTL  + (size_t)Mv*FFv)
#define P_WQL   (P_WQH   + (size_t)QKv*Dv)
#define P_WKH   (P_WQL   + (size_t)QKv*Dv)
#define P_WKL   (P_WKH   + (size_t)QKv*Dv)
#define P_WVH   (P_WKL   + (size_t)QKv*Dv)
#define P_WVL   (P_WVH   + (size_t)Dv*Dv)
#define P_WOGH  (P_WVL   + (size_t)Dv*Dv)
#define P_WOGL  (P_WOGH  + (size_t)Dv*Dv)
#define P_WOUTH (P_WOGL  + (size_t)Dv*Dv)
#define P_WOUTL (P_WOUTH + (size_t)Dv*Dv)
#define P_WGH   (P_WOUTL + (size_t)Dv*Dv)
#define P_WGL   (P_WGH   + (size_t)FFv*Dv)
#define P_WUH   (P_WGL   + (size_t)FFv*Dv)
#define P_WUL   (P_WUH   + (size_t)FFv*Dv)
#define P_WDH   (P_WUL   + (size_t)FFv*Dv)
#define P_WDL   (P_WDH   + (size_t)Dv*FFv)
#define P_TOTAL (P_WDL   + (size_t)Dv*FFv)
__device__ __half g_fp16[P_TOTAL];

// ----------------------------- helpers -------------------------------------
__device__ __forceinline__ uint32_t smem_u32(const void* p) {
    uint32_t a;
    asm("{ .reg .u64 t; cvta.to.shared.u64 t, %1; cvt.u32.u64 %0, t; }"
        : "=r"(a) : "l"(p));
    return a;
}

__device__ __forceinline__ void cp16(uint32_t sa, const void* g) {
    asm volatile("cp.async.ca.shared.global [%0], [%1], 16;"
                 :: "r"(sa), "l"(g) : "memory");
}
#define CP_COMMIT() asm volatile("cp.async.commit_group;" ::: "memory")
#define CP_WAIT1()  asm volatile("cp.async.wait_group 1;" ::: "memory")
#define CP_WAIT0()  asm volatile("cp.async.wait_group 0;" ::: "memory")

__device__ __forceinline__ void ldsm4(uint32_t* r, uint32_t addr) {
    asm volatile("ldmatrix.sync.aligned.m8n8.x4.shared.b16 {%0,%1,%2,%3}, [%4];"
                 : "=r"(r[0]), "=r"(r[1]), "=r"(r[2]), "=r"(r[3]) : "r"(addr));
}

__device__ __forceinline__ void mma16816(float* c, const uint32_t* a,
                                         uint32_t b0, uint32_t b1) {
    asm volatile(
        "mma.sync.aligned.m16n8k16.row.col.f32.f16.f16.f32 "
        "{%0,%1,%2,%3}, {%4,%5,%6,%7}, {%8,%9}, {%0,%1,%2,%3};"
        : "+f"(c[0]), "+f"(c[1]), "+f"(c[2]), "+f"(c[3])
        : "r"(a[0]), "r"(a[1]), "r"(a[2]), "r"(a[3]), "r"(b0), "r"(b1));
}

__device__ __forceinline__ void split_h(float v, __half& hi, __half& lo) {
    hi = __float2half_rn(v);
    lo = __float2half_rn(v - __half2float(hi));
}

// --------------------------- HMMA GEMM -------------------------------------
// C[M, N] = epilogue(A @ W).  A: fp16 hi/lo [M][K] K-major.
// W: fp16 hi/lo pre-transposed [N][K] K-major.
// EPI 0: C fp32 = acc.   EPI 1: C fp32 = aux + acc.
// EPI 2: (CH,CL) fp16 = split(silu(aux) * acc).
#define KCH   32                      // K per chunk
#define RSTR  40                      // smem row stride in halves (pad 8)
#define TILEB (128*RSTR*2)            // 10240 B per operand tile
#define STAGEB (4*TILEB)              // 40960 B per stage
#define GSMEM (2*STAGEB)              // 81920 B

template<int EPI>
__global__ void __launch_bounds__(256) tgemm_kernel(
    const __half* __restrict__ AH, const __half* __restrict__ AL,
    const __half* __restrict__ BH, const __half* __restrict__ BL,
    const float* __restrict__ aux, float* __restrict__ C,
    __half* __restrict__ CH, __half* __restrict__ CL,
    int N, int K)
{
    extern __shared__ char smem[];
    const uint32_t sb = smem_u32(smem);
    const int tid = threadIdx.x;
    const int lane = tid & 31;
    const int wid = tid >> 5;
    const int wm = wid & 3;           // warp m group (32 rows)
    const int wn = wid >> 2;          // warp n group (64 cols)
    const int m0 = blockIdx.y * 128;
    const int n0 = blockIdx.x * 128;

    const __half* src[4] = { AH + (size_t)m0 * K, AL + (size_t)m0 * K,
                             BH + (size_t)n0 * K, BL + (size_t)n0 * K };

    float acc[2][8][4];
    #pragma unroll
    for (int i = 0; i < 2; i++)
        #pragma unroll
        for (int j = 0; j < 8; j++)
            #pragma unroll
            for (int e = 0; e < 4; e++) acc[i][j][e] = 0.f;

    const int NC = K / KCH;

    auto load_chunk = [&](int c, int s) {
        #pragma unroll
        for (int t = 0; t < 4; t++) {
            #pragma unroll
            for (int i = 0; i < 2; i++) {
                int seg = tid * 2 + i;
                int row = seg >> 2, s4 = seg & 3;
                const __half* g = src[t] + (size_t)row * K + c * KCH + s4 * 8;
                uint32_t sa = sb + (uint32_t)(s * STAGEB + t * TILEB + row * (RSTR*2) + s4 * 16);
                cp16(sa, g);
            }
        }
    };

    load_chunk(0, 0); CP_COMMIT();
    load_chunk(1, 1); CP_COMMIT();

    // ldmatrix lane addressing (precompute offsets)
    const int a_r = (lane & 15);            // row within 16
    const int a_k = (lane >> 4) * 8;        // k offset 0/8
    const int b_r = (lane & 7) + (lane >> 4) * 8;   // row within 16 (two n8 tiles)
    const int b_k = ((lane >> 3) & 1) * 8;

    for (int c = 0; c < NC; c++) {
        const int s = c & 1;
        if (c + 1 < NC) CP_WAIT1(); else CP_WAIT0();
        __syncthreads();

        const uint32_t bAh = sb + s * STAGEB;
        const uint32_t bAl = bAh + TILEB;
        const uint32_t bBh = bAh + 2 * TILEB;
        const uint32_t bBl = bAh + 3 * TILEB;

        #pragma unroll
        for (int kk = 0; kk < KCH; kk += 16) {
            uint32_t aH[2][4], aL[2][4], bf[4][4];
            #pragma unroll
            for (int mt = 0; mt < 2; mt++) {
                int row = wm * 32 + mt * 16 + a_r;
                uint32_t off = (uint32_t)(row * (RSTR*2) + (kk + a_k) * 2);
                ldsm4(aH[mt], bAh + off);
                ldsm4(aL[mt], bAl + off);
            }
            #pragma unroll
            for (int j = 0; j < 4; j++) {
                int row = wn * 64 + j * 16 + b_r;
                uint32_t off = (uint32_t)(row * (RSTR*2) + (kk + b_k) * 2);
                ldsm4(bf[j], bBh + off);
            }
            // pass 1: Ah * Bh ; pass 2: Al * Bh
            #pragma unroll
            for (int mt = 0; mt < 2; mt++)
                #pragma unroll
                for (int j = 0; j < 4; j++) {
                    mma16816(acc[mt][2*j],   aH[mt], bf[j][0], bf[j][1]);
                    mma16816(acc[mt][2*j+1], aH[mt], bf[j][2], bf[j][3]);
                }
            #pragma unroll
            for (int mt = 0; mt < 2; mt++)
                #pragma unroll
                for (int j = 0; j < 4; j++) {
                    mma16816(acc[mt][2*j],   aL[mt], bf[j][0], bf[j][1]);
                    mma16816(acc[mt][2*j+1], aL[mt], bf[j][2], bf[j][3]);
                }
            // pass 3: Ah * Bl
            #pragma unroll
            for (int j = 0; j < 4; j++) {
                int row = wn * 64 + j * 16 + b_r;
                uint32_t off = (uint32_t)(row * (RSTR*2) + (kk + b_k) * 2);
                ldsm4(bf[j], bBl + off);
            }
            #pragma unroll
            for (int mt = 0; mt < 2; mt++)
                #pragma unroll
                for (int j = 0; j < 4; j++) {
                    mma16816(acc[mt][2*j],   aH[mt], bf[j][0], bf[j][1]);
                    mma16816(acc[mt][2*j+1], aH[mt], bf[j][2], bf[j][3]);
                }
        }
        __syncthreads();
        if (c + 2 < NC) { load_chunk(c + 2, s); CP_COMMIT(); }
    }

    // ---------------- epilogue ----------------
    const int mrow = m0 + wm * 32;
    const int ncol = n0 + wn * 64;
    #pragma unroll
    for (int mt = 0; mt < 2; mt++) {
        #pragma unroll
        for (int nt = 0; nt < 8; nt++) {
            int r0 = mrow + mt * 16 + (lane >> 2);
            int r1 = r0 + 8;
            int cc = ncol + nt * 8 + (lane & 3) * 2;
            float* a = acc[mt][nt];
            size_t i0 = (size_t)r0 * N + cc;
            size_t i1 = (size_t)r1 * N + cc;
            if (EPI == 0) {
                *(float2*)(C + i0) = make_float2(a[0], a[1]);
                *(float2*)(C + i1) = make_float2(a[2], a[3]);
            } else if (EPI == 1) {
                float2 x0 = *(const float2*)(aux + i0);
                float2 x1 = *(const float2*)(aux + i1);
                *(float2*)(C + i0) = make_float2(a[0] + x0.x, a[1] + x0.y);
                *(float2*)(C + i1) = make_float2(a[2] + x1.x, a[3] + x1.y);
            } else {
                float2 g0 = *(const float2*)(aux + i0);
                float2 g1 = *(const float2*)(aux + i1);
                float v00 = a[0] * (g0.x / (1.f + __expf(-g0.x)));
                float v01 = a[1] * (g0.y / (1.f + __expf(-g0.y)));
                float v10 = a[2] * (g1.x / (1.f + __expf(-g1.x)));
                float v11 = a[3] * (g1.y / (1.f + __expf(-g1.y)));
                __half h00, l00, h01, l01, h10, l10, h11, l11;
                split_h(v00, h00, l00); split_h(v01, h01, l01);
                split_h(v10, h10, l10); split_h(v11, h11, l11);
                *(__half2*)(CH + i0) = __halves2half2(h00, h01);
                *(__half2*)(CL + i0) = __halves2half2(l00, l01);
                *(__half2*)(CH + i1) = __halves2half2(h10, h11);
                *(__half2*)(CL + i1) = __halves2half2(l10, l11);
            }
        }
    }
}

// ---------------- weight transpose + fp16 split ----------------------------
// W[K][N] fp32 -> TH/TL[N][K] fp16
__global__ void wsplit_kernel(const float* __restrict__ W,
                              __half* __restrict__ TH, __half* __restrict__ TL,
                              int K, int N)
{
    __shared__ float t[32][33];
    int tx = threadIdx.x, ty = threadIdx.y;
    int n0 = blockIdx.x * 32, k0 = blockIdx.y * 32;
    #pragma unroll
    for (int j = 0; j < 4; j++)
        t[ty + 8 * j][tx] = W[(size_t)(k0 + ty + 8 * j) * N + n0 + tx];
    __syncthreads();
    #pragma unroll
    for (int j = 0; j < 4; j++) {
        float v = t[tx][ty + 8 * j];
        __half hi, lo; split_h(v, hi, lo);
        size_t idx = (size_t)(n0 + ty + 8 * j) * K + k0 + tx;
        TH[idx] = hi; TL[idx] = lo;
    }
}

// --------------------------- RMSNorm (+split) -------------------------------
template<int WRITE_F32>
__global__ void rmsnorm_kernel(const float* __restrict__ x, const float* __restrict__ w,
                               float* __restrict__ out,
                               __half* __restrict__ oh, __half* __restrict__ ol)
{
    int row = blockIdx.x;
    int tid = threadIdx.x;
    const float4* xr = (const float4*)(x + (size_t)row * Dv);
    float4 v0 = xr[tid];
    float4 v1 = xr[tid + 256];
    float ss = v0.x*v0.x + v0.y*v0.y + v0.z*v0.z + v0.w*v0.w
             + v1.x*v1.x + v1.y*v1.y + v1.z*v1.z + v1.w*v1.w;
    #pragma unroll
    for (int o = 16; o > 0; o >>= 1) ss += __shfl_xor_sync(0xffffffffu, ss, o);
    __shared__ float red[8];
    int wp = tid >> 5, lane = tid & 31;
    if (lane == 0) red[wp] = ss;
    __syncthreads();
    float tot = 0.f;
    #pragma unroll
    for (int i = 0; i < 8; i++) tot += red[i];
    float inv = rsqrtf(tot * (1.f / Dv) + 1e-6f);
    const float4* wr = (const float4*)w;
    #pragma unroll
    for (int half_ = 0; half_ < 2; half_++) {
        float4 v = half_ ? v1 : v0;
        float4 ww = wr[tid + 256 * half_];
        float r[4] = { v.x*inv*ww.x, v.y*inv*ww.y, v.z*inv*ww.z, v.w*inv*ww.w };
        size_t idx = (size_t)row * Dv + (tid + 256 * half_) * 4;
        if (WRITE_F32) *(float4*)(out + idx) = make_float4(r[0], r[1], r[2], r[3]);
        __half h4[4], l4[4];
        #pragma unroll
        for (int e = 0; e < 4; e++) split_h(r[e], h4[e], l4[e]);
        *(uint2*)(oh + idx) = *(uint2*)h4;
        *(uint2*)(ol + idx) = *(uint2*)l4;
    }
}

// --------------------------- i/f gate projections ---------------------------
__device__ __forceinline__ float softcap15(float x) {
    return 15.f * tanhf(x * (1.f / 15.f));
}

__global__ void gates_kernel(const float* __restrict__ hin,
                             const float* __restrict__ w_ig, const float* __restrict__ b_ig,
                             const float* __restrict__ w_fg, const float* __restrict__ b_fg,
                             float* __restrict__ ipre, float* __restrict__ fpre)
{
    int row = blockIdx.x;
    int tid = threadIdx.x;
    float pi[8], pf[8];
    #pragma unroll
    for (int h = 0; h < 8; h++) { pi[h] = 0.f; pf[h] = 0.f; }
    const float* xr = hin + (size_t)row * Dv;
    for (int d = tid; d < Dv; d += 256) {
        float xv = xr[d];
        #pragma unroll
        for (int h = 0; h < 8; h++) {
            pi[h] += xv * w_ig[d * 8 + h];
            pf[h] += xv * w_fg[d * 8 + h];
        }
    }
    #pragma unroll
    for (int h = 0; h < 8; h++) {
        #pragma unroll
        for (int o = 16; o > 0; o >>= 1) {
            pi[h] += __shfl_xor_sync(0xffffffffu, pi[h], o);
            pf[h] += __shfl_xor_sync(0xffffffffu, pf[h], o);
        }
    }
    __shared__ float sred[8][16];
    int wp = tid >> 5, lane = tid & 31;
    if (lane == 0) {
        #pragma unroll
        for (int h = 0; h < 8; h++) { sred[wp][h] = pi[h]; sred[wp][8 + h] = pf[h]; }
    }
    __syncthreads();
    if (tid < 16) {
        float s = 0.f;
        #pragma unroll
        for (int w8 = 0; w8 < 8; w8++) s += sred[w8][tid];
        int h = tid & 7;
        bool isf = (tid >= 8);
        float bias = isf ? b_fg[h] : b_ig[h];
        float val = softcap15(s + bias);
        int b = row >> 11;
        int sp = row & (Sv - 1);
        int bh = b * Hv + h;
        (isf ? fpre : ipre)[bh * Sv + sp] = val;
    }
}

// --------------------------- gate scans ------------------------------------
__global__ void scan_kernel(const float* __restrict__ ipre, const float* __restrict__ fpre,
                            float* __restrict__ aout, float* __restrict__ Gout,
                            float* __restrict__ nflout)
{
    int bh = blockIdx.x;
    int tid = threadIdx.x;
    __shared__ float bufA[2048], bufB[2048], fc[2048];

    for (int i = tid; i < 2048; i += 1024) {
        float f = fpre[bh * Sv + i];
        bufA[i] = fminf(f, 0.f) - log1pf(expf(-fabsf(f)));
    }
    __syncthreads();
    float* src = bufA; float* dst = bufB;
    for (int off = 1; off < 2048; off <<= 1) {
        for (int i = tid; i < 2048; i += 1024)
            dst[i] = src[i] + ((i >= off) ? src[i - off] : 0.f);
        __syncthreads();
        float* t = src; src = dst; dst = t;
    }
    for (int i = tid; i < 2048; i += 1024) fc[i] = src[i];
    __syncthreads();
    for (int i = tid; i < 2048; i += 1024) {
        float a = ipre[bh * Sv + i] - fc[i];
        aout[bh * Sv + i] = a;
        dst[i] = a;
    }
    __syncthreads();
    { float* t = src; src = dst; dst = t; }
    for (int off = 1; off < 2048; off <<= 1) {
        for (int i = tid; i < 2048; i += 1024)
            dst[i] = fmaxf(src[i], (i >= off) ? src[i - off] : -1e30f);
        __syncthreads();
        float* t = src; src = dst; dst = t;
    }
    for (int i = tid; i < 2048; i += 1024) {
        float G = src[i];
        Gout[bh * Sv + i] = G;
        nflout[bh * Sv + i] = expf(-(fc[i] + G));
    }
}

// --------------------------- mLSTM attention -------------------------------
#define ATT_SMEM_FLOATS (64*129 + 64*129 + 64*260 + 64*72 + 4*64)
#define ATT_SMEM_BYTES  (ATT_SMEM_FLOATS * 4)

__global__ void __launch_bounds__(256, 1) attn_kernel(
    const float* __restrict__ q, const float* __restrict__ k, const float* __restrict__ v,
    const float* __restrict__ av, const float* __restrict__ Gv, const float* __restrict__ nfv,
    float* __restrict__ hout)
{
    extern __shared__ float sm[];
    float* qs     = sm;
    float* ks     = qs + 64 * 129;
    float* vs     = ks + 64 * 129;
    float* sct    = vs + 64 * 260;
    float* rowsum = sct + 64 * 72;
    float* Gt     = rowsum + 64;
    float* nfl    = Gt + 64;
    float* aly    = nfl + 64;

    int bh = blockIdx.y;
    int bb = bh >> 3, hh = bh & 7;
    int t0 = blockIdx.x * 64;
    int tid = threadIdx.x, tx = tid & 15, ty = tid >> 4;

    const float* qbase = q + ((size_t)(bb * Sv + t0)) * QKv + hh * DQK;
    #pragma unroll
    for (int j = 0; j < 8; j++) {
        int f4 = tid + 256 * j;
        int r = f4 >> 5, d4 = f4 & 31;
        float4 qv = *(const float4*)(qbase + (size_t)r * QKv + d4 * 4);
        float* dst = &qs[r * 129 + d4 * 4];
        dst[0] = qv.x; dst[1] = qv.y; dst[2] = qv.z; dst[3] = qv.w;
    }
    if (tid < 64) {
        rowsum[tid] = 0.f;
        Gt[tid]  = Gv[bh * Sv + t0 + tid];
        nfl[tid] = nfv[bh * Sv + t0 + tid];
    }

    float acc[4][16];
    #pragma unroll
    for (int i = 0; i < 4; i++)
        #pragma unroll
        for (int j = 0; j < 16; j++) acc[i][j] = 0.f;

    int nst = (t0 >> 6) + 1;
    for (int st = 0; st < nst; st++) {
        int s0 = st << 6;
        __syncthreads();
        const float* kbase = k + ((size_t)(bb * Sv + s0)) * QKv + hh * DQK;
        #pragma unroll
        for (int j = 0; j < 8; j++) {
            int f4 = tid + 256 * j;
            int r = f4 >> 5, d4 = f4 & 31;
            float4 kv4 = *(const float4*)(kbase + (size_t)r * QKv + d4 * 4);
            float* dst = &ks[r * 129 + d4 * 4];
            dst[0] = kv4.x; dst[1] = kv4.y; dst[2] = kv4.z; dst[3] = kv4.w;
        }
        const float* vbase = v + ((size_t)(bb * Sv + s0)) * Dv + hh * DVv;
        #pragma unroll
        for (int j = 0; j < 16; j++) {
            int f4 = tid + 256 * j;
            int r = f4 >> 6, c4 = f4 & 63;
            *(float4*)&vs[r * 260 + c4 * 4] = *(const float4*)(vbase + (size_t)r * Dv + c4 * 4);
        }
        if (tid < 64) aly[tid] = av[bh * Sv + s0 + tid];
        __syncthreads();

        float sc[4][4];
        #pragma unroll
        for (int i = 0; i < 4; i++)
            #pragma unroll
            for (int j = 0; j < 4; j++) sc[i][j] = 0.f;
        const float* qrow = &qs[(ty * 4) * 129];
        const float* krow = &ks[(tx * 4) * 129];
        #pragma unroll 4
        for (int kk = 0; kk < 128; kk++) {
            float a0 = qrow[kk], a1 = qrow[129 + kk], a2 = qrow[258 + kk], a3 = qrow[387 + kk];
            float b0 = krow[kk], b1 = krow[129 + kk], b2 = krow[258 + kk], b3 = krow[387 + kk];
            sc[0][0] += a0 * b0; sc[0][1] += a0 * b1; sc[0][2] += a0 * b2; sc[0][3] += a0 * b3;
            sc[1][0] += a1 * b0; sc[1][1] += a1 * b1; sc[1][2] += a1 * b2; sc[1][3] += a1 * b3;
            sc[2][0] += a2 * b0; sc[2][1] += a2 * b1; sc[2][2] += a2 * b2; sc[2][3] += a2 * b3;
            sc[3][0] += a3 * b0; sc[3][1] += a3 * b1; sc[3][2] += a3 * b2; sc[3][3] += a3 * b3;
        }
        bool diag = (st == nst - 1);
        const float invsq = 0.08838834764831845f;
        #pragma unroll
        for (int i = 0; i < 4; i++) {
            int rloc = ty * 4 + i;
            int tg = t0 + rloc;
            float gt = Gt[rloc];
            float rs = 0.f;
            #pragma unroll
            for (int j = 0; j < 4; j++) {
                int sg = s0 + tx * 4 + j;
                float val;
                if (!diag || sg <= tg) {
                    float w = __expf(aly[tx * 4 + j] - gt) * invsq;
                    val = sc[i][j] * w;
                } else {
                    val = 0.f;
                }
                sc[i][j] = val;
                rs += val;
            }
            atomicAdd(&rowsum[rloc], rs);
        }
        #pragma unroll
        for (int j = 0; j < 4; j++) {
            float4 t4 = make_float4(sc[0][j], sc[1][j], sc[2][j], sc[3][j]);
            *(float4*)&sct[(tx * 4 + j) * 72 + ty * 4] = t4;
        }
        __syncthreads();

        #pragma unroll 4
        for (int s = 0; s < 64; s++) {
            float4 p = *(float4*)&sct[s * 72 + ty * 4];
            float pr[4] = {p.x, p.y, p.z, p.w};
            #pragma unroll
            for (int jg = 0; jg < 4; jg++) {
                float4 vv = *(float4*)&vs[s * 260 + jg * 64 + tx * 4];
                #pragma unroll
                for (int i = 0; i < 4; i++) {
                    acc[i][jg * 4 + 0] += pr[i] * vv.x;
                    acc[i][jg * 4 + 1] += pr[i] * vv.y;
                    acc[i][jg * 4 + 2] += pr[i] * vv.z;
                    acc[i][jg * 4 + 3] += pr[i] * vv.w;
                }
            }
        }
    }
    __syncthreads();

    float* ho = hout + ((size_t)(bb * Sv + t0)) * Dv + hh * DVv;
    #pragma unroll
    for (int i = 0; i < 4; i++) {
        int r = ty * 4 + i;
        float n = fmaxf(fabsf(rowsum[r]), nfl[r]);
        float inv = 1.f / n;
        #pragma unroll
        for (int jg = 0; jg < 4; jg++) {
            float4 o = make_float4(acc[i][jg * 4 + 0] * inv, acc[i][jg * 4 + 1] * inv,
                                   acc[i][jg * 4 + 2] * inv, acc[i][jg * 4 + 3] * inv);
            *(float4*)(ho + (size_t)r * Dv + jg * 64 + tx * 4) = o;
        }
    }
}

// ----------------- per-head RMSNorm + output gate (-> fp16 split) ----------
__global__ void headnorm_kernel(const float* __restrict__ h, const float* __restrict__ opre,
                                const float* __restrict__ mh_w,
                                __half* __restrict__ oh, __half* __restrict__ ol)
{
    int row = blockIdx.x;
    int tid = threadIdx.x;
    int wp = tid >> 5, lane = tid & 31;
    const float* hr = h + (size_t)row * Dv + wp * DVv;
    float vv[8];
    float ss = 0.f;
    #pragma unroll
    for (int j = 0; j < 8; j++) { vv[j] = hr[lane + 32 * j]; ss += vv[j] * vv[j]; }
    #pragma unroll
    for (int o = 16; o > 0; o >>= 1) ss += __shfl_xor_sync(0xffffffffu, ss, o);
    float inv = rsqrtf(ss * (1.f / DVv) + 1e-6f);
    const float* op = opre + (size_t)row * Dv + wp * DVv;
    const float* mw = mh_w + wp * DVv;
    __half* outh = oh + (size_t)row * Dv + wp * DVv;
    __half* outl = ol + (size_t)row * Dv + wp * DVv;
    #pragma unroll
    for (int j = 0; j < 8; j++) {
        int c = lane + 32 * j;
        float o = op[c];
        float sg = 1.f / (1.f + expf(-o));
        float val = sg * vv[j] * inv * mw[c];
        __half hi, lo; split_h(val, hi, lo);
        outh[c] = hi; outl[c] = lo;
    }
}

// --------------------------- launch ----------------------------------------
extern "C" void kernel_launch(void* const* d_in, const int* in_sizes, int n_in,
                              void* d_out, int out_size)
{
    const float* x       = (const float*)d_in[0];
    const float* norm1_w = (const float*)d_in[1];
    const float* wq      = (const float*)d_in[2];
    const float* wk      = (const float*)d_in[3];
    const float* wv      = (const float*)d_in[4];
    const float* w_ig    = (const float*)d_in[5];
    const float* b_ig    = (const float*)d_in[6];
    const float* w_fg    = (const float*)d_in[7];
    const float* b_fg    = (const float*)d_in[8];
    const float* w_og    = (const float*)d_in[9];
    const float* mh_w    = (const float*)d_in[10];
    const float* w_out   = (const float*)d_in[11];
    const float* norm2_w = (const float*)d_in[12];
    const float* w_gate  = (const float*)d_in[13];
    const float* w_up    = (const float*)d_in[14];
    const float* w_down  = (const float*)d_in[15];
    float* out = (float*)d_out;

    void* fp = nullptr; cudaGetSymbolAddress(&fp, g_f32);
    void* hp = nullptr; cudaGetSymbolAddress(&hp, g_fp16);
    float* F = (float*)fp;
    __half* Hh = (__half*)hp;

    float *hin = F+F_HIN, *qb = F+F_Q, *kb = F+F_K, *vb = F+F_V, *opre = F+F_OPRE;
    float *hb = F+F_H, *x1 = F+F_X1, *gate = F+F_GATE;
    float *ipre = F+F_IPRE, *fpre = F+F_FPRE, *ab = F+F_A, *Gb = F+F_G, *nfl = F+F_NFL;

    __half *hinH=Hh+P_HINH, *hinL=Hh+P_HINL, *houtH=Hh+P_HOUTH, *houtL=Hh+P_HOUTL;
    __half *h2H=Hh+P_H2H, *h2L=Hh+P_H2L, *actH=Hh+P_ACTH, *actL=Hh+P_ACTL;
    __half *wqH=Hh+P_WQH, *wqL=Hh+P_WQL, *wkH=Hh+P_WKH, *wkL=Hh+P_WKL;
    __half *wvH=Hh+P_WVH, *wvL=Hh+P_WVL, *wogH=Hh+P_WOGH, *wogL=Hh+P_WOGL;
    __half *woutH=Hh+P_WOUTH, *woutL=Hh+P_WOUTL;
    __half *wgH=Hh+P_WGH, *wgL=Hh+P_WGL, *wuH=Hh+P_WUH, *wuL=Hh+P_WUL;
    __half *wdH=Hh+P_WDH, *wdL=Hh+P_WDL;

    cudaFuncSetAttribute(attn_kernel, cudaFuncAttributeMaxDynamicSharedMemorySize, ATT_SMEM_BYTES);
    cudaFuncSetAttribute(tgemm_kernel<0>, cudaFuncAttributeMaxDynamicSharedMemorySize, GSMEM);
    cudaFuncSetAttribute(tgemm_kernel<1>, cudaFuncAttributeMaxDynamicSharedMemorySize, GSMEM);
    cudaFuncSetAttribute(tgemm_kernel<2>, cudaFuncAttributeMaxDynamicSharedMemorySize, GSMEM);

    dim3 tb(32, 8);
    wsplit_kernel<<<dim3(QKv/32, Dv/32), tb>>>(wq, wqH, wqL, Dv, QKv);
    wsplit_kernel<<<dim3(QKv/32, Dv/32), tb>>>(wk, wkH, wkL, Dv, QKv);
    wsplit_kernel<<<dim3(Dv/32,  Dv/32), tb>>>(wv, wvH, wvL, Dv, Dv);
    wsplit_kernel<<<dim3(Dv/32,  Dv/32), tb>>>(w_og, wogH, wogL, Dv, Dv);
    wsplit_kernel<<<dim3(Dv/32,  Dv/32), tb>>>(w_out, woutH, woutL, Dv, Dv);
    wsplit_kernel<<<dim3(FFv/32, Dv/32), tb>>>(w_gate, wgH, wgL, Dv, FFv);
    wsplit_kernel<<<dim3(FFv/32, Dv/32), tb>>>(w_up, wuH, wuL, Dv, FFv);
    wsplit_kernel<<<dim3(Dv/32, FFv/32), tb>>>(w_down, wdH, wdL, FFv, Dv);

    rmsnorm_kernel<1><<<Mv, 256>>>(x, norm1_w, hin, hinH, hinL);

    tgemm_kernel<0><<<dim3(QKv/128, Mv/128), 256, GSMEM>>>(hinH, hinL, wqH, wqL, nullptr, qb, nullptr, nullptr, QKv, Dv);
    tgemm_kernel<0><<<dim3(QKv/128, Mv/128), 256, GSMEM>>>(hinH, hinL, wkH, wkL, nullptr, kb, nullptr, nullptr, QKv, Dv);
    tgemm_kernel<0><<<dim3(Dv/128,  Mv/128), 256, GSMEM>>>(hinH, hinL, wvH, wvL, nullptr, vb, nullptr, nullptr, Dv, Dv);
    tgemm_kernel<0><<<dim3(Dv/128,  Mv/128), 256, GSMEM>>>(hinH, hinL, wogH, wogL, nullptr, opre, nullptr, nullptr, Dv, Dv);

    gates_kernel<<<Mv, 256>>>(hin, w_ig, b_ig, w_fg, b_fg, ipre, fpre);
    scan_kernel<<<BHv, 1024>>>(ipre, fpre, ab, Gb, nfl);
    attn_kernel<<<dim3(Sv/64, BHv), 256, ATT_SMEM_BYTES>>>(qb, kb, vb, ab, Gb, nfl, hb);
    headnorm_kernel<<<Mv, 256>>>(hb, opre, mh_w, houtH, houtL);

    tgemm_kernel<1><<<dim3(Dv/128, Mv/128), 256, GSMEM>>>(houtH, houtL, woutH, woutL, x, x1, nullptr, nullptr, Dv, Dv);

    rmsnorm_kernel<0><<<Mv, 256>>>(x1, norm2_w, nullptr, h2H, h2L);

    tgemm_kernel<0><<<dim3(FFv/128, Mv/128), 256, GSMEM>>>(h2H, h2L, wgH, wgL, nullptr, gate, nullptr, nullptr, FFv, Dv);
    tgemm_kernel<2><<<dim3(FFv/128, Mv/128), 256, GSMEM>>>(h2H, h2L, wuH, wuL, gate, nullptr, actH, actL, FFv, Dv);

    tgemm_kernel<1><<<dim3(Dv/128, Mv/128), 256, GSMEM>>>(actH, actL, wdH, wdL, x1, out, Dv == 0 ? nullptr : nullptr, nullptr, Dv, FFv);

    (void)in_sizes; (void)n_in; (void)out_size;
}

// round 5
// speedup vs baseline: 3.0921x; 1.5039x over previous
#include <cuda_runtime.h>
#include <cuda_fp16.h>
#include <math.h>
#include <stdint.h>

// ---------------------------------------------------------------------------
// BolmoLocalLayer: xLSTM mixer + SwiGLU MLP.  B=2, S=2048, D=2048, H=8.
// Round 5: 2-pass HMMA GEMM (A = fp16 hi+lo exact, W = fp16 hi only),
// 3-stage cp.async pipeline, K-chunk 64.
// ---------------------------------------------------------------------------

#define Bv   2
#define Sv   2048
#define Dv   2048
#define Hv   8
#define QKv  1024
#define DQK  128
#define DVv  256
#define FFv  8192
#define Mv   (Bv*Sv)      // 4096
#define BHv  (Bv*Hv)      // 16

// ----------------------------- fp32 scratch --------------------------------
#define F_HIN   ((size_t)0)
#define F_Q     (F_HIN  + (size_t)Mv*Dv)
#define F_K     (F_Q    + (size_t)Mv*QKv)
#define F_V     (F_K    + (size_t)Mv*QKv)
#define F_OPRE  (F_V    + (size_t)Mv*Dv)
#define F_H     (F_OPRE + (size_t)Mv*Dv)
#define F_X1    (F_H    + (size_t)Mv*Dv)
#define F_GATE  (F_X1   + (size_t)Mv*Dv)
#define F_IPRE  (F_GATE + (size_t)Mv*FFv)
#define F_FPRE  (F_IPRE + (size_t)BHv*Sv)
#define F_A     (F_FPRE + (size_t)BHv*Sv)
#define F_G     (F_A    + (size_t)BHv*Sv)
#define F_NFL   (F_G    + (size_t)BHv*Sv)
#define F_TOTAL (F_NFL  + (size_t)BHv*Sv)
__device__ __align__(256) float g_f32[F_TOTAL];

// ----------------------------- fp16 scratch --------------------------------
#define P_HINH  ((size_t)0)
#define P_HINL  (P_HINH  + (size_t)Mv*Dv)
#define P_HOUTH (P_HINL  + (size_t)Mv*Dv)
#define P_HOUTL (P_HOUTH + (size_t)Mv*Dv)
#define P_H2H   (P_HOUTL + (size_t)Mv*Dv)
#define P_H2L   (P_H2H   + (size_t)Mv*Dv)
#define P_ACTH  (P_H2L   + (size_t)Mv*Dv)
#define P_ACTL  (P_ACTH  + (size_t)Mv*FFv)
#define P_WQ    (P_ACTL  + (size_t)Mv*FFv)
#define P_WK    (P_WQ    + (size_t)QKv*Dv)
#define P_WV    (P_WK    + (size_t)QKv*Dv)
#define P_WOG   (P_WV    + (size_t)Dv*Dv)
#define P_WOUT  (P_WOG   + (size_t)Dv*Dv)
#define P_WG    (P_WOUT  + (size_t)Dv*Dv)
#define P_WU    (P_WG    + (size_t)FFv*Dv)
#define P_WD    (P_WU    + (size_t)FFv*Dv)
#define P_TOTAL (P_WD    + (size_t)Dv*FFv)
__device__ __align__(256) __half g_fp16[P_TOTAL];

// ----------------------------- helpers -------------------------------------
__device__ __forceinline__ uint32_t smem_u32(const void* p) {
    uint32_t a;
    asm("{ .reg .u64 t; cvta.to.shared.u64 t, %1; cvt.u32.u64 %0, t; }"
        : "=r"(a) : "l"(p));
    return a;
}

__device__ __forceinline__ void cp16(uint32_t sa, const void* g) {
    asm volatile("cp.async.ca.shared.global [%0], [%1], 16;"
                 :: "r"(sa), "l"(g) : "memory");
}
#define CP_COMMIT() asm volatile("cp.async.commit_group;" ::: "memory")
#define CP_WAIT1()  asm volatile("cp.async.wait_group 1;" ::: "memory")
#define CP_WAIT0()  asm volatile("cp.async.wait_group 0;" ::: "memory")

__device__ __forceinline__ void ldsm4(uint32_t* r, uint32_t addr) {
    asm volatile("ldmatrix.sync.aligned.m8n8.x4.shared.b16 {%0,%1,%2,%3}, [%4];"
                 : "=r"(r[0]), "=r"(r[1]), "=r"(r[2]), "=r"(r[3]) : "r"(addr));
}

__device__ __forceinline__ void mma16816(float* c, const uint32_t* a,
                                         uint32_t b0, uint32_t b1) {
    asm volatile(
        "mma.sync.aligned.m16n8k16.row.col.f32.f16.f16.f32 "
        "{%0,%1,%2,%3}, {%4,%5,%6,%7}, {%8,%9}, {%0,%1,%2,%3};"
        : "+f"(c[0]), "+f"(c[1]), "+f"(c[2]), "+f"(c[3])
        : "r"(a[0]), "r"(a[1]), "r"(a[2]), "r"(a[3]), "r"(b0), "r"(b1));
}

__device__ __forceinline__ void split_h(float v, __half& hi, __half& lo) {
    hi = __float2half_rn(v);
    lo = __float2half_rn(v - __half2float(hi));
}

// --------------------------- HMMA GEMM (2-pass) ----------------------------
// C[M, N] = epilogue(A @ W).  A: fp16 hi/lo [M][K] K-major (exact sum).
// W: fp16 hi only, pre-transposed [N][K] K-major.
// EPI 0: C fp32 = acc.   EPI 1: C fp32 = aux + acc.
// EPI 2: (CH,CL) fp16 = split(silu(aux) * acc).
#define KCH   64                       // K per chunk
#define RSTRB 144                      // smem row stride in bytes (128 + 16)
#define TILEB (128*RSTRB)              // 18432 B per operand tile
#define NSTG  3
#define STAGEB (3*TILEB)               // Ah, Al, Bh
#define GSMEM (NSTG*STAGEB)            // 165888 B

template<int EPI>
__global__ void __launch_bounds__(256) tgemm_kernel(
    const __half* __restrict__ AH, const __half* __restrict__ AL,
    const __half* __restrict__ BH,
    const float* __restrict__ aux, float* __restrict__ C,
    __half* __restrict__ CH, __half* __restrict__ CL,
    int N, int K)
{
    extern __shared__ char smem[];
    const uint32_t sb = smem_u32(smem);
    const int tid = threadIdx.x;
    const int lane = tid & 31;
    const int wid = tid >> 5;
    const int wm = wid & 3;           // warp m group (32 rows)
    const int wn = wid >> 2;          // warp n group (64 cols)
    const int m0 = blockIdx.y * 128;
    const int n0 = blockIdx.x * 128;

    const __half* src[3] = { AH + (size_t)m0 * K, AL + (size_t)m0 * K,
                             BH + (size_t)n0 * K };

    float acc[2][8][4];
    #pragma unroll
    for (int i = 0; i < 2; i++)
        #pragma unroll
        for (int j = 0; j < 8; j++)
            #pragma unroll
            for (int e = 0; e < 4; e++) acc[i][j][e] = 0.f;

    const int NC = K / KCH;

    auto load_chunk = [&](int c, int s) {
        #pragma unroll
        for (int t = 0; t < 3; t++) {
            const __half* gb = src[t] + c * KCH;
            uint32_t sbase = sb + (uint32_t)(s * STAGEB + t * TILEB);
            #pragma unroll
            for (int i = 0; i < 4; i++) {
                int seg = tid + 256 * i;           // 0..1023
                int row = seg >> 3, s8 = seg & 7;  // 8 x 16B per row
                cp16(sbase + (uint32_t)(row * RSTRB + s8 * 16),
                     gb + (size_t)row * K + s8 * 8);
            }
        }
    };

    load_chunk(0, 0); CP_COMMIT();
    load_chunk(1, 1); CP_COMMIT();

    // ldmatrix lane addressing
    const int a_r = (lane & 15);
    const int a_k = (lane >> 4) * 8;
    const int b_r = (lane & 7) + (lane >> 4) * 8;
    const int b_k = ((lane >> 3) & 1) * 8;

    for (int c = 0; c < NC; c++) {
        const int s = c % NSTG;
        if (c + 1 < NC) CP_WAIT1(); else CP_WAIT0();
        __syncthreads();
        if (c + 2 < NC) { load_chunk(c + 2, (c + 2) % NSTG); CP_COMMIT(); }

        const uint32_t bAh = sb + s * STAGEB;
        const uint32_t bAl = bAh + TILEB;
        const uint32_t bBh = bAh + 2 * TILEB;

        #pragma unroll
        for (int kk = 0; kk < KCH; kk += 16) {
            uint32_t aH[2][4], aL[2][4], bf[4][4];
            #pragma unroll
            for (int mt = 0; mt < 2; mt++) {
                int row = wm * 32 + mt * 16 + a_r;
                uint32_t off = (uint32_t)(row * RSTRB + (kk + a_k) * 2);
                ldsm4(aH[mt], bAh + off);
                ldsm4(aL[mt], bAl + off);
            }
            #pragma unroll
            for (int j = 0; j < 4; j++) {
                int row = wn * 64 + j * 16 + b_r;
                uint32_t off = (uint32_t)(row * RSTRB + (kk + b_k) * 2);
                ldsm4(bf[j], bBh + off);
            }
            #pragma unroll
            for (int mt = 0; mt < 2; mt++)
                #pragma unroll
                for (int j = 0; j < 4; j++) {
                    mma16816(acc[mt][2*j],   aH[mt], bf[j][0], bf[j][1]);
                    mma16816(acc[mt][2*j+1], aH[mt], bf[j][2], bf[j][3]);
                }
            #pragma unroll
            for (int mt = 0; mt < 2; mt++)
                #pragma unroll
                for (int j = 0; j < 4; j++) {
                    mma16816(acc[mt][2*j],   aL[mt], bf[j][0], bf[j][1]);
                    mma16816(acc[mt][2*j+1], aL[mt], bf[j][2], bf[j][3]);
                }
        }
    }

    // ---------------- epilogue ----------------
    const int mrow = m0 + wm * 32;
    const int ncol = n0 + wn * 64;
    #pragma unroll
    for (int mt = 0; mt < 2; mt++) {
        #pragma unroll
        for (int nt = 0; nt < 8; nt++) {
            int r0 = mrow + mt * 16 + (lane >> 2);
            int r1 = r0 + 8;
            int cc = ncol + nt * 8 + (lane & 3) * 2;
            float* a = acc[mt][nt];
            size_t i0 = (size_t)r0 * N + cc;
            size_t i1 = (size_t)r1 * N + cc;
            if (EPI == 0) {
                *(float2*)(C + i0) = make_float2(a[0], a[1]);
                *(float2*)(C + i1) = make_float2(a[2], a[3]);
            } else if (EPI == 1) {
                float2 x0 = *(const float2*)(aux + i0);
                float2 x1 = *(const float2*)(aux + i1);
                *(float2*)(C + i0) = make_float2(a[0] + x0.x, a[1] + x0.y);
                *(float2*)(C + i1) = make_float2(a[2] + x1.x, a[3] + x1.y);
            } else {
                float2 g0 = *(const float2*)(aux + i0);
                float2 g1 = *(const float2*)(aux + i1);
                float v00 = a[0] * (g0.x / (1.f + __expf(-g0.x)));
                float v01 = a[1] * (g0.y / (1.f + __expf(-g0.y)));
                float v10 = a[2] * (g1.x / (1.f + __expf(-g1.x)));
                float v11 = a[3] * (g1.y / (1.f + __expf(-g1.y)));
                __half h00, l00, h01, l01, h10, l10, h11, l11;
                split_h(v00, h00, l00); split_h(v01, h01, l01);
                split_h(v10, h10, l10); split_h(v11, h11, l11);
                *(__half2*)(CH + i0) = __halves2half2(h00, h01);
                *(__half2*)(CL + i0) = __halves2half2(l00, l01);
                *(__half2*)(CH + i1) = __halves2half2(h10, h11);
                *(__half2*)(CL + i1) = __halves2half2(l10, l11);
            }
        }
    }
}

// ---------------- weight transpose + fp16 (hi only) ------------------------
// W[K][N] fp32 -> TH[N][K] fp16
__global__ void wsplit_kernel(const float* __restrict__ W,
                              __half* __restrict__ TH, int K, int N)
{
    __shared__ float t[32][33];
    int tx = threadIdx.x, ty = threadIdx.y;
    int n0 = blockIdx.x * 32, k0 = blockIdx.y * 32;
    #pragma unroll
    for (int j = 0; j < 4; j++)
        t[ty + 8 * j][tx] = W[(size_t)(k0 + ty + 8 * j) * N + n0 + tx];
    __syncthreads();
    #pragma unroll
    for (int j = 0; j < 4; j++) {
        float v = t[tx][ty + 8 * j];
        TH[(size_t)(n0 + ty + 8 * j) * K + k0 + tx] = __float2half_rn(v);
    }
}

// --------------------------- RMSNorm (+split) -------------------------------
template<int WRITE_F32>
__global__ void rmsnorm_kernel(const float* __restrict__ x, const float* __restrict__ w,
                               float* __restrict__ out,
                               __half* __restrict__ oh, __half* __restrict__ ol)
{
    int row = blockIdx.x;
    int tid = threadIdx.x;
    const float4* xr = (const float4*)(x + (size_t)row * Dv);
    float4 v0 = xr[tid];
    float4 v1 = xr[tid + 256];
    float ss = v0.x*v0.x + v0.y*v0.y + v0.z*v0.z + v0.w*v0.w
             + v1.x*v1.x + v1.y*v1.y + v1.z*v1.z + v1.w*v1.w;
    #pragma unroll
    for (int o = 16; o > 0; o >>= 1) ss += __shfl_xor_sync(0xffffffffu, ss, o);
    __shared__ float red[8];
    int wp = tid >> 5, lane = tid & 31;
    if (lane == 0) red[wp] = ss;
    __syncthreads();
    float tot = 0.f;
    #pragma unroll
    for (int i = 0; i < 8; i++) tot += red[i];
    float inv = rsqrtf(tot * (1.f / Dv) + 1e-6f);
    const float4* wr = (const float4*)w;
    #pragma unroll
    for (int half_ = 0; half_ < 2; half_++) {
        float4 v = half_ ? v1 : v0;
        float4 ww = wr[tid + 256 * half_];
        float r[4] = { v.x*inv*ww.x, v.y*inv*ww.y, v.z*inv*ww.z, v.w*inv*ww.w };
        size_t idx = (size_t)row * Dv + (tid + 256 * half_) * 4;
        if (WRITE_F32) *(float4*)(out + idx) = make_float4(r[0], r[1], r[2], r[3]);
        __half h4[4], l4[4];
        #pragma unroll
        for (int e = 0; e < 4; e++) split_h(r[e], h4[e], l4[e]);
        *(uint2*)(oh + idx) = *(uint2*)h4;
        *(uint2*)(ol + idx) = *(uint2*)l4;
    }
}

// --------------------------- i/f gate projections ---------------------------
__device__ __forceinline__ float softcap15(float x) {
    return 15.f * tanhf(x * (1.f / 15.f));
}

__global__ void gates_kernel(const float* __restrict__ hin,
                             const float* __restrict__ w_ig, const float* __restrict__ b_ig,
                             const float* __restrict__ w_fg, const float* __restrict__ b_fg,
                             float* __restrict__ ipre, float* __restrict__ fpre)
{
    int row = blockIdx.x;
    int tid = threadIdx.x;
    float pi[8], pf[8];
    #pragma unroll
    for (int h = 0; h < 8; h++) { pi[h] = 0.f; pf[h] = 0.f; }
    const float* xr = hin + (size_t)row * Dv;
    for (int d = tid; d < Dv; d += 256) {
        float xv = xr[d];
        #pragma unroll
        for (int h = 0; h < 8; h++) {
            pi[h] += xv * w_ig[d * 8 + h];
            pf[h] += xv * w_fg[d * 8 + h];
        }
    }
    #pragma unroll
    for (int h = 0; h < 8; h++) {
        #pragma unroll
        for (int o = 16; o > 0; o >>= 1) {
            pi[h] += __shfl_xor_sync(0xffffffffu, pi[h], o);
            pf[h] += __shfl_xor_sync(0xffffffffu, pf[h], o);
        }
    }
    __shared__ float sred[8][16];
    int wp = tid >> 5, lane = tid & 31;
    if (lane == 0) {
        #pragma unroll
        for (int h = 0; h < 8; h++) { sred[wp][h] = pi[h]; sred[wp][8 + h] = pf[h]; }
    }
    __syncthreads();
    if (tid < 16) {
        float s = 0.f;
        #pragma unroll
        for (int w8 = 0; w8 < 8; w8++) s += sred[w8][tid];
        int h = tid & 7;
        bool isf = (tid >= 8);
        float bias = isf ? b_fg[h] : b_ig[h];
        float val = softcap15(s + bias);
        int b = row >> 11;
        int sp = row & (Sv - 1);
        int bh = b * Hv + h;
        (isf ? fpre : ipre)[bh * Sv + sp] = val;
    }
}

// --------------------------- gate scans ------------------------------------
__global__ void scan_kernel(const float* __restrict__ ipre, const float* __restrict__ fpre,
                            float* __restrict__ aout, float* __restrict__ Gout,
                            float* __restrict__ nflout)
{
    int bh = blockIdx.x;
    int tid = threadIdx.x;
    __shared__ float bufA[2048], bufB[2048], fc[2048];

    for (int i = tid; i < 2048; i += 1024) {
        float f = fpre[bh * Sv + i];
        bufA[i] = fminf(f, 0.f) - log1pf(expf(-fabsf(f)));
    }
    __syncthreads();
    float* src = bufA; float* dst = bufB;
    for (int off = 1; off < 2048; off <<= 1) {
        for (int i = tid; i < 2048; i += 1024)
            dst[i] = src[i] + ((i >= off) ? src[i - off] : 0.f);
        __syncthreads();
        float* t = src; src = dst; dst = t;
    }
    for (int i = tid; i < 2048; i += 1024) fc[i] = src[i];
    __syncthreads();
    for (int i = tid; i < 2048; i += 1024) {
        float a = ipre[bh * Sv + i] - fc[i];
        aout[bh * Sv + i] = a;
        dst[i] = a;
    }
    __syncthreads();
    { float* t = src; src = dst; dst = t; }
    for (int off = 1; off < 2048; off <<= 1) {
        for (int i = tid; i < 2048; i += 1024)
            dst[i] = fmaxf(src[i], (i >= off) ? src[i - off] : -1e30f);
        __syncthreads();
        float* t = src; src = dst; dst = t;
    }
    for (int i = tid; i < 2048; i += 1024) {
        float G = src[i];
        Gout[bh * Sv + i] = G;
        nflout[bh * Sv + i] = expf(-(fc[i] + G));
    }
}

// --------------------------- mLSTM attention -------------------------------
#define ATT_SMEM_FLOATS (64*129 + 64*129 + 64*260 + 64*72 + 4*64)
#define ATT_SMEM_BYTES  (ATT_SMEM_FLOATS * 4)

__global__ void __launch_bounds__(256, 1) attn_kernel(
    const float* __restrict__ q, const float* __restrict__ k, const float* __restrict__ v,
    const float* __restrict__ av, const float* __restrict__ Gv, const float* __restrict__ nfv,
    float* __restrict__ hout)
{
    extern __shared__ float sm[];
    float* qs     = sm;
    float* ks     = qs + 64 * 129;
    float* vs     = ks + 64 * 129;
    float* sct    = vs + 64 * 260;
    float* rowsum = sct + 64 * 72;
    float* Gt     = rowsum + 64;
    float* nfl    = Gt + 64;
    float* aly    = nfl + 64;

    int bh = blockIdx.y;
    int bb = bh >> 3, hh = bh & 7;
    int t0 = blockIdx.x * 64;
    int tid = threadIdx.x, tx = tid & 15, ty = tid >> 4;

    const float* qbase = q + ((size_t)(bb * Sv + t0)) * QKv + hh * DQK;
    #pragma unroll
    for (int j = 0; j < 8; j++) {
        int f4 = tid + 256 * j;
        int r = f4 >> 5, d4 = f4 & 31;
        float4 qv = *(const float4*)(qbase + (size_t)r * QKv + d4 * 4);
        float* dst = &qs[r * 129 + d4 * 4];
        dst[0] = qv.x; dst[1] = qv.y; dst[2] = qv.z; dst[3] = qv.w;
    }
    if (tid < 64) {
        rowsum[tid] = 0.f;
        Gt[tid]  = Gv[bh * Sv + t0 + tid];
        nfl[tid] = nfv[bh * Sv + t0 + tid];
    }

    float acc[4][16];
    #pragma unroll
    for (int i = 0; i < 4; i++)
        #pragma unroll
        for (int j = 0; j < 16; j++) acc[i][j] = 0.f;

    int nst = (t0 >> 6) + 1;
    for (int st = 0; st < nst; st++) {
        int s0 = st << 6;
        __syncthreads();
        const float* kbase = k + ((size_t)(bb * Sv + s0)) * QKv + hh * DQK;
        #pragma unroll
        for (int j = 0; j < 8; j++) {
            int f4 = tid + 256 * j;
            int r = f4 >> 5, d4 = f4 & 31;
            float4 kv4 = *(const float4*)(kbase + (size_t)r * QKv + d4 * 4);
            float* dst = &ks[r * 129 + d4 * 4];
            dst[0] = kv4.x; dst[1] = kv4.y; dst[2] = kv4.z; dst[3] = kv4.w;
        }
        const float* vbase = v + ((size_t)(bb * Sv + s0)) * Dv + hh * DVv;
        #pragma unroll
        for (int j = 0; j < 16; j++) {
            int f4 = tid + 256 * j;
            int r = f4 >> 6, c4 = f4 & 63;
            *(float4*)&vs[r * 260 + c4 * 4] = *(const float4*)(vbase + (size_t)r * Dv + c4 * 4);
        }
        if (tid < 64) aly[tid] = av[bh * Sv + s0 + tid];
        __syncthreads();

        float sc[4][4];
        #pragma unroll
        for (int i = 0; i < 4; i++)
            #pragma unroll
            for (int j = 0; j < 4; j++) sc[i][j] = 0.f;
        const float* qrow = &qs[(ty * 4) * 129];
        const float* krow = &ks[(tx * 4) * 129];
        #pragma unroll 4
        for (int kk = 0; kk < 128; kk++) {
            float a0 = qrow[kk], a1 = qrow[129 + kk], a2 = qrow[258 + kk], a3 = qrow[387 + kk];
            float b0 = krow[kk], b1 = krow[129 + kk], b2 = krow[258 + kk], b3 = krow[387 + kk];
            sc[0][0] += a0 * b0; sc[0][1] += a0 * b1; sc[0][2] += a0 * b2; sc[0][3] += a0 * b3;
            sc[1][0] += a1 * b0; sc[1][1] += a1 * b1; sc[1][2] += a1 * b2; sc[1][3] += a1 * b3;
            sc[2][0] += a2 * b0; sc[2][1] += a2 * b1; sc[2][2] += a2 * b2; sc[2][3] += a2 * b3;
            sc[3][0] += a3 * b0; sc[3][1] += a3 * b1; sc[3][2] += a3 * b2; sc[3][3] += a3 * b3;
        }
        bool diag = (st == nst - 1);
        const float invsq = 0.08838834764831845f;
        #pragma unroll
        for (int i = 0; i < 4; i++) {
            int rloc = ty * 4 + i;
            int tg = t0 + rloc;
            float gt = Gt[rloc];
            float rs = 0.f;
            #pragma unroll
            for (int j = 0; j < 4; j++) {
                int sg = s0 + tx * 4 + j;
                float val;
                if (!diag || sg <= tg) {
                    float w = __expf(aly[tx * 4 + j] - gt) * invsq;
                    val = sc[i][j] * w;
                } else {
                    val = 0.f;
                }
                sc[i][j] = val;
                rs += val;
            }
            atomicAdd(&rowsum[rloc], rs);
        }
        #pragma unroll
        for (int j = 0; j < 4; j++) {
            float4 t4 = make_float4(sc[0][j], sc[1][j], sc[2][j], sc[3][j]);
            *(float4*)&sct[(tx * 4 + j) * 72 + ty * 4] = t4;
        }
        __syncthreads();

        #pragma unroll 4
        for (int s = 0; s < 64; s++) {
            float4 p = *(float4*)&sct[s * 72 + ty * 4];
            float pr[4] = {p.x, p.y, p.z, p.w};
            #pragma unroll
            for (int jg = 0; jg < 4; jg++) {
                float4 vv = *(float4*)&vs[s * 260 + jg * 64 + tx * 4];
                #pragma unroll
                for (int i = 0; i < 4; i++) {
                    acc[i][jg * 4 + 0] += pr[i] * vv.x;
                    acc[i][jg * 4 + 1] += pr[i] * vv.y;
                    acc[i][jg * 4 + 2] += pr[i] * vv.z;
                    acc[i][jg * 4 + 3] += pr[i] * vv.w;
                }
            }
        }
    }
    __syncthreads();

    float* ho = hout + ((size_t)(bb * Sv + t0)) * Dv + hh * DVv;
    #pragma unroll
    for (int i = 0; i < 4; i++) {
        int r = ty * 4 + i;
        float n = fmaxf(fabsf(rowsum[r]), nfl[r]);
        float inv = 1.f / n;
        #pragma unroll
        for (int jg = 0; jg < 4; jg++) {
            float4 o = make_float4(acc[i][jg * 4 + 0] * inv, acc[i][jg * 4 + 1] * inv,
                                   acc[i][jg * 4 + 2] * inv, acc[i][jg * 4 + 3] * inv);
            *(float4*)(ho + (size_t)r * Dv + jg * 64 + tx * 4) = o;
        }
    }
}

// ----------------- per-head RMSNorm + output gate (-> fp16 split) ----------
__global__ void headnorm_kernel(const float* __restrict__ h, const float* __restrict__ opre,
                                const float* __restrict__ mh_w,
                                __half* __restrict__ oh, __half* __restrict__ ol)
{
    int row = blockIdx.x;
    int tid = threadIdx.x;
    int wp = tid >> 5, lane = tid & 31;
    const float* hr = h + (size_t)row * Dv + wp * DVv;
    float vv[8];
    float ss = 0.f;
    #pragma unroll
    for (int j = 0; j < 8; j++) { vv[j] = hr[lane + 32 * j]; ss += vv[j] * vv[j]; }
    #pragma unroll
    for (int o = 16; o > 0; o >>= 1) ss += __shfl_xor_sync(0xffffffffu, ss, o);
    float inv = rsqrtf(ss * (1.f / DVv) + 1e-6f);
    const float* op = opre + (size_t)row * Dv + wp * DVv;
    const float* mw = mh_w + wp * DVv;
    __half* outh = oh + (size_t)row * Dv + wp * DVv;
    __half* outl = ol + (size_t)row * Dv + wp * DVv;
    #pragma unroll
    for (int j = 0; j < 8; j++) {
        int c = lane + 32 * j;
        float o = op[c];
        float sg = 1.f / (1.f + expf(-o));
        float val = sg * vv[j] * inv * mw[c];
        __half hi, lo; split_h(val, hi, lo);
        outh[c] = hi; outl[c] = lo;
    }
}

// --------------------------- launch ----------------------------------------
extern "C" void kernel_launch(void* const* d_in, const int* in_sizes, int n_in,
                              void* d_out, int out_size)
{
    const float* x       = (const float*)d_in[0];
    const float* norm1_w = (const float*)d_in[1];
    const float* wq      = (const float*)d_in[2];
    const float* wk      = (const float*)d_in[3];
    const float* wv      = (const float*)d_in[4];
    const float* w_ig    = (const float*)d_in[5];
    const float* b_ig    = (const float*)d_in[6];
    const float* w_fg    = (const float*)d_in[7];
    const float* b_fg    = (const float*)d_in[8];
    const float* w_og    = (const float*)d_in[9];
    const float* mh_w    = (const float*)d_in[10];
    const float* w_out   = (const float*)d_in[11];
    const float* norm2_w = (const float*)d_in[12];
    const float* w_gate  = (const float*)d_in[13];
    const float* w_up    = (const float*)d_in[14];
    const float* w_down  = (const float*)d_in[15];
    float* out = (float*)d_out;

    void* fp = nullptr; cudaGetSymbolAddress(&fp, g_f32);
    void* hp = nullptr; cudaGetSymbolAddress(&hp, g_fp16);
    float* F = (float*)fp;
    __half* Hh = (__half*)hp;

    float *hin = F+F_HIN, *qb = F+F_Q, *kb = F+F_K, *vb = F+F_V, *opre = F+F_OPRE;
    float *hb = F+F_H, *x1 = F+F_X1, *gate = F+F_GATE;
    float *ipre = F+F_IPRE, *fpre = F+F_FPRE, *ab = F+F_A, *Gb = F+F_G, *nfl = F+F_NFL;

    __half *hinH=Hh+P_HINH, *hinL=Hh+P_HINL, *houtH=Hh+P_HOUTH, *houtL=Hh+P_HOUTL;
    __half *h2H=Hh+P_H2H, *h2L=Hh+P_H2L, *actH=Hh+P_ACTH, *actL=Hh+P_ACTL;
    __half *wqh=Hh+P_WQ, *wkh=Hh+P_WK, *wvh=Hh+P_WV, *wogh=Hh+P_WOG;
    __half *wouth=Hh+P_WOUT, *wgh=Hh+P_WG, *wuh=Hh+P_WU, *wdh=Hh+P_WD;

    cudaFuncSetAttribute(attn_kernel, cudaFuncAttributeMaxDynamicSharedMemorySize, ATT_SMEM_BYTES);
    cudaFuncSetAttribute(tgemm_kernel<0>, cudaFuncAttributeMaxDynamicSharedMemorySize, GSMEM);
    cudaFuncSetAttribute(tgemm_kernel<1>, cudaFuncAttributeMaxDynamicSharedMemorySize, GSMEM);
    cudaFuncSetAttribute(tgemm_kernel<2>, cudaFuncAttributeMaxDynamicSharedMemorySize, GSMEM);

    dim3 tb(32, 8);
    wsplit_kernel<<<dim3(QKv/32, Dv/32), tb>>>(wq, wqh, Dv, QKv);
    wsplit_kernel<<<dim3(QKv/32, Dv/32), tb>>>(wk, wkh, Dv, QKv);
    wsplit_kernel<<<dim3(Dv/32,  Dv/32), tb>>>(wv, wvh, Dv, Dv);
    wsplit_kernel<<<dim3(Dv/32,  Dv/32), tb>>>(w_og, wogh, Dv, Dv);
    wsplit_kernel<<<dim3(Dv/32,  Dv/32), tb>>>(w_out, wouth, Dv, Dv);
    wsplit_kernel<<<dim3(FFv/32, Dv/32), tb>>>(w_gate, wgh, Dv, FFv);
    wsplit_kernel<<<dim3(FFv/32, Dv/32), tb>>>(w_up, wuh, Dv, FFv);
    wsplit_kernel<<<dim3(Dv/32, FFv/32), tb>>>(w_down, wdh, FFv, Dv);

    rmsnorm_kernel<1><<<Mv, 256>>>(x, norm1_w, hin, hinH, hinL);

    tgemm_kernel<0><<<dim3(QKv/128, Mv/128), 256, GSMEM>>>(hinH, hinL, wqh, nullptr, qb, nullptr, nullptr, QKv, Dv);
    tgemm_kernel<0><<<dim3(QKv/128, Mv/128), 256, GSMEM>>>(hinH, hinL, wkh, nullptr, kb, nullptr, nullptr, QKv, Dv);
    tgemm_kernel<0><<<dim3(Dv/128,  Mv/128), 256, GSMEM>>>(hinH, hinL, wvh, nullptr, vb, nullptr, nullptr, Dv, Dv);
    tgemm_kernel<0><<<dim3(Dv/128,  Mv/128), 256, GSMEM>>>(hinH, hinL, wogh, nullptr, opre, nullptr, nullptr, Dv, Dv);

    gates_kernel<<<Mv, 256>>>(hin, w_ig, b_ig, w_fg, b_fg, ipre, fpre);
    scan_kernel<<<BHv, 1024>>>(ipre, fpre, ab, Gb, nfl);
    attn_kernel<<<dim3(Sv/64, BHv), 256, ATT_SMEM_BYTES>>>(qb, kb, vb, ab, Gb, nfl, hb);
    headnorm_kernel<<<Mv, 256>>>(hb, opre, mh_w, houtH, houtL);

    tgemm_kernel<1><<<dim3(Dv/128, Mv/128), 256, GSMEM>>>(houtH, houtL, wouth, x, x1, nullptr, nullptr, Dv, Dv);

    rmsnorm_kernel<0><<<Mv, 256>>>(x1, norm2_w, nullptr, h2H, h2L);

    tgemm_kernel<0><<<dim3(FFv/128, Mv/128), 256, GSMEM>>>(h2H, h2L, wgh, nullptr, gate, nullptr, nullptr, FFv, Dv);
    tgemm_kernel<2><<<dim3(FFv/128, Mv/128), 256, GSMEM>>>(h2H, h2L, wuh, gate, nullptr, actH, actL, FFv, Dv);

    tgemm_kernel<1><<<dim3(Dv/128, Mv/128), 256, GSMEM>>>(actH, actL, wdh, x1, out, nullptr, nullptr, Dv, FFv);

    (void)in_sizes; (void)n_in; (void)out_size;
}

// round 6
// speedup vs baseline: 4.0665x; 1.3151x over previous
#include <cuda_runtime.h>
#include <cuda_fp16.h>
#include <math.h>
#include <stdint.h>

// ---------------------------------------------------------------------------
// BolmoLocalLayer: xLSTM mixer + SwiGLU MLP.  B=2, S=2048, D=2048, H=8.
// Round 6: HMMA GEMMs (2-pass A-split) + HMMA flash-style mLSTM attention
// (fp16 q/k/v/P, register-resident score->A repack, exp-split decay weights).
// ---------------------------------------------------------------------------

#define Bv   2
#define Sv   2048
#define Dv   2048
#define Hv   8
#define QKv  1024
#define DQK  128
#define DVv  256
#define FFv  8192
#define Mv   (Bv*Sv)      // 4096
#define BHv  (Bv*Hv)      // 16

// ----------------------------- fp32 scratch --------------------------------
#define F_HIN   ((size_t)0)
#define F_OPRE  (F_HIN  + (size_t)Mv*Dv)
#define F_H     (F_OPRE + (size_t)Mv*Dv)
#define F_X1    (F_H    + (size_t)Mv*Dv)
#define F_GATE  (F_X1   + (size_t)Mv*Dv)
#define F_IPRE  (F_GATE + (size_t)Mv*FFv)
#define F_FPRE  (F_IPRE + (size_t)BHv*Sv)
#define F_A     (F_FPRE + (size_t)BHv*Sv)
#define F_G     (F_A    + (size_t)BHv*Sv)
#define F_NFL   (F_G    + (size_t)BHv*Sv)
#define F_TOTAL (F_NFL  + (size_t)BHv*Sv)
__device__ __align__(256) float g_f32[F_TOTAL];

// ----------------------------- fp16 scratch --------------------------------
#define P_HINH  ((size_t)0)
#define P_HINL  (P_HINH  + (size_t)Mv*Dv)
#define P_HOUTH (P_HINL  + (size_t)Mv*Dv)
#define P_HOUTL (P_HOUTH + (size_t)Mv*Dv)
#define P_H2H   (P_HOUTL + (size_t)Mv*Dv)
#define P_H2L   (P_H2H   + (size_t)Mv*Dv)
#define P_ACTH  (P_H2L   + (size_t)Mv*Dv)
#define P_ACTL  (P_ACTH  + (size_t)Mv*FFv)
#define P_WQ    (P_ACTL  + (size_t)Mv*FFv)
#define P_WK    (P_WQ    + (size_t)QKv*Dv)
#define P_WV    (P_WK    + (size_t)QKv*Dv)
#define P_WOG   (P_WV    + (size_t)Dv*Dv)
#define P_WOUT  (P_WOG   + (size_t)Dv*Dv)
#define P_WG    (P_WOUT  + (size_t)Dv*Dv)
#define P_WU    (P_WG    + (size_t)FFv*Dv)
#define P_WD    (P_WU    + (size_t)FFv*Dv)
#define P_QH    (P_WD    + (size_t)Dv*FFv)
#define P_KH    (P_QH    + (size_t)Mv*QKv)
#define P_VH    (P_KH    + (size_t)Mv*QKv)
#define P_TOTAL (P_VH    + (size_t)Mv*Dv)
__device__ __align__(256) __half g_fp16[P_TOTAL];

// ----------------------------- helpers -------------------------------------
__device__ __forceinline__ uint32_t smem_u32(const void* p) {
    uint32_t a;
    asm("{ .reg .u64 t; cvta.to.shared.u64 t, %1; cvt.u32.u64 %0, t; }"
        : "=r"(a) : "l"(p));
    return a;
}

__device__ __forceinline__ void cp16(uint32_t sa, const void* g) {
    asm volatile("cp.async.ca.shared.global [%0], [%1], 16;"
                 :: "r"(sa), "l"(g) : "memory");
}
#define CP_COMMIT() asm volatile("cp.async.commit_group;" ::: "memory")
#define CP_WAIT1()  asm volatile("cp.async.wait_group 1;" ::: "memory")
#define CP_WAIT0()  asm volatile("cp.async.wait_group 0;" ::: "memory")

__device__ __forceinline__ void ldsm4(uint32_t* r, uint32_t addr) {
    asm volatile("ldmatrix.sync.aligned.m8n8.x4.shared.b16 {%0,%1,%2,%3}, [%4];"
                 : "=r"(r[0]), "=r"(r[1]), "=r"(r[2]), "=r"(r[3]) : "r"(addr));
}
__device__ __forceinline__ void ldsm4t(uint32_t* r, uint32_t addr) {
    asm volatile("ldmatrix.sync.aligned.m8n8.x4.trans.shared.b16 {%0,%1,%2,%3}, [%4];"
                 : "=r"(r[0]), "=r"(r[1]), "=r"(r[2]), "=r"(r[3]) : "r"(addr));
}

__device__ __forceinline__ void mma16816(float* c, const uint32_t* a,
                                         uint32_t b0, uint32_t b1) {
    asm volatile(
        "mma.sync.aligned.m16n8k16.row.col.f32.f16.f16.f32 "
        "{%0,%1,%2,%3}, {%4,%5,%6,%7}, {%8,%9}, {%0,%1,%2,%3};"
        : "+f"(c[0]), "+f"(c[1]), "+f"(c[2]), "+f"(c[3])
        : "r"(a[0]), "r"(a[1]), "r"(a[2]), "r"(a[3]), "r"(b0), "r"(b1));
}

__device__ __forceinline__ void split_h(float v, __half& hi, __half& lo) {
    hi = __float2half_rn(v);
    lo = __float2half_rn(v - __half2float(hi));
}

// --------------------------- HMMA GEMM (2-pass) ----------------------------
// C[M, N] = epilogue(A @ W).  A: fp16 hi/lo [M][K] K-major (exact sum).
// W: fp16 hi only, pre-transposed [N][K] K-major.
// EPI 0: C fp32 = acc.   EPI 1: C fp32 = aux + acc.
// EPI 2: (CH,CL) fp16 = split(silu(aux) * acc).   EPI 3: CH fp16 = acc.
#define KCH   64
#define RSTRB 144
#define TILEB (128*RSTRB)
#define NSTG  3
#define STAGEB (3*TILEB)
#define GSMEM (NSTG*STAGEB)

template<int EPI>
__global__ void __launch_bounds__(256) tgemm_kernel(
    const __half* __restrict__ AH, const __half* __restrict__ AL,
    const __half* __restrict__ BH,
    const float* __restrict__ aux, float* __restrict__ C,
    __half* __restrict__ CH, __half* __restrict__ CL,
    int N, int K)
{
    extern __shared__ char smem[];
    const uint32_t sb = smem_u32(smem);
    const int tid = threadIdx.x;
    const int lane = tid & 31;
    const int wid = tid >> 5;
    const int wm = wid & 3;
    const int wn = wid >> 2;
    const int m0 = blockIdx.y * 128;
    const int n0 = blockIdx.x * 128;

    const __half* src[3] = { AH + (size_t)m0 * K, AL + (size_t)m0 * K,
                             BH + (size_t)n0 * K };

    float acc[2][8][4];
    #pragma unroll
    for (int i = 0; i < 2; i++)
        #pragma unroll
        for (int j = 0; j < 8; j++)
            #pragma unroll
            for (int e = 0; e < 4; e++) acc[i][j][e] = 0.f;

    const int NC = K / KCH;

    auto load_chunk = [&](int c, int s) {
        #pragma unroll
        for (int t = 0; t < 3; t++) {
            const __half* gb = src[t] + c * KCH;
            uint32_t sbase = sb + (uint32_t)(s * STAGEB + t * TILEB);
            #pragma unroll
            for (int i = 0; i < 4; i++) {
                int seg = tid + 256 * i;
                int row = seg >> 3, s8 = seg & 7;
                cp16(sbase + (uint32_t)(row * RSTRB + s8 * 16),
                     gb + (size_t)row * K + s8 * 8);
            }
        }
    };

    load_chunk(0, 0); CP_COMMIT();
    load_chunk(1, 1); CP_COMMIT();

    const int a_r = (lane & 15);
    const int a_k = (lane >> 4) * 8;
    const int b_r = (lane & 7) + (lane >> 4) * 8;
    const int b_k = ((lane >> 3) & 1) * 8;

    for (int c = 0; c < NC; c++) {
        const int s = c % NSTG;
        if (c + 1 < NC) CP_WAIT1(); else CP_WAIT0();
        __syncthreads();
        if (c + 2 < NC) { load_chunk(c + 2, (c + 2) % NSTG); CP_COMMIT(); }

        const uint32_t bAh = sb + s * STAGEB;
        const uint32_t bAl = bAh + TILEB;
        const uint32_t bBh = bAh + 2 * TILEB;

        #pragma unroll
        for (int kk = 0; kk < KCH; kk += 16) {
            uint32_t aH[2][4], aL[2][4], bf[4][4];
            #pragma unroll
            for (int mt = 0; mt < 2; mt++) {
                int row = wm * 32 + mt * 16 + a_r;
                uint32_t off = (uint32_t)(row * RSTRB + (kk + a_k) * 2);
                ldsm4(aH[mt], bAh + off);
                ldsm4(aL[mt], bAl + off);
            }
            #pragma unroll
            for (int j = 0; j < 4; j++) {
                int row = wn * 64 + j * 16 + b_r;
                uint32_t off = (uint32_t)(row * RSTRB + (kk + b_k) * 2);
                ldsm4(bf[j], bBh + off);
            }
            #pragma unroll
            for (int mt = 0; mt < 2; mt++)
                #pragma unroll
                for (int j = 0; j < 4; j++) {
                    mma16816(acc[mt][2*j],   aH[mt], bf[j][0], bf[j][1]);
                    mma16816(acc[mt][2*j+1], aH[mt], bf[j][2], bf[j][3]);
                }
            #pragma unroll
            for (int mt = 0; mt < 2; mt++)
                #pragma unroll
                for (int j = 0; j < 4; j++) {
                    mma16816(acc[mt][2*j],   aL[mt], bf[j][0], bf[j][1]);
                    mma16816(acc[mt][2*j+1], aL[mt], bf[j][2], bf[j][3]);
                }
        }
    }

    const int mrow = m0 + wm * 32;
    const int ncol = n0 + wn * 64;
    #pragma unroll
    for (int mt = 0; mt < 2; mt++) {
        #pragma unroll
        for (int nt = 0; nt < 8; nt++) {
            int r0 = mrow + mt * 16 + (lane >> 2);
            int r1 = r0 + 8;
            int cc = ncol + nt * 8 + (lane & 3) * 2;
            float* a = acc[mt][nt];
            size_t i0 = (size_t)r0 * N + cc;
            size_t i1 = (size_t)r1 * N + cc;
            if (EPI == 0) {
                *(float2*)(C + i0) = make_float2(a[0], a[1]);
                *(float2*)(C + i1) = make_float2(a[2], a[3]);
            } else if (EPI == 1) {
                float2 x0 = *(const float2*)(aux + i0);
                float2 x1 = *(const float2*)(aux + i1);
                *(float2*)(C + i0) = make_float2(a[0] + x0.x, a[1] + x0.y);
                *(float2*)(C + i1) = make_float2(a[2] + x1.x, a[3] + x1.y);
            } else if (EPI == 2) {
                float2 g0 = *(const float2*)(aux + i0);
                float2 g1 = *(const float2*)(aux + i1);
                float v00 = a[0] * (g0.x / (1.f + __expf(-g0.x)));
                float v01 = a[1] * (g0.y / (1.f + __expf(-g0.y)));
                float v10 = a[2] * (g1.x / (1.f + __expf(-g1.x)));
                float v11 = a[3] * (g1.y / (1.f + __expf(-g1.y)));
                __half h00, l00, h01, l01, h10, l10, h11, l11;
                split_h(v00, h00, l00); split_h(v01, h01, l01);
                split_h(v10, h10, l10); split_h(v11, h11, l11);
                *(__half2*)(CH + i0) = __halves2half2(h00, h01);
                *(__half2*)(CL + i0) = __halves2half2(l00, l01);
                *(__half2*)(CH + i1) = __halves2half2(h10, h11);
                *(__half2*)(CL + i1) = __halves2half2(l10, l11);
            } else {
                __half2 h0 = __floats2half2_rn(a[0], a[1]);
                __half2 h1 = __floats2half2_rn(a[2], a[3]);
                *(__half2*)(CH + i0) = h0;
                *(__half2*)(CH + i1) = h1;
            }
        }
    }
}

// ---------------- weight transpose + fp16 (hi only) ------------------------
__global__ void wsplit_kernel(const float* __restrict__ W,
                              __half* __restrict__ TH, int K, int N)
{
    __shared__ float t[32][33];
    int tx = threadIdx.x, ty = threadIdx.y;
    int n0 = blockIdx.x * 32, k0 = blockIdx.y * 32;
    #pragma unroll
    for (int j = 0; j < 4; j++)
        t[ty + 8 * j][tx] = W[(size_t)(k0 + ty + 8 * j) * N + n0 + tx];
    __syncthreads();
    #pragma unroll
    for (int j = 0; j < 4; j++) {
        float v = t[tx][ty + 8 * j];
        TH[(size_t)(n0 + ty + 8 * j) * K + k0 + tx] = __float2half_rn(v);
    }
}

// --------------------------- RMSNorm (+split) -------------------------------
template<int WRITE_F32>
__global__ void rmsnorm_kernel(const float* __restrict__ x, const float* __restrict__ w,
                               float* __restrict__ out,
                               __half* __restrict__ oh, __half* __restrict__ ol)
{
    int row = blockIdx.x;
    int tid = threadIdx.x;
    const float4* xr = (const float4*)(x + (size_t)row * Dv);
    float4 v0 = xr[tid];
    float4 v1 = xr[tid + 256];
    float ss = v0.x*v0.x + v0.y*v0.y + v0.z*v0.z + v0.w*v0.w
             + v1.x*v1.x + v1.y*v1.y + v1.z*v1.z + v1.w*v1.w;
    #pragma unroll
    for (int o = 16; o > 0; o >>= 1) ss += __shfl_xor_sync(0xffffffffu, ss, o);
    __shared__ float red[8];
    int wp = tid >> 5, lane = tid & 31;
    if (lane == 0) red[wp] = ss;
    __syncthreads();
    float tot = 0.f;
    #pragma unroll
    for (int i = 0; i < 8; i++) tot += red[i];
    float inv = rsqrtf(tot * (1.f / Dv) + 1e-6f);
    const float4* wr = (const float4*)w;
    #pragma unroll
    for (int half_ = 0; half_ < 2; half_++) {
        float4 v = half_ ? v1 : v0;
        float4 ww = wr[tid + 256 * half_];
        float r[4] = { v.x*inv*ww.x, v.y*inv*ww.y, v.z*inv*ww.z, v.w*inv*ww.w };
        size_t idx = (size_t)row * Dv + (tid + 256 * half_) * 4;
        if (WRITE_F32) *(float4*)(out + idx) = make_float4(r[0], r[1], r[2], r[3]);
        __half h4[4], l4[4];
        #pragma unroll
        for (int e = 0; e < 4; e++) split_h(r[e], h4[e], l4[e]);
        *(uint2*)(oh + idx) = *(uint2*)h4;
        *(uint2*)(ol + idx) = *(uint2*)l4;
    }
}

// --------------------------- i/f gate projections ---------------------------
__device__ __forceinline__ float softcap15(float x) {
    return 15.f * tanhf(x * (1.f / 15.f));
}

__global__ void gates_kernel(const float* __restrict__ hin,
                             const float* __restrict__ w_ig, const float* __restrict__ b_ig,
                             const float* __restrict__ w_fg, const float* __restrict__ b_fg,
                             float* __restrict__ ipre, float* __restrict__ fpre)
{
    int row = blockIdx.x;
    int tid = threadIdx.x;
    float pi[8], pf[8];
    #pragma unroll
    for (int h = 0; h < 8; h++) { pi[h] = 0.f; pf[h] = 0.f; }
    const float* xr = hin + (size_t)row * Dv;
    for (int d = tid; d < Dv; d += 256) {
        float xv = xr[d];
        #pragma unroll
        for (int h = 0; h < 8; h++) {
            pi[h] += xv * w_ig[d * 8 + h];
            pf[h] += xv * w_fg[d * 8 + h];
        }
    }
    #pragma unroll
    for (int h = 0; h < 8; h++) {
        #pragma unroll
        for (int o = 16; o > 0; o >>= 1) {
            pi[h] += __shfl_xor_sync(0xffffffffu, pi[h], o);
            pf[h] += __shfl_xor_sync(0xffffffffu, pf[h], o);
        }
    }
    __shared__ float sred[8][16];
    int wp = tid >> 5, lane = tid & 31;
    if (lane == 0) {
        #pragma unroll
        for (int h = 0; h < 8; h++) { sred[wp][h] = pi[h]; sred[wp][8 + h] = pf[h]; }
    }
    __syncthreads();
    if (tid < 16) {
        float s = 0.f;
        #pragma unroll
        for (int w8 = 0; w8 < 8; w8++) s += sred[w8][tid];
        int h = tid & 7;
        bool isf = (tid >= 8);
        float bias = isf ? b_fg[h] : b_ig[h];
        float val = softcap15(s + bias);
        int b = row >> 11;
        int sp = row & (Sv - 1);
        int bh = b * Hv + h;
        (isf ? fpre : ipre)[bh * Sv + sp] = val;
    }
}

// --------------------------- gate scans ------------------------------------
__global__ void scan_kernel(const float* __restrict__ ipre, const float* __restrict__ fpre,
                            float* __restrict__ aout, float* __restrict__ Gout,
                            float* __restrict__ nflout)
{
    int bh = blockIdx.x;
    int tid = threadIdx.x;
    __shared__ float bufA[2048], bufB[2048], fc[2048];

    for (int i = tid; i < 2048; i += 1024) {
        float f = fpre[bh * Sv + i];
        bufA[i] = fminf(f, 0.f) - log1pf(expf(-fabsf(f)));
    }
    __syncthreads();
    float* src = bufA; float* dst = bufB;
    for (int off = 1; off < 2048; off <<= 1) {
        for (int i = tid; i < 2048; i += 1024)
            dst[i] = src[i] + ((i >= off) ? src[i - off] : 0.f);
        __syncthreads();
        float* t = src; src = dst; dst = t;
    }
    for (int i = tid; i < 2048; i += 1024) fc[i] = src[i];
    __syncthreads();
    for (int i = tid; i < 2048; i += 1024) {
        float a = ipre[bh * Sv + i] - fc[i];
        aout[bh * Sv + i] = a;
        dst[i] = a;
    }
    __syncthreads();
    { float* t = src; src = dst; dst = t; }
    for (int off = 1; off < 2048; off <<= 1) {
        for (int i = tid; i < 2048; i += 1024)
            dst[i] = fmaxf(src[i], (i >= off) ? src[i - off] : -1e30f);
        __syncthreads();
        float* t = src; src = dst; dst = t;
    }
    for (int i = tid; i < 2048; i += 1024) {
        float G = src[i];
        Gout[bh * Sv + i] = G;
        nflout[bh * Sv + i] = expf(-(fc[i] + G));
    }
}

// --------------------------- HMMA mLSTM attention ---------------------------
// One CTA = 64 Q-rows of one (b,h); 128 threads (4 warps x 16 rows).
// weight(t,s) = exp(a_s - c0)*exp(c0 - G_t)/sqrt(d);  single pass, no rescale.
#define AQ_STRB 272                      // 128 halves + 8 pad
#define AV_STRB 528                      // 256 halves + 8 pad
#define ATT_Q_OFF   0
#define ATT_K_OFF   (64*AQ_STRB)                 // 17408
#define ATT_V_OFF   (ATT_K_OFF + 64*AQ_STRB)     // 34816
#define ATT_WCOL    (ATT_V_OFF + 64*AV_STRB)     // 68608
#define ATT_C0      (ATT_WCOL + 2048*4)          // 76800
#define ATT_GT      (ATT_C0 + 32*4)              // 76928
#define ATT_NF      (ATT_GT + 64*4)              // 77184
#define ATT_BYTES   (ATT_NF + 64*4)              // 77440

__global__ void __launch_bounds__(128, 2) attn_kernel(
    const __half* __restrict__ qh, const __half* __restrict__ kh,
    const __half* __restrict__ vh,
    const float* __restrict__ av, const float* __restrict__ Gv,
    const float* __restrict__ nfv, float* __restrict__ hout)
{
    extern __shared__ char smem[];
    const uint32_t sb = smem_u32(smem);
    float* wcol = (float*)(smem + ATT_WCOL);
    float* c0s  = (float*)(smem + ATT_C0);
    float* gts  = (float*)(smem + ATT_GT);
    float* nfs  = (float*)(smem + ATT_NF);

    const int bh = blockIdx.y;
    const int bb = bh >> 3, hh = bh & 7;
    const int t0 = ((int)gridDim.x - 1 - (int)blockIdx.x) * 64;  // heavy CTAs first
    const int tid = threadIdx.x, lane = tid & 31, wid = tid >> 5;
    const int nst = (t0 >> 6) + 1;
    const int nS = t0 + 64;

    // Q tile 64x128 fp16
    const __half* qbase = qh + ((size_t)(bb * Sv + t0)) * QKv + hh * DQK;
    #pragma unroll
    for (int i = 0; i < 8; i++) {
        int seg = tid + 128 * i;
        int row = seg >> 4, s16 = seg & 15;
        cp16(sb + ATT_Q_OFF + (uint32_t)(row * AQ_STRB + s16 * 16),
             qbase + (size_t)row * QKv + s16 * 8);
    }
    CP_COMMIT();

    // raw decay logits a_s, per-tile maxima c0, then wcol = exp(a-c0)/sqrt(d)
    for (int s = tid; s < nS; s += 128) wcol[s] = av[(size_t)bh * Sv + s];
    if (tid < 64) {
        gts[tid] = Gv[(size_t)bh * Sv + t0 + tid];
        nfs[tid] = nfv[(size_t)bh * Sv + t0 + tid];
    }
    __syncthreads();
    if (tid < nst) {
        float m = -1e30f;
        #pragma unroll 8
        for (int i = 0; i < 64; i++) m = fmaxf(m, wcol[tid * 64 + i]);
        c0s[tid] = m;
    }
    __syncthreads();
    const float invsq = 0.08838834764831845f;    // 1/sqrt(128)
    for (int s = tid; s < nS; s += 128)
        wcol[s] = __expf(wcol[s] - c0s[s >> 6]) * invsq;
    __syncthreads();

    const int qr = lane >> 2;
    const int r0 = wid * 16 + qr, r1 = r0 + 8;
    const float gt0 = gts[r0], gt1 = gts[r1];

    const int a_r = lane & 15, a_k = (lane >> 4) * 8;
    const int b_r = (lane & 7) + (lane >> 4) * 8;
    const int b_k = ((lane >> 3) & 1) * 8;
    const int v_k = (lane & 7) + ((lane >> 3) & 1) * 8;
    const int v_n = (lane >> 4) * 8;

    float acc[32][4];
    #pragma unroll
    for (int f = 0; f < 32; f++)
        #pragma unroll
        for (int e = 0; e < 4; e++) acc[f][e] = 0.f;
    float rsa0 = 0.f, rsa1 = 0.f;

    for (int st = 0; st < nst; st++) {
        const int s0 = st << 6;
        __syncthreads();                          // K/V smem reuse guard
        const __half* kbase = kh + ((size_t)(bb * Sv + s0)) * QKv + hh * DQK;
        #pragma unroll
        for (int i = 0; i < 8; i++) {
            int seg = tid + 128 * i;
            int row = seg >> 4, s16 = seg & 15;
            cp16(sb + ATT_K_OFF + (uint32_t)(row * AQ_STRB + s16 * 16),
                 kbase + (size_t)row * QKv + s16 * 8);
        }
        const __half* vbase = vh + ((size_t)(bb * Sv + s0)) * Dv + hh * DVv;
        #pragma unroll
        for (int i = 0; i < 16; i++) {
            int seg = tid + 128 * i;
            int row = seg >> 5, s16 = seg & 31;
            cp16(sb + ATT_V_OFF + (uint32_t)(row * AV_STRB + s16 * 16),
                 vbase + (size_t)row * Dv + s16 * 8);
        }
        CP_COMMIT(); CP_WAIT0();
        __syncthreads();

        // ---- scores: m16 x n64 x k128 per warp ----
        float sc[8][4];
        #pragma unroll
        for (int j = 0; j < 8; j++)
            #pragma unroll
            for (int e = 0; e < 4; e++) sc[j][e] = 0.f;
        #pragma unroll
        for (int ks16 = 0; ks16 < 8; ks16++) {
            uint32_t aq[4];
            ldsm4(aq, sb + ATT_Q_OFF +
                  (uint32_t)((wid * 16 + a_r) * AQ_STRB + (ks16 * 16 + a_k) * 2));
            #pragma unroll
            for (int j2 = 0; j2 < 4; j2++) {
                uint32_t bk[4];
                ldsm4(bk, sb + ATT_K_OFF +
                      (uint32_t)((j2 * 16 + b_r) * AQ_STRB + (ks16 * 16 + b_k) * 2));
                mma16816(sc[2*j2],   aq, bk[0], bk[1]);
                mma16816(sc[2*j2+1], aq, bk[2], bk[3]);
            }
        }

        // ---- decay weights + rowsum + repack C->A fp16 ----
        const float w0 = __expf(fminf(c0s[st] - gt0, 80.f));
        const float w1 = __expf(fminf(c0s[st] - gt1, 80.f));
        const bool diag = (st == nst - 1);
        const int tg0 = t0 + r0, tg1 = t0 + r1;
        uint32_t pa[8][2];
        #pragma unroll
        for (int j = 0; j < 8; j++) {
            int cb = s0 + j * 8 + 2 * (lane & 3);
            float wc0 = wcol[cb - s0 + s0];     // wcol indexed globally
            float wc1 = wcol[cb + 1];
            wc0 = wcol[cb];
            float v00 = sc[j][0] * wc0 * w0, v01 = sc[j][1] * wc1 * w0;
            float v10 = sc[j][2] * wc0 * w1, v11 = sc[j][3] * wc1 * w1;
            if (diag) {
                if (cb     > tg0) v00 = 0.f;
                if (cb + 1 > tg0) v01 = 0.f;
                if (cb     > tg1) v10 = 0.f;
                if (cb + 1 > tg1) v11 = 0.f;
            }
            rsa0 += v00 + v01;
            rsa1 += v10 + v11;
            __half2 h0 = __floats2half2_rn(v00, v01);
            __half2 h1 = __floats2half2_rn(v10, v11);
            pa[j][0] = *(uint32_t*)&h0;
            pa[j][1] = *(uint32_t*)&h1;
        }

        // ---- P @ V: m16 x n256 x k64 per warp ----
        #pragma unroll
        for (int kst = 0; kst < 4; kst++) {
            uint32_t af[4] = { pa[2*kst][0], pa[2*kst][1],
                               pa[2*kst+1][0], pa[2*kst+1][1] };
            #pragma unroll
            for (int n16 = 0; n16 < 16; n16++) {
                uint32_t bv[4];
                ldsm4t(bv, sb + ATT_V_OFF +
                       (uint32_t)((kst * 16 + v_k) * AV_STRB + (n16 * 16 + v_n) * 2));
                mma16816(acc[2*n16],   af, bv[0], bv[1]);
                mma16816(acc[2*n16+1], af, bv[2], bv[3]);
            }
        }
    }

    // rowsum reduce within quad (same row, different col subsets)
    rsa0 += __shfl_xor_sync(0xffffffffu, rsa0, 1);
    rsa0 += __shfl_xor_sync(0xffffffffu, rsa0, 2);
    rsa1 += __shfl_xor_sync(0xffffffffu, rsa1, 1);
    rsa1 += __shfl_xor_sync(0xffffffffu, rsa1, 2);

    const float invn0 = 1.f / fmaxf(fabsf(rsa0), nfs[r0]);
    const float invn1 = 1.f / fmaxf(fabsf(rsa1), nfs[r1]);
    float* ho0 = hout + ((size_t)(bb * Sv + t0 + r0)) * Dv + hh * DVv;
    float* ho1 = hout + ((size_t)(bb * Sv + t0 + r1)) * Dv + hh * DVv;
    #pragma unroll
    for (int f = 0; f < 32; f++) {
        int col = f * 8 + 2 * (lane & 3);
        *(float2*)(ho0 + col) = make_float2(acc[f][0] * invn0, acc[f][1] * invn0);
        *(float2*)(ho1 + col) = make_float2(acc[f][2] * invn1, acc[f][3] * invn1);
    }
}

// ----------------- per-head RMSNorm + output gate (-> fp16 split) ----------
__global__ void headnorm_kernel(const float* __restrict__ h, const float* __restrict__ opre,
                                const float* __restrict__ mh_w,
                                __half* __restrict__ oh, __half* __restrict__ ol)
{
    int row = blockIdx.x;
    int tid = threadIdx.x;
    int wp = tid >> 5, lane = tid & 31;
    const float* hr = h + (size_t)row * Dv + wp * DVv;
    float vv[8];
    float ss = 0.f;
    #pragma unroll
    for (int j = 0; j < 8; j++) { vv[j] = hr[lane + 32 * j]; ss += vv[j] * vv[j]; }
    #pragma unroll
    for (int o = 16; o > 0; o >>= 1) ss += __shfl_xor_sync(0xffffffffu, ss, o);
    float inv = rsqrtf(ss * (1.f / DVv) + 1e-6f);
    const float* op = opre + (size_t)row * Dv + wp * DVv;
    const float* mw = mh_w + wp * DVv;
    __half* outh = oh + (size_t)row * Dv + wp * DVv;
    __half* outl = ol + (size_t)row * Dv + wp * DVv;
    #pragma unroll
    for (int j = 0; j < 8; j++) {
        int c = lane + 32 * j;
        float o = op[c];
        float sg = 1.f / (1.f + expf(-o));
        float val = sg * vv[j] * inv * mw[c];
        __half hi, lo; split_h(val, hi, lo);
        outh[c] = hi; outl[c] = lo;
    }
}

// --------------------------- launch ----------------------------------------
extern "C" void kernel_launch(void* const* d_in, const int* in_sizes, int n_in,
                              void* d_out, int out_size)
{
    const float* x       = (const float*)d_in[0];
    const float* norm1_w = (const float*)d_in[1];
    const float* wq      = (const float*)d_in[2];
    const float* wk      = (const float*)d_in[3];
    const float* wv      = (const float*)d_in[4];
    const float* w_ig    = (const float*)d_in[5];
    const float* b_ig    = (const float*)d_in[6];
    const float* w_fg    = (const float*)d_in[7];
    const float* b_fg    = (const float*)d_in[8];
    const float* w_og    = (const float*)d_in[9];
    const float* mh_w    = (const float*)d_in[10];
    const float* w_out   = (const float*)d_in[11];
    const float* norm2_w = (const float*)d_in[12];
    const float* w_gate  = (const float*)d_in[13];
    const float* w_up    = (const float*)d_in[14];
    const float* w_down  = (const float*)d_in[15];
    float* out = (float*)d_out;

    void* fp = nullptr; cudaGetSymbolAddress(&fp, g_f32);
    void* hp = nullptr; cudaGetSymbolAddress(&hp, g_fp16);
    float* F = (float*)fp;
    __half* Hh = (__half*)hp;

    float *hin = F+F_HIN, *opre = F+F_OPRE, *hb = F+F_H, *x1 = F+F_X1, *gate = F+F_GATE;
    float *ipre = F+F_IPRE, *fpre = F+F_FPRE, *ab = F+F_A, *Gb = F+F_G, *nfl = F+F_NFL;

    __half *hinH=Hh+P_HINH, *hinL=Hh+P_HINL, *houtH=Hh+P_HOUTH, *houtL=Hh+P_HOUTL;
    __half *h2H=Hh+P_H2H, *h2L=Hh+P_H2L, *actH=Hh+P_ACTH, *actL=Hh+P_ACTL;
    __half *wqh=Hh+P_WQ, *wkh=Hh+P_WK, *wvh=Hh+P_WV, *wogh=Hh+P_WOG;
    __half *wouth=Hh+P_WOUT, *wgh=Hh+P_WG, *wuh=Hh+P_WU, *wdh=Hh+P_WD;
    __half *qhB=Hh+P_QH, *khB=Hh+P_KH, *vhB=Hh+P_VH;

    cudaFuncSetAttribute(attn_kernel, cudaFuncAttributeMaxDynamicSharedMemorySize, ATT_BYTES);
    cudaFuncSetAttribute(tgemm_kernel<0>, cudaFuncAttributeMaxDynamicSharedMemorySize, GSMEM);
    cudaFuncSetAttribute(tgemm_kernel<1>, cudaFuncAttributeMaxDynamicSharedMemorySize, GSMEM);
    cudaFuncSetAttribute(tgemm_kernel<2>, cudaFuncAttributeMaxDynamicSharedMemorySize, GSMEM);
    cudaFuncSetAttribute(tgemm_kernel<3>, cudaFuncAttributeMaxDynamicSharedMemorySize, GSMEM);

    dim3 tb(32, 8);
    wsplit_kernel<<<dim3(QKv/32, Dv/32), tb>>>(wq, wqh, Dv, QKv);
    wsplit_kernel<<<dim3(QKv/32, Dv/32), tb>>>(wk, wkh, Dv, QKv);
    wsplit_kernel<<<dim3(Dv/32,  Dv/32), tb>>>(wv, wvh, Dv, Dv);
    wsplit_kernel<<<dim3(Dv/32,  Dv/32), tb>>>(w_og, wogh, Dv, Dv);
    wsplit_kernel<<<dim3(Dv/32,  Dv/32), tb>>>(w_out, wouth, Dv, Dv);
    wsplit_kernel<<<dim3(FFv/32, Dv/32), tb>>>(w_gate, wgh, Dv, FFv);
    wsplit_kernel<<<dim3(FFv/32, Dv/32), tb>>>(w_up, wuh, Dv, FFv);
    wsplit_kernel<<<dim3(Dv/32, FFv/32), tb>>>(w_down, wdh, FFv, Dv);

    rmsnorm_kernel<1><<<Mv, 256>>>(x, norm1_w, hin, hinH, hinL);

    // q/k/v projections emit fp16 (EPI 3); og stays fp32 for sigmoid gate
    tgemm_kernel<3><<<dim3(QKv/128, Mv/128), 256, GSMEM>>>(hinH, hinL, wqh, nullptr, nullptr, qhB, nullptr, QKv, Dv);
    tgemm_kernel<3><<<dim3(QKv/128, Mv/128), 256, GSMEM>>>(hinH, hinL, wkh, nullptr, nullptr, khB, nullptr, QKv, Dv);
    tgemm_kernel<3><<<dim3(Dv/128,  Mv/128), 256, GSMEM>>>(hinH, hinL, wvh, nullptr, nullptr, vhB, nullptr, Dv, Dv);
    tgemm_kernel<0><<<dim3(Dv/128,  Mv/128), 256, GSMEM>>>(hinH, hinL, wogh, nullptr, opre, nullptr, nullptr, Dv, Dv);

    gates_kernel<<<Mv, 256>>>(hin, w_ig, b_ig, w_fg, b_fg, ipre, fpre);
    scan_kernel<<<BHv, 1024>>>(ipre, fpre, ab, Gb, nfl);
    attn_kernel<<<dim3(Sv/64, BHv), 128, ATT_BYTES>>>(qhB, khB, vhB, ab, Gb, nfl, hb);
    headnorm_kernel<<<Mv, 256>>>(hb, opre, mh_w, houtH, houtL);

    tgemm_kernel<1><<<dim3(Dv/128, Mv/128), 256, GSMEM>>>(houtH, houtL, wouth, x, x1, nullptr, nullptr, Dv, Dv);

    rmsnorm_kernel<0><<<Mv, 256>>>(x1, norm2_w, nullptr, h2H, h2L);

    tgemm_kernel<0><<<dim3(FFv/128, Mv/128), 256, GSMEM>>>(h2H, h2L, wgh, nullptr, gate, nullptr, nullptr, FFv, Dv);
    tgemm_kernel<2><<<dim3(FFv/128, Mv/128), 256, GSMEM>>>(h2H, h2L, wuh, gate, nullptr, actH, actL, FFv, Dv);

    tgemm_kernel<1><<<dim3(Dv/128, Mv/128), 256, GSMEM>>>(actH, actL, wdh, x1, out, nullptr, nullptr, Dv, FFv);

    (void)in_sizes; (void)n_in; (void)out_size;
}

// round 7
// speedup vs baseline: 5.9608x; 1.4658x over previous
#include <cuda_runtime.h>
#include <cuda_fp16.h>
#include <math.h>
#include <stdint.h>

// ---------------------------------------------------------------------------
// BolmoLocalLayer: xLSTM mixer + SwiGLU MLP.  B=2, S=2048, D=2048, H=8.
// Round 7: 1-pass fp16 HMMA GEMMs (A and W both fp16, fp32 accum) +
// HMMA flash-style mLSTM attention.
// ---------------------------------------------------------------------------

#define Bv   2
#define Sv   2048
#define Dv   2048
#define Hv   8
#define QKv  1024
#define DQK  128
#define DVv  256
#define FFv  8192
#define Mv   (Bv*Sv)      // 4096
#define BHv  (Bv*Hv)      // 16

// ----------------------------- fp32 scratch --------------------------------
#define F_HIN   ((size_t)0)
#define F_OPRE  (F_HIN  + (size_t)Mv*Dv)
#define F_H     (F_OPRE + (size_t)Mv*Dv)
#define F_X1    (F_H    + (size_t)Mv*Dv)
#define F_GATE  (F_X1   + (size_t)Mv*Dv)
#define F_IPRE  (F_GATE + (size_t)Mv*FFv)
#define F_FPRE  (F_IPRE + (size_t)BHv*Sv)
#define F_A     (F_FPRE + (size_t)BHv*Sv)
#define F_G     (F_A    + (size_t)BHv*Sv)
#define F_NFL   (F_G    + (size_t)BHv*Sv)
#define F_TOTAL (F_NFL  + (size_t)BHv*Sv)
__device__ __align__(256) float g_f32[F_TOTAL];

// ----------------------------- fp16 scratch --------------------------------
#define P_HIN   ((size_t)0)
#define P_HOUT  (P_HIN   + (size_t)Mv*Dv)
#define P_H2    (P_HOUT  + (size_t)Mv*Dv)
#define P_ACT   (P_H2    + (size_t)Mv*Dv)
#define P_WQ    (P_ACT   + (size_t)Mv*FFv)
#define P_WK    (P_WQ    + (size_t)QKv*Dv)
#define P_WV    (P_WK    + (size_t)QKv*Dv)
#define P_WOG   (P_WV    + (size_t)Dv*Dv)
#define P_WOUT  (P_WOG   + (size_t)Dv*Dv)
#define P_WG    (P_WOUT  + (size_t)Dv*Dv)
#define P_WU    (P_WG    + (size_t)FFv*Dv)
#define P_WD    (P_WU    + (size_t)FFv*Dv)
#define P_QH    (P_WD    + (size_t)Dv*FFv)
#define P_KH    (P_QH    + (size_t)Mv*QKv)
#define P_VH    (P_KH    + (size_t)Mv*QKv)
#define P_TOTAL (P_VH    + (size_t)Mv*Dv)
__device__ __align__(256) __half g_fp16[P_TOTAL];

// ----------------------------- helpers -------------------------------------
__device__ __forceinline__ uint32_t smem_u32(const void* p) {
    uint32_t a;
    asm("{ .reg .u64 t; cvta.to.shared.u64 t, %1; cvt.u32.u64 %0, t; }"
        : "=r"(a) : "l"(p));
    return a;
}

__device__ __forceinline__ void cp16(uint32_t sa, const void* g) {
    asm volatile("cp.async.ca.shared.global [%0], [%1], 16;"
                 :: "r"(sa), "l"(g) : "memory");
}
#define CP_COMMIT() asm volatile("cp.async.commit_group;" ::: "memory")
#define CP_WAIT1()  asm volatile("cp.async.wait_group 1;" ::: "memory")
#define CP_WAIT0()  asm volatile("cp.async.wait_group 0;" ::: "memory")

__device__ __forceinline__ void ldsm4(uint32_t* r, uint32_t addr) {
    asm volatile("ldmatrix.sync.aligned.m8n8.x4.shared.b16 {%0,%1,%2,%3}, [%4];"
                 : "=r"(r[0]), "=r"(r[1]), "=r"(r[2]), "=r"(r[3]) : "r"(addr));
}
__device__ __forceinline__ void ldsm4t(uint32_t* r, uint32_t addr) {
    asm volatile("ldmatrix.sync.aligned.m8n8.x4.trans.shared.b16 {%0,%1,%2,%3}, [%4];"
                 : "=r"(r[0]), "=r"(r[1]), "=r"(r[2]), "=r"(r[3]) : "r"(addr));
}

__device__ __forceinline__ void mma16816(float* c, const uint32_t* a,
                                         uint32_t b0, uint32_t b1) {
    asm volatile(
        "mma.sync.aligned.m16n8k16.row.col.f32.f16.f16.f32 "
        "{%0,%1,%2,%3}, {%4,%5,%6,%7}, {%8,%9}, {%0,%1,%2,%3};"
        : "+f"(c[0]), "+f"(c[1]), "+f"(c[2]), "+f"(c[3])
        : "r"(a[0]), "r"(a[1]), "r"(a[2]), "r"(a[3]), "r"(b0), "r"(b1));
}

// --------------------------- HMMA GEMM (1-pass fp16) ------------------------
// C[M, N] = epilogue(A @ W).  A: fp16 [M][K] K-major.
// W: fp16 pre-transposed [N][K] K-major.
// EPI 0: C fp32 = acc.   EPI 1: C fp32 = aux + acc.
// EPI 2: CH fp16 = silu(aux) * acc.   EPI 3: CH fp16 = acc.
#define KCH   64
#define RSTRB 144
#define TILEB (128*RSTRB)
#define NSTG  3
#define STAGEB (2*TILEB)
#define GSMEM (NSTG*STAGEB)

template<int EPI>
__global__ void __launch_bounds__(256) tgemm_kernel(
    const __half* __restrict__ AH, const __half* __restrict__ BH,
    const float* __restrict__ aux, float* __restrict__ C,
    __half* __restrict__ CH, int N, int K)
{
    extern __shared__ char smem[];
    const uint32_t sb = smem_u32(smem);
    const int tid = threadIdx.x;
    const int lane = tid & 31;
    const int wid = tid >> 5;
    const int wm = wid & 3;
    const int wn = wid >> 2;
    const int m0 = blockIdx.y * 128;
    const int n0 = blockIdx.x * 128;

    const __half* src[2] = { AH + (size_t)m0 * K, BH + (size_t)n0 * K };

    float acc[2][8][4];
    #pragma unroll
    for (int i = 0; i < 2; i++)
        #pragma unroll
        for (int j = 0; j < 8; j++)
            #pragma unroll
            for (int e = 0; e < 4; e++) acc[i][j][e] = 0.f;

    const int NC = K / KCH;

    auto load_chunk = [&](int c, int s) {
        #pragma unroll
        for (int t = 0; t < 2; t++) {
            const __half* gb = src[t] + c * KCH;
            uint32_t sbase = sb + (uint32_t)(s * STAGEB + t * TILEB);
            #pragma unroll
            for (int i = 0; i < 4; i++) {
                int seg = tid + 256 * i;
                int row = seg >> 3, s8 = seg & 7;
                cp16(sbase + (uint32_t)(row * RSTRB + s8 * 16),
                     gb + (size_t)row * K + s8 * 8);
            }
        }
    };

    load_chunk(0, 0); CP_COMMIT();
    load_chunk(1, 1); CP_COMMIT();

    const int a_r = (lane & 15);
    const int a_k = (lane >> 4) * 8;
    const int b_r = (lane & 7) + (lane >> 4) * 8;
    const int b_k = ((lane >> 3) & 1) * 8;

    for (int c = 0; c < NC; c++) {
        const int s = c % NSTG;
        if (c + 1 < NC) CP_WAIT1(); else CP_WAIT0();
        __syncthreads();
        if (c + 2 < NC) { load_chunk(c + 2, (c + 2) % NSTG); CP_COMMIT(); }

        const uint32_t bAh = sb + s * STAGEB;
        const uint32_t bBh = bAh + TILEB;

        #pragma unroll
        for (int kk = 0; kk < KCH; kk += 16) {
            uint32_t aH[2][4], bf[4][4];
            #pragma unroll
            for (int mt = 0; mt < 2; mt++) {
                int row = wm * 32 + mt * 16 + a_r;
                ldsm4(aH[mt], bAh + (uint32_t)(row * RSTRB + (kk + a_k) * 2));
            }
            #pragma unroll
            for (int j = 0; j < 4; j++) {
                int row = wn * 64 + j * 16 + b_r;
                ldsm4(bf[j], bBh + (uint32_t)(row * RSTRB + (kk + b_k) * 2));
            }
            #pragma unroll
            for (int mt = 0; mt < 2; mt++)
                #pragma unroll
                for (int j = 0; j < 4; j++) {
                    mma16816(acc[mt][2*j],   aH[mt], bf[j][0], bf[j][1]);
                    mma16816(acc[mt][2*j+1], aH[mt], bf[j][2], bf[j][3]);
                }
        }
    }

    const int mrow = m0 + wm * 32;
    const int ncol = n0 + wn * 64;
    #pragma unroll
    for (int mt = 0; mt < 2; mt++) {
        #pragma unroll
        for (int nt = 0; nt < 8; nt++) {
            int r0 = mrow + mt * 16 + (lane >> 2);
            int r1 = r0 + 8;
            int cc = ncol + nt * 8 + (lane & 3) * 2;
            float* a = acc[mt][nt];
            size_t i0 = (size_t)r0 * N + cc;
            size_t i1 = (size_t)r1 * N + cc;
            if (EPI == 0) {
                *(float2*)(C + i0) = make_float2(a[0], a[1]);
                *(float2*)(C + i1) = make_float2(a[2], a[3]);
            } else if (EPI == 1) {
                float2 x0 = *(const float2*)(aux + i0);
                float2 x1 = *(const float2*)(aux + i1);
                *(float2*)(C + i0) = make_float2(a[0] + x0.x, a[1] + x0.y);
                *(float2*)(C + i1) = make_float2(a[2] + x1.x, a[3] + x1.y);
            } else if (EPI == 2) {
                float2 g0 = *(const float2*)(aux + i0);
                float2 g1 = *(const float2*)(aux + i1);
                float v00 = a[0] * (g0.x / (1.f + __expf(-g0.x)));
                float v01 = a[1] * (g0.y / (1.f + __expf(-g0.y)));
                float v10 = a[2] * (g1.x / (1.f + __expf(-g1.x)));
                float v11 = a[3] * (g1.y / (1.f + __expf(-g1.y)));
                *(__half2*)(CH + i0) = __floats2half2_rn(v00, v01);
                *(__half2*)(CH + i1) = __floats2half2_rn(v10, v11);
            } else {
                *(__half2*)(CH + i0) = __floats2half2_rn(a[0], a[1]);
                *(__half2*)(CH + i1) = __floats2half2_rn(a[2], a[3]);
            }
        }
    }
}

// ---------------- weight transpose -> fp16 ---------------------------------
__global__ void wsplit_kernel(const float* __restrict__ W,
                              __half* __restrict__ TH, int K, int N)
{
    __shared__ float t[32][33];
    int tx = threadIdx.x, ty = threadIdx.y;
    int n0 = blockIdx.x * 32, k0 = blockIdx.y * 32;
    #pragma unroll
    for (int j = 0; j < 4; j++)
        t[ty + 8 * j][tx] = W[(size_t)(k0 + ty + 8 * j) * N + n0 + tx];
    __syncthreads();
    #pragma unroll
    for (int j = 0; j < 4; j++) {
        float v = t[tx][ty + 8 * j];
        TH[(size_t)(n0 + ty + 8 * j) * K + k0 + tx] = __float2half_rn(v);
    }
}

// --------------------------- RMSNorm (-> fp16, optional fp32) ---------------
template<int WRITE_F32>
__global__ void rmsnorm_kernel(const float* __restrict__ x, const float* __restrict__ w,
                               float* __restrict__ out, __half* __restrict__ oh)
{
    int row = blockIdx.x;
    int tid = threadIdx.x;
    const float4* xr = (const float4*)(x + (size_t)row * Dv);
    float4 v0 = xr[tid];
    float4 v1 = xr[tid + 256];
    float ss = v0.x*v0.x + v0.y*v0.y + v0.z*v0.z + v0.w*v0.w
             + v1.x*v1.x + v1.y*v1.y + v1.z*v1.z + v1.w*v1.w;
    #pragma unroll
    for (int o = 16; o > 0; o >>= 1) ss += __shfl_xor_sync(0xffffffffu, ss, o);
    __shared__ float red[8];
    int wp = tid >> 5, lane = tid & 31;
    if (lane == 0) red[wp] = ss;
    __syncthreads();
    float tot = 0.f;
    #pragma unroll
    for (int i = 0; i < 8; i++) tot += red[i];
    float inv = rsqrtf(tot * (1.f / Dv) + 1e-6f);
    const float4* wr = (const float4*)w;
    #pragma unroll
    for (int half_ = 0; half_ < 2; half_++) {
        float4 v = half_ ? v1 : v0;
        float4 ww = wr[tid + 256 * half_];
        float r[4] = { v.x*inv*ww.x, v.y*inv*ww.y, v.z*inv*ww.z, v.w*inv*ww.w };
        size_t idx = (size_t)row * Dv + (tid + 256 * half_) * 4;
        if (WRITE_F32) *(float4*)(out + idx) = make_float4(r[0], r[1], r[2], r[3]);
        __half2 h0 = __floats2half2_rn(r[0], r[1]);
        __half2 h1 = __floats2half2_rn(r[2], r[3]);
        *(__half2*)(oh + idx) = h0;
        *(__half2*)(oh + idx + 2) = h1;
    }
}

// --------------------------- i/f gate projections ---------------------------
__device__ __forceinline__ float softcap15(float x) {
    return 15.f * tanhf(x * (1.f / 15.f));
}

__global__ void gates_kernel(const float* __restrict__ hin,
                             const float* __restrict__ w_ig, const float* __restrict__ b_ig,
                             const float* __restrict__ w_fg, const float* __restrict__ b_fg,
                             float* __restrict__ ipre, float* __restrict__ fpre)
{
    int row = blockIdx.x;
    int tid = threadIdx.x;
    float pi[8], pf[8];
    #pragma unroll
    for (int h = 0; h < 8; h++) { pi[h] = 0.f; pf[h] = 0.f; }
    const float* xr = hin + (size_t)row * Dv;
    for (int d = tid; d < Dv; d += 256) {
        float xv = xr[d];
        #pragma unroll
        for (int h = 0; h < 8; h++) {
            pi[h] += xv * w_ig[d * 8 + h];
            pf[h] += xv * w_fg[d * 8 + h];
        }
    }
    #pragma unroll
    for (int h = 0; h < 8; h++) {
        #pragma unroll
        for (int o = 16; o > 0; o >>= 1) {
            pi[h] += __shfl_xor_sync(0xffffffffu, pi[h], o);
            pf[h] += __shfl_xor_sync(0xffffffffu, pf[h], o);
        }
    }
    __shared__ float sred[8][16];
    int wp = tid >> 5, lane = tid & 31;
    if (lane == 0) {
        #pragma unroll
        for (int h = 0; h < 8; h++) { sred[wp][h] = pi[h]; sred[wp][8 + h] = pf[h]; }
    }
    __syncthreads();
    if (tid < 16) {
        float s = 0.f;
        #pragma unroll
        for (int w8 = 0; w8 < 8; w8++) s += sred[w8][tid];
        int h = tid & 7;
        bool isf = (tid >= 8);
        float bias = isf ? b_fg[h] : b_ig[h];
        float val = softcap15(s + bias);
        int b = row >> 11;
        int sp = row & (Sv - 1);
        int bh = b * Hv + h;
        (isf ? fpre : ipre)[bh * Sv + sp] = val;
    }
}

// --------------------------- gate scans ------------------------------------
__global__ void scan_kernel(const float* __restrict__ ipre, const float* __restrict__ fpre,
                            float* __restrict__ aout, float* __restrict__ Gout,
                            float* __restrict__ nflout)
{
    int bh = blockIdx.x;
    int tid = threadIdx.x;
    __shared__ float bufA[2048], bufB[2048], fc[2048];

    for (int i = tid; i < 2048; i += 1024) {
        float f = fpre[bh * Sv + i];
        bufA[i] = fminf(f, 0.f) - log1pf(expf(-fabsf(f)));
    }
    __syncthreads();
    float* src = bufA; float* dst = bufB;
    for (int off = 1; off < 2048; off <<= 1) {
        for (int i = tid; i < 2048; i += 1024)
            dst[i] = src[i] + ((i >= off) ? src[i - off] : 0.f);
        __syncthreads();
        float* t = src; src = dst; dst = t;
    }
    for (int i = tid; i < 2048; i += 1024) fc[i] = src[i];
    __syncthreads();
    for (int i = tid; i < 2048; i += 1024) {
        float a = ipre[bh * Sv + i] - fc[i];
        aout[bh * Sv + i] = a;
        dst[i] = a;
    }
    __syncthreads();
    { float* t = src; src = dst; dst = t; }
    for (int off = 1; off < 2048; off <<= 1) {
        for (int i = tid; i < 2048; i += 1024)
            dst[i] = fmaxf(src[i], (i >= off) ? src[i - off] : -1e30f);
        __syncthreads();
        float* t = src; src = dst; dst = t;
    }
    for (int i = tid; i < 2048; i += 1024) {
        float G = src[i];
        Gout[bh * Sv + i] = G;
        nflout[bh * Sv + i] = expf(-(fc[i] + G));
    }
}

// --------------------------- HMMA mLSTM attention ---------------------------
#define AQ_STRB 272
#define AV_STRB 528
#define ATT_Q_OFF   0
#define ATT_K_OFF   (64*AQ_STRB)
#define ATT_V_OFF   (ATT_K_OFF + 64*AQ_STRB)
#define ATT_WCOL    (ATT_V_OFF + 64*AV_STRB)
#define ATT_C0      (ATT_WCOL + 2048*4)
#define ATT_GT      (ATT_C0 + 32*4)
#define ATT_NF      (ATT_GT + 64*4)
#define ATT_BYTES   (ATT_NF + 64*4)

__global__ void __launch_bounds__(128, 2) attn_kernel(
    const __half* __restrict__ qh, const __half* __restrict__ kh,
    const __half* __restrict__ vh,
    const float* __restrict__ av, const float* __restrict__ Gv,
    const float* __restrict__ nfv, float* __restrict__ hout)
{
    extern __shared__ char smem[];
    const uint32_t sb = smem_u32(smem);
    float* wcol = (float*)(smem + ATT_WCOL);
    float* c0s  = (float*)(smem + ATT_C0);
    float* gts  = (float*)(smem + ATT_GT);
    float* nfs  = (float*)(smem + ATT_NF);

    const int bh = blockIdx.y;
    const int bb = bh >> 3, hh = bh & 7;
    const int t0 = ((int)gridDim.x - 1 - (int)blockIdx.x) * 64;
    const int tid = threadIdx.x, lane = tid & 31, wid = tid >> 5;
    const int nst = (t0 >> 6) + 1;
    const int nS = t0 + 64;

    const __half* qbase = qh + ((size_t)(bb * Sv + t0)) * QKv + hh * DQK;
    #pragma unroll
    for (int i = 0; i < 8; i++) {
        int seg = tid + 128 * i;
        int row = seg >> 4, s16 = seg & 15;
        cp16(sb + ATT_Q_OFF + (uint32_t)(row * AQ_STRB + s16 * 16),
             qbase + (size_t)row * QKv + s16 * 8);
    }
    CP_COMMIT();

    for (int s = tid; s < nS; s += 128) wcol[s] = av[(size_t)bh * Sv + s];
    if (tid < 64) {
        gts[tid] = Gv[(size_t)bh * Sv + t0 + tid];
        nfs[tid] = nfv[(size_t)bh * Sv + t0 + tid];
    }
    __syncthreads();
    if (tid < nst) {
        float m = -1e30f;
        #pragma unroll 8
        for (int i = 0; i < 64; i++) m = fmaxf(m, wcol[tid * 64 + i]);
        c0s[tid] = m;
    }
    __syncthreads();
    const float invsq = 0.08838834764831845f;
    for (int s = tid; s < nS; s += 128)
        wcol[s] = __expf(wcol[s] - c0s[s >> 6]) * invsq;
    __syncthreads();

    const int qr = lane >> 2;
    const int r0 = wid * 16 + qr, r1 = r0 + 8;
    const float gt0 = gts[r0], gt1 = gts[r1];

    const int a_r = lane & 15, a_k = (lane >> 4) * 8;
    const int b_r = (lane & 7) + (lane >> 4) * 8;
    const int b_k = ((lane >> 3) & 1) * 8;
    const int v_k = (lane & 7) + ((lane >> 3) & 1) * 8;
    const int v_n = (lane >> 4) * 8;

    float acc[32][4];
    #pragma unroll
    for (int f = 0; f < 32; f++)
        #pragma unroll
        for (int e = 0; e < 4; e++) acc[f][e] = 0.f;
    float rsa0 = 0.f, rsa1 = 0.f;

    for (int st = 0; st < nst; st++) {
        const int s0 = st << 6;
        __syncthreads();
        const __half* kbase = kh + ((size_t)(bb * Sv + s0)) * QKv + hh * DQK;
        #pragma unroll
        for (int i = 0; i < 8; i++) {
            int seg = tid + 128 * i;
            int row = seg >> 4, s16 = seg & 15;
            cp16(sb + ATT_K_OFF + (uint32_t)(row * AQ_STRB + s16 * 16),
                 kbase + (size_t)row * QKv + s16 * 8);
        }
        const __half* vbase = vh + ((size_t)(bb * Sv + s0)) * Dv + hh * DVv;
        #pragma unroll
        for (int i = 0; i < 16; i++) {
            int seg = tid + 128 * i;
            int row = seg >> 5, s16 = seg & 31;
            cp16(sb + ATT_V_OFF + (uint32_t)(row * AV_STRB + s16 * 16),
                 vbase + (size_t)row * Dv + s16 * 8);
        }
        CP_COMMIT(); CP_WAIT0();
        __syncthreads();

        float sc[8][4];
        #pragma unroll
        for (int j = 0; j < 8; j++)
            #pragma unroll
            for (int e = 0; e < 4; e++) sc[j][e] = 0.f;
        #pragma unroll
        for (int ks16 = 0; ks16 < 8; ks16++) {
            uint32_t aq[4];
            ldsm4(aq, sb + ATT_Q_OFF +
                  (uint32_t)((wid * 16 + a_r) * AQ_STRB + (ks16 * 16 + a_k) * 2));
            #pragma unroll
            for (int j2 = 0; j2 < 4; j2++) {
                uint32_t bk[4];
                ldsm4(bk, sb + ATT_K_OFF +
                      (uint32_t)((j2 * 16 + b_r) * AQ_STRB + (ks16 * 16 + b_k) * 2));
                mma16816(sc[2*j2],   aq, bk[0], bk[1]);
                mma16816(sc[2*j2+1], aq, bk[2], bk[3]);
            }
        }

        const float w0 = __expf(fminf(c0s[st] - gt0, 80.f));
        const float w1 = __expf(fminf(c0s[st] - gt1, 80.f));
        const bool diag = (st == nst - 1);
        const int tg0 = t0 + r0, tg1 = t0 + r1;
        uint32_t pa[8][2];
        #pragma unroll
        for (int j = 0; j < 8; j++) {
            int cb = s0 + j * 8 + 2 * (lane & 3);
            float wc0 = wcol[cb];
            float wc1 = wcol[cb + 1];
            float v00 = sc[j][0] * wc0 * w0, v01 = sc[j][1] * wc1 * w0;
            float v10 = sc[j][2] * wc0 * w1, v11 = sc[j][3] * wc1 * w1;
            if (diag) {
                if (cb     > tg0) v00 = 0.f;
                if (cb + 1 > tg0) v01 = 0.f;
                if (cb     > tg1) v10 = 0.f;
                if (cb + 1 > tg1) v11 = 0.f;
            }
            rsa0 += v00 + v01;
            rsa1 += v10 + v11;
            __half2 h0 = __floats2half2_rn(v00, v01);
            __half2 h1 = __floats2half2_rn(v10, v11);
            pa[j][0] = *(uint32_t*)&h0;
            pa[j][1] = *(uint32_t*)&h1;
        }

        #pragma unroll
        for (int kst = 0; kst < 4; kst++) {
            uint32_t af[4] = { pa[2*kst][0], pa[2*kst][1],
                               pa[2*kst+1][0], pa[2*kst+1][1] };
            #pragma unroll
            for (int n16 = 0; n16 < 16; n16++) {
                uint32_t bv[4];
                ldsm4t(bv, sb + ATT_V_OFF +
                       (uint32_t)((kst * 16 + v_k) * AV_STRB + (n16 * 16 + v_n) * 2));
                mma16816(acc[2*n16],   af, bv[0], bv[1]);
                mma16816(acc[2*n16+1], af, bv[2], bv[3]);
            }
        }
    }

    rsa0 += __shfl_xor_sync(0xffffffffu, rsa0, 1);
    rsa0 += __shfl_xor_sync(0xffffffffu, rsa0, 2);
    rsa1 += __shfl_xor_sync(0xffffffffu, rsa1, 1);
    rsa1 += __shfl_xor_sync(0xffffffffu, rsa1, 2);

    const float invn0 = 1.f / fmaxf(fabsf(rsa0), nfs[r0]);
    const float invn1 = 1.f / fmaxf(fabsf(rsa1), nfs[r1]);
    float* ho0 = hout + ((size_t)(bb * Sv + t0 + r0)) * Dv + hh * DVv;
    float* ho1 = hout + ((size_t)(bb * Sv + t0 + r1)) * Dv + hh * DVv;
    #pragma unroll
    for (int f = 0; f < 32; f++) {
        int col = f * 8 + 2 * (lane & 3);
        *(float2*)(ho0 + col) = make_float2(acc[f][0] * invn0, acc[f][1] * invn0);
        *(float2*)(ho1 + col) = make_float2(acc[f][2] * invn1, acc[f][3] * invn1);
    }
}

// ----------------- per-head RMSNorm + output gate (-> fp16) ----------------
__global__ void headnorm_kernel(const float* __restrict__ h, const float* __restrict__ opre,
                                const float* __restrict__ mh_w,
                                __half* __restrict__ oh)
{
    int row = blockIdx.x;
    int tid = threadIdx.x;
    int wp = tid >> 5, lane = tid & 31;
    const float* hr = h + (size_t)row * Dv + wp * DVv;
    float vv[8];
    float ss = 0.f;
    #pragma unroll
    for (int j = 0; j < 8; j++) { vv[j] = hr[lane + 32 * j]; ss += vv[j] * vv[j]; }
    #pragma unroll
    for (int o = 16; o > 0; o >>= 1) ss += __shfl_xor_sync(0xffffffffu, ss, o);
    float inv = rsqrtf(ss * (1.f / DVv) + 1e-6f);
    const float* op = opre + (size_t)row * Dv + wp * DVv;
    const float* mw = mh_w + wp * DVv;
    __half* outh = oh + (size_t)row * Dv + wp * DVv;
    #pragma unroll
    for (int j = 0; j < 8; j++) {
        int c = lane + 32 * j;
        float o = op[c];
        float sg = 1.f / (1.f + expf(-o));
        outh[c] = __float2half_rn(sg * vv[j] * inv * mw[c]);
    }
}

// --------------------------- launch ----------------------------------------
extern "C" void kernel_launch(void* const* d_in, const int* in_sizes, int n_in,
                              void* d_out, int out_size)
{
    const float* x       = (const float*)d_in[0];
    const float* norm1_w = (const float*)d_in[1];
    const float* wq      = (const float*)d_in[2];
    const float* wk      = (const float*)d_in[3];
    const float* wv      = (const float*)d_in[4];
    const float* w_ig    = (const float*)d_in[5];
    const float* b_ig    = (const float*)d_in[6];
    const float* w_fg    = (const float*)d_in[7];
    const float* b_fg    = (const float*)d_in[8];
    const float* w_og    = (const float*)d_in[9];
    const float* mh_w    = (const float*)d_in[10];
    const float* w_out   = (const float*)d_in[11];
    const float* norm2_w = (const float*)d_in[12];
    const float* w_gate  = (const float*)d_in[13];
    const float* w_up    = (const float*)d_in[14];
    const float* w_down  = (const float*)d_in[15];
    float* out = (float*)d_out;

    void* fp = nullptr; cudaGetSymbolAddress(&fp, g_f32);
    void* hp = nullptr; cudaGetSymbolAddress(&hp, g_fp16);
    float* F = (float*)fp;
    __half* Hh = (__half*)hp;

    float *hin = F+F_HIN, *opre = F+F_OPRE, *hb = F+F_H, *x1 = F+F_X1, *gate = F+F_GATE;
    float *ipre = F+F_IPRE, *fpre = F+F_FPRE, *ab = F+F_A, *Gb = F+F_G, *nfl = F+F_NFL;

    __half *hinP=Hh+P_HIN, *houtP=Hh+P_HOUT, *h2P=Hh+P_H2, *actP=Hh+P_ACT;
    __half *wqh=Hh+P_WQ, *wkh=Hh+P_WK, *wvh=Hh+P_WV, *wogh=Hh+P_WOG;
    __half *wouth=Hh+P_WOUT, *wgh=Hh+P_WG, *wuh=Hh+P_WU, *wdh=Hh+P_WD;
    __half *qhB=Hh+P_QH, *khB=Hh+P_KH, *vhB=Hh+P_VH;

    cudaFuncSetAttribute(attn_kernel, cudaFuncAttributeMaxDynamicSharedMemorySize, ATT_BYTES);
    cudaFuncSetAttribute(tgemm_kernel<0>, cudaFuncAttributeMaxDynamicSharedMemorySize, GSMEM);
    cudaFuncSetAttribute(tgemm_kernel<1>, cudaFuncAttributeMaxDynamicSharedMemorySize, GSMEM);
    cudaFuncSetAttribute(tgemm_kernel<2>, cudaFuncAttributeMaxDynamicSharedMemorySize, GSMEM);
    cudaFuncSetAttribute(tgemm_kernel<3>, cudaFuncAttributeMaxDynamicSharedMemorySize, GSMEM);

    dim3 tb(32, 8);
    wsplit_kernel<<<dim3(QKv/32, Dv/32), tb>>>(wq, wqh, Dv, QKv);
    wsplit_kernel<<<dim3(QKv/32, Dv/32), tb>>>(wk, wkh, Dv, QKv);
    wsplit_kernel<<<dim3(Dv/32,  Dv/32), tb>>>(wv, wvh, Dv, Dv);
    wsplit_kernel<<<dim3(Dv/32,  Dv/32), tb>>>(w_og, wogh, Dv, Dv);
    wsplit_kernel<<<dim3(Dv/32,  Dv/32), tb>>>(w_out, wouth, Dv, Dv);
    wsplit_kernel<<<dim3(FFv/32, Dv/32), tb>>>(w_gate, wgh, Dv, FFv);
    wsplit_kernel<<<dim3(FFv/32, Dv/32), tb>>>(w_up, wuh, Dv, FFv);
    wsplit_kernel<<<dim3(Dv/32, FFv/32), tb>>>(w_down, wdh, FFv, Dv);

    rmsnorm_kernel<1><<<Mv, 256>>>(x, norm1_w, hin, hinP);

    tgemm_kernel<3><<<dim3(QKv/128, Mv/128), 256, GSMEM>>>(hinP, wqh, nullptr, nullptr, qhB, QKv, Dv);
    tgemm_kernel<3><<<dim3(QKv/128, Mv/128), 256, GSMEM>>>(hinP, wkh, nullptr, nullptr, khB, QKv, Dv);
    tgemm_kernel<3><<<dim3(Dv/128,  Mv/128), 256, GSMEM>>>(hinP, wvh, nullptr, nullptr, vhB, Dv, Dv);
    tgemm_kernel<0><<<dim3(Dv/128,  Mv/128), 256, GSMEM>>>(hinP, wogh, nullptr, opre, nullptr, Dv, Dv);

    gates_kernel<<<Mv, 256>>>(hin, w_ig, b_ig, w_fg, b_fg, ipre, fpre);
    scan_kernel<<<BHv, 1024>>>(ipre, fpre, ab, Gb, nfl);
    attn_kernel<<<dim3(Sv/64, BHv), 128, ATT_BYTES>>>(qhB, khB, vhB, ab, Gb, nfl, hb);
    headnorm_kernel<<<Mv, 256>>>(hb, opre, mh_w, houtP);

    tgemm_kernel<1><<<dim3(Dv/128, Mv/128), 256, GSMEM>>>(houtP, wouth, x, x1, nullptr, Dv, Dv);

    rmsnorm_kernel<0><<<Mv, 256>>>(x1, norm2_w, nullptr, h2P);

    tgemm_kernel<0><<<dim3(FFv/128, Mv/128), 256, GSMEM>>>(h2P, wgh, nullptr, gate, nullptr, FFv, Dv);
    tgemm_kernel<2><<<dim3(FFv/128, Mv/128), 256, GSMEM>>>(h2P, wuh, gate, nullptr, actP, FFv, Dv);

    tgemm_kernel<1><<<dim3(Dv/128, Mv/128), 256, GSMEM>>>(actP, wdh, x1, out, nullptr, Dv, FFv);

    (void)in_sizes; (void)n_in; (void)out_size;
}

// round 8
// speedup vs baseline: 6.8518x; 1.1495x over previous
#include <cuda_runtime.h>
#include <cuda_fp16.h>
#include <math.h>
#include <stdint.h>

// ---------------------------------------------------------------------------
// BolmoLocalLayer: xLSTM mixer + SwiGLU MLP.  B=2, S=2048, D=2048, H=8.
// Round 8: 1-pass fp16 HMMA GEMMs with 256x128 CTA tile (64x64 warp tile) +
// HMMA flash-style mLSTM attention.
// ---------------------------------------------------------------------------

#define Bv   2
#define Sv   2048
#define Dv   2048
#define Hv   8
#define QKv  1024
#define DQK  128
#define DVv  256
#define FFv  8192
#define Mv   (Bv*Sv)      // 4096
#define BHv  (Bv*Hv)      // 16

// ----------------------------- fp32 scratch --------------------------------
#define F_HIN   ((size_t)0)
#define F_OPRE  (F_HIN  + (size_t)Mv*Dv)
#define F_H     (F_OPRE + (size_t)Mv*Dv)
#define F_X1    (F_H    + (size_t)Mv*Dv)
#define F_GATE  (F_X1   + (size_t)Mv*Dv)
#define F_IPRE  (F_GATE + (size_t)Mv*FFv)
#define F_FPRE  (F_IPRE + (size_t)BHv*Sv)
#define F_A     (F_FPRE + (size_t)BHv*Sv)
#define F_G     (F_A    + (size_t)BHv*Sv)
#define F_NFL   (F_G    + (size_t)BHv*Sv)
#define F_TOTAL (F_NFL  + (size_t)BHv*Sv)
__device__ __align__(256) float g_f32[F_TOTAL];

// ----------------------------- fp16 scratch --------------------------------
#define P_HIN   ((size_t)0)
#define P_HOUT  (P_HIN   + (size_t)Mv*Dv)
#define P_H2    (P_HOUT  + (size_t)Mv*Dv)
#define P_ACT   (P_H2    + (size_t)Mv*Dv)
#define P_WQ    (P_ACT   + (size_t)Mv*FFv)
#define P_WK    (P_WQ    + (size_t)QKv*Dv)
#define P_WV    (P_WK    + (size_t)QKv*Dv)
#define P_WOG   (P_WV    + (size_t)Dv*Dv)
#define P_WOUT  (P_WOG   + (size_t)Dv*Dv)
#define P_WG    (P_WOUT  + (size_t)Dv*Dv)
#define P_WU    (P_WG    + (size_t)FFv*Dv)
#define P_WD    (P_WU    + (size_t)FFv*Dv)
#define P_QH    (P_WD    + (size_t)Dv*FFv)
#define P_KH    (P_QH    + (size_t)Mv*QKv)
#define P_VH    (P_KH    + (size_t)Mv*QKv)
#define P_TOTAL (P_VH    + (size_t)Mv*Dv)
__device__ __align__(256) __half g_fp16[P_TOTAL];

// ----------------------------- helpers -------------------------------------
__device__ __forceinline__ uint32_t smem_u32(const void* p) {
    uint32_t a;
    asm("{ .reg .u64 t; cvta.to.shared.u64 t, %1; cvt.u32.u64 %0, t; }"
        : "=r"(a) : "l"(p));
    return a;
}

__device__ __forceinline__ void cp16(uint32_t sa, const void* g) {
    asm volatile("cp.async.ca.shared.global [%0], [%1], 16;"
                 :: "r"(sa), "l"(g) : "memory");
}
#define CP_COMMIT() asm volatile("cp.async.commit_group;" ::: "memory")
#define CP_WAIT1()  asm volatile("cp.async.wait_group 1;" ::: "memory")
#define CP_WAIT0()  asm volatile("cp.async.wait_group 0;" ::: "memory")

__device__ __forceinline__ void ldsm4(uint32_t* r, uint32_t addr) {
    asm volatile("ldmatrix.sync.aligned.m8n8.x4.shared.b16 {%0,%1,%2,%3}, [%4];"
                 : "=r"(r[0]), "=r"(r[1]), "=r"(r[2]), "=r"(r[3]) : "r"(addr));
}
__device__ __forceinline__ void ldsm4t(uint32_t* r, uint32_t addr) {
    asm volatile("ldmatrix.sync.aligned.m8n8.x4.trans.shared.b16 {%0,%1,%2,%3}, [%4];"
                 : "=r"(r[0]), "=r"(r[1]), "=r"(r[2]), "=r"(r[3]) : "r"(addr));
}

__device__ __forceinline__ void mma16816(float* c, const uint32_t* a,
                                         uint32_t b0, uint32_t b1) {
    asm volatile(
        "mma.sync.aligned.m16n8k16.row.col.f32.f16.f16.f32 "
        "{%0,%1,%2,%3}, {%4,%5,%6,%7}, {%8,%9}, {%0,%1,%2,%3};"
        : "+f"(c[0]), "+f"(c[1]), "+f"(c[2]), "+f"(c[3])
        : "r"(a[0]), "r"(a[1]), "r"(a[2]), "r"(a[3]), "r"(b0), "r"(b1));
}

// --------------------------- HMMA GEMM (1-pass fp16) ------------------------
// C[M, N] = epilogue(A @ W).  A: fp16 [M][K] K-major.  M % 256 == 0.
// W: fp16 pre-transposed [N][K] K-major.
// CTA tile 256x128, warp tile 64x64 (wm 0..3, wn 0..1).
// EPI 0: C fp32 = acc.   EPI 1: C fp32 = aux + acc.
// EPI 2: CH fp16 = silu(aux) * acc.   EPI 3: CH fp16 = acc.
#define KCH    64
#define RSTRB  144
#define ATILEB (256*RSTRB)              // 36864
#define BTILEB (128*RSTRB)              // 18432
#define NSTG   3
#define STAGEB (ATILEB + BTILEB)        // 55296
#define GSMEM  (NSTG*STAGEB)            // 165888

template<int EPI>
__global__ void __launch_bounds__(256) tgemm_kernel(
    const __half* __restrict__ AH, const __half* __restrict__ BH,
    const float* __restrict__ aux, float* __restrict__ C,
    __half* __restrict__ CH, int N, int K)
{
    extern __shared__ char smem[];
    const uint32_t sb = smem_u32(smem);
    const int tid = threadIdx.x;
    const int lane = tid & 31;
    const int wid = tid >> 5;
    const int wm = wid & 3;           // 64-row group
    const int wn = wid >> 2;          // 64-col group
    const int m0 = blockIdx.y * 256;
    const int n0 = blockIdx.x * 128;

    const __half* srcA = AH + (size_t)m0 * K;
    const __half* srcB = BH + (size_t)n0 * K;

    float acc[4][8][4];
    #pragma unroll
    for (int i = 0; i < 4; i++)
        #pragma unroll
        for (int j = 0; j < 8; j++)
            #pragma unroll
            for (int e = 0; e < 4; e++) acc[i][j][e] = 0.f;

    const int NC = K / KCH;

    auto load_chunk = [&](int c, int s) {
        const __half* ga = srcA + c * KCH;
        uint32_t abase = sb + (uint32_t)(s * STAGEB);
        #pragma unroll
        for (int i = 0; i < 8; i++) {
            int seg = tid + 256 * i;              // 0..2047  (256 rows x 8)
            int row = seg >> 3, s8 = seg & 7;
            cp16(abase + (uint32_t)(row * RSTRB + s8 * 16),
                 ga + (size_t)row * K + s8 * 8);
        }
        const __half* gb = srcB + c * KCH;
        uint32_t bbase = abase + ATILEB;
        #pragma unroll
        for (int i = 0; i < 4; i++) {
            int seg = tid + 256 * i;              // 0..1023  (128 rows x 8)
            int row = seg >> 3, s8 = seg & 7;
            cp16(bbase + (uint32_t)(row * RSTRB + s8 * 16),
                 gb + (size_t)row * K + s8 * 8);
        }
    };

    load_chunk(0, 0); CP_COMMIT();
    load_chunk(1, 1); CP_COMMIT();

    const int a_r = (lane & 15);
    const int a_k = (lane >> 4) * 8;
    const int b_r = (lane & 7) + (lane >> 4) * 8;
    const int b_k = ((lane >> 3) & 1) * 8;

    for (int c = 0; c < NC; c++) {
        const int s = c % NSTG;
        if (c + 1 < NC) CP_WAIT1(); else CP_WAIT0();
        __syncthreads();
        if (c + 2 < NC) { load_chunk(c + 2, (c + 2) % NSTG); CP_COMMIT(); }

        const uint32_t bA = sb + s * STAGEB;
        const uint32_t bB = bA + ATILEB;

        #pragma unroll
        for (int kk = 0; kk < KCH; kk += 16) {
            uint32_t aH[4][4], bf[4][4];
            #pragma unroll
            for (int mt = 0; mt < 4; mt++) {
                int row = wm * 64 + mt * 16 + a_r;
                ldsm4(aH[mt], bA + (uint32_t)(row * RSTRB + (kk + a_k) * 2));
            }
            #pragma unroll
            for (int j = 0; j < 4; j++) {
                int row = wn * 64 + j * 16 + b_r;
                ldsm4(bf[j], bB + (uint32_t)(row * RSTRB + (kk + b_k) * 2));
            }
            #pragma unroll
            for (int mt = 0; mt < 4; mt++)
                #pragma unroll
                for (int j = 0; j < 4; j++) {
                    mma16816(acc[mt][2*j],   aH[mt], bf[j][0], bf[j][1]);
                    mma16816(acc[mt][2*j+1], aH[mt], bf[j][2], bf[j][3]);
                }
        }
    }

    const int mrow = m0 + wm * 64;
    const int ncol = n0 + wn * 64;
    #pragma unroll
    for (int mt = 0; mt < 4; mt++) {
        #pragma unroll
        for (int nt = 0; nt < 8; nt++) {
            int r0 = mrow + mt * 16 + (lane >> 2);
            int r1 = r0 + 8;
            int cc = ncol + nt * 8 + (lane & 3) * 2;
            float* a = acc[mt][nt];
            size_t i0 = (size_t)r0 * N + cc;
            size_t i1 = (size_t)r1 * N + cc;
            if (EPI == 0) {
                *(float2*)(C + i0) = make_float2(a[0], a[1]);
                *(float2*)(C + i1) = make_float2(a[2], a[3]);
            } else if (EPI == 1) {
                float2 x0 = *(const float2*)(aux + i0);
                float2 x1 = *(const float2*)(aux + i1);
                *(float2*)(C + i0) = make_float2(a[0] + x0.x, a[1] + x0.y);
                *(float2*)(C + i1) = make_float2(a[2] + x1.x, a[3] + x1.y);
            } else if (EPI == 2) {
                float2 g0 = *(const float2*)(aux + i0);
                float2 g1 = *(const float2*)(aux + i1);
                float v00 = a[0] * (g0.x / (1.f + __expf(-g0.x)));
                float v01 = a[1] * (g0.y / (1.f + __expf(-g0.y)));
                float v10 = a[2] * (g1.x / (1.f + __expf(-g1.x)));
                float v11 = a[3] * (g1.y / (1.f + __expf(-g1.y)));
                *(__half2*)(CH + i0) = __floats2half2_rn(v00, v01);
                *(__half2*)(CH + i1) = __floats2half2_rn(v10, v11);
            } else {
                *(__half2*)(CH + i0) = __floats2half2_rn(a[0], a[1]);
                *(__half2*)(CH + i1) = __floats2half2_rn(a[2], a[3]);
            }
        }
    }
}

// ---------------- weight transpose -> fp16 ---------------------------------
__global__ void wsplit_kernel(const float* __restrict__ W,
                              __half* __restrict__ TH, int K, int N)
{
    __shared__ float t[32][33];
    int tx = threadIdx.x, ty = threadIdx.y;
    int n0 = blockIdx.x * 32, k0 = blockIdx.y * 32;
    #pragma unroll
    for (int j = 0; j < 4; j++)
        t[ty + 8 * j][tx] = W[(size_t)(k0 + ty + 8 * j) * N + n0 + tx];
    __syncthreads();
    #pragma unroll
    for (int j = 0; j < 4; j++) {
        float v = t[tx][ty + 8 * j];
        TH[(size_t)(n0 + ty + 8 * j) * K + k0 + tx] = __float2half_rn(v);
    }
}

// --------------------------- RMSNorm (-> fp16, optional fp32) ---------------
template<int WRITE_F32>
__global__ void rmsnorm_kernel(const float* __restrict__ x, const float* __restrict__ w,
                               float* __restrict__ out, __half* __restrict__ oh)
{
    int row = blockIdx.x;
    int tid = threadIdx.x;
    const float4* xr = (const float4*)(x + (size_t)row * Dv);
    float4 v0 = xr[tid];
    float4 v1 = xr[tid + 256];
    float ss = v0.x*v0.x + v0.y*v0.y + v0.z*v0.z + v0.w*v0.w
             + v1.x*v1.x + v1.y*v1.y + v1.z*v1.z + v1.w*v1.w;
    #pragma unroll
    for (int o = 16; o > 0; o >>= 1) ss += __shfl_xor_sync(0xffffffffu, ss, o);
    __shared__ float red[8];
    int wp = tid >> 5, lane = tid & 31;
    if (lane == 0) red[wp] = ss;
    __syncthreads();
    float tot = 0.f;
    #pragma unroll
    for (int i = 0; i < 8; i++) tot += red[i];
    float inv = rsqrtf(tot * (1.f / Dv) + 1e-6f);
    const float4* wr = (const float4*)w;
    #pragma unroll
    for (int half_ = 0; half_ < 2; half_++) {
        float4 v = half_ ? v1 : v0;
        float4 ww = wr[tid + 256 * half_];
        float r[4] = { v.x*inv*ww.x, v.y*inv*ww.y, v.z*inv*ww.z, v.w*inv*ww.w };
        size_t idx = (size_t)row * Dv + (tid + 256 * half_) * 4;
        if (WRITE_F32) *(float4*)(out + idx) = make_float4(r[0], r[1], r[2], r[3]);
        __half2 h0 = __floats2half2_rn(r[0], r[1]);
        __half2 h1 = __floats2half2_rn(r[2], r[3]);
        *(__half2*)(oh + idx) = h0;
        *(__half2*)(oh + idx + 2) = h1;
    }
}

// --------------------------- i/f gate projections ---------------------------
__device__ __forceinline__ float softcap15(float x) {
    return 15.f * tanhf(x * (1.f / 15.f));
}

__global__ void gates_kernel(const float* __restrict__ hin,
                             const float* __restrict__ w_ig, const float* __restrict__ b_ig,
                             const float* __restrict__ w_fg, const float* __restrict__ b_fg,
                             float* __restrict__ ipre, float* __restrict__ fpre)
{
    int row = blockIdx.x;
    int tid = threadIdx.x;
    float pi[8], pf[8];
    #pragma unroll
    for (int h = 0; h < 8; h++) { pi[h] = 0.f; pf[h] = 0.f; }
    const float* xr = hin + (size_t)row * Dv;
    for (int d = tid; d < Dv; d += 256) {
        float xv = xr[d];
        #pragma unroll
        for (int h = 0; h < 8; h++) {
            pi[h] += xv * w_ig[d * 8 + h];
            pf[h] += xv * w_fg[d * 8 + h];
        }
    }
    #pragma unroll
    for (int h = 0; h < 8; h++) {
        #pragma unroll
        for (int o = 16; o > 0; o >>= 1) {
            pi[h] += __shfl_xor_sync(0xffffffffu, pi[h], o);
            pf[h] += __shfl_xor_sync(0xffffffffu, pf[h], o);
        }
    }
    __shared__ float sred[8][16];
    int wp = tid >> 5, lane = tid & 31;
    if (lane == 0) {
        #pragma unroll
        for (int h = 0; h < 8; h++) { sred[wp][h] = pi[h]; sred[wp][8 + h] = pf[h]; }
    }
    __syncthreads();
    if (tid < 16) {
        float s = 0.f;
        #pragma unroll
        for (int w8 = 0; w8 < 8; w8++) s += sred[w8][tid];
        int h = tid & 7;
        bool isf = (tid >= 8);
        float bias = isf ? b_fg[h] : b_ig[h];
        float val = softcap15(s + bias);
        int b = row >> 11;
        int sp = row & (Sv - 1);
        int bh = b * Hv + h;
        (isf ? fpre : ipre)[bh * Sv + sp] = val;
    }
}

// --------------------------- gate scans ------------------------------------
__global__ void scan_kernel(const float* __restrict__ ipre, const float* __restrict__ fpre,
                            float* __restrict__ aout, float* __restrict__ Gout,
                            float* __restrict__ nflout)
{
    int bh = blockIdx.x;
    int tid = threadIdx.x;
    __shared__ float bufA[2048], bufB[2048], fc[2048];

    for (int i = tid; i < 2048; i += 1024) {
        float f = fpre[bh * Sv + i];
        bufA[i] = fminf(f, 0.f) - log1pf(expf(-fabsf(f)));
    }
    __syncthreads();
    float* src = bufA; float* dst = bufB;
    for (int off = 1; off < 2048; off <<= 1) {
        for (int i = tid; i < 2048; i += 1024)
            dst[i] = src[i] + ((i >= off) ? src[i - off] : 0.f);
        __syncthreads();
        float* t = src; src = dst; dst = t;
    }
    for (int i = tid; i < 2048; i += 1024) fc[i] = src[i];
    __syncthreads();
    for (int i = tid; i < 2048; i += 1024) {
        float a = ipre[bh * Sv + i] - fc[i];
        aout[bh * Sv + i] = a;
        dst[i] = a;
    }
    __syncthreads();
    { float* t = src; src = dst; dst = t; }
    for (int off = 1; off < 2048; off <<= 1) {
        for (int i = tid; i < 2048; i += 1024)
            dst[i] = fmaxf(src[i], (i >= off) ? src[i - off] : -1e30f);
        __syncthreads();
        float* t = src; src = dst; dst = t;
    }
    for (int i = tid; i < 2048; i += 1024) {
        float G = src[i];
        Gout[bh * Sv + i] = G;
        nflout[bh * Sv + i] = expf(-(fc[i] + G));
    }
}

// --------------------------- HMMA mLSTM attention ---------------------------
#define AQ_STRB 272
#define AV_STRB 528
#define ATT_Q_OFF   0
#define ATT_K_OFF   (64*AQ_STRB)
#define ATT_V_OFF   (ATT_K_OFF + 64*AQ_STRB)
#define ATT_WCOL    (ATT_V_OFF + 64*AV_STRB)
#define ATT_C0      (ATT_WCOL + 2048*4)
#define ATT_GT      (ATT_C0 + 32*4)
#define ATT_NF      (ATT_GT + 64*4)
#define ATT_BYTES   (ATT_NF + 64*4)

__global__ void __launch_bounds__(128, 2) attn_kernel(
    const __half* __restrict__ qh, const __half* __restrict__ kh,
    const __half* __restrict__ vh,
    const float* __restrict__ av, const float* __restrict__ Gv,
    const float* __restrict__ nfv, float* __restrict__ hout)
{
    extern __shared__ char smem[];
    const uint32_t sb = smem_u32(smem);
    float* wcol = (float*)(smem + ATT_WCOL);
    float* c0s  = (float*)(smem + ATT_C0);
    float* gts  = (float*)(smem + ATT_GT);
    float* nfs  = (float*)(smem + ATT_NF);

    const int bh = blockIdx.y;
    const int bb = bh >> 3, hh = bh & 7;
    const int t0 = ((int)gridDim.x - 1 - (int)blockIdx.x) * 64;
    const int tid = threadIdx.x, lane = tid & 31, wid = tid >> 5;
    const int nst = (t0 >> 6) + 1;
    const int nS = t0 + 64;

    const __half* qbase = qh + ((size_t)(bb * Sv + t0)) * QKv + hh * DQK;
    #pragma unroll
    for (int i = 0; i < 8; i++) {
        int seg = tid + 128 * i;
        int row = seg >> 4, s16 = seg & 15;
        cp16(sb + ATT_Q_OFF + (uint32_t)(row * AQ_STRB + s16 * 16),
             qbase + (size_t)row * QKv + s16 * 8);
    }
    CP_COMMIT();

    for (int s = tid; s < nS; s += 128) wcol[s] = av[(size_t)bh * Sv + s];
    if (tid < 64) {
        gts[tid] = Gv[(size_t)bh * Sv + t0 + tid];
        nfs[tid] = nfv[(size_t)bh * Sv + t0 + tid];
    }
    __syncthreads();
    if (tid < nst) {
        float m = -1e30f;
        #pragma unroll 8
        for (int i = 0; i < 64; i++) m = fmaxf(m, wcol[tid * 64 + i]);
        c0s[tid] = m;
    }
    __syncthreads();
    const float invsq = 0.08838834764831845f;
    for (int s = tid; s < nS; s += 128)
        wcol[s] = __expf(wcol[s] - c0s[s >> 6]) * invsq;
    __syncthreads();

    const int qr = lane >> 2;
    const int r0 = wid * 16 + qr, r1 = r0 + 8;
    const float gt0 = gts[r0], gt1 = gts[r1];

    const int a_r = lane & 15, a_k = (lane >> 4) * 8;
    const int b_r = (lane & 7) + (lane >> 4) * 8;
    const int b_k = ((lane >> 3) & 1) * 8;
    const int v_k = (lane & 7) + ((lane >> 3) & 1) * 8;
    const int v_n = (lane >> 4) * 8;

    float acc[32][4];
    #pragma unroll
    for (int f = 0; f < 32; f++)
        #pragma unroll
        for (int e = 0; e < 4; e++) acc[f][e] = 0.f;
    float rsa0 = 0.f, rsa1 = 0.f;

    for (int st = 0; st < nst; st++) {
        const int s0 = st << 6;
        __syncthreads();
        const __half* kbase = kh + ((size_t)(bb * Sv + s0)) * QKv + hh * DQK;
        #pragma unroll
        for (int i = 0; i < 8; i++) {
            int seg = tid + 128 * i;
            int row = seg >> 4, s16 = seg & 15;
            cp16(sb + ATT_K_OFF + (uint32_t)(row * AQ_STRB + s16 * 16),
                 kbase + (size_t)row * QKv + s16 * 8);
        }
        const __half* vbase = vh + ((size_t)(bb * Sv + s0)) * Dv + hh * DVv;
        #pragma unroll
        for (int i = 0; i < 16; i++) {
            int seg = tid + 128 * i;
            int row = seg >> 5, s16 = seg & 31;
            cp16(sb + ATT_V_OFF + (uint32_t)(row * AV_STRB + s16 * 16),
                 vbase + (size_t)row * Dv + s16 * 8);
        }
        CP_COMMIT(); CP_WAIT0();
        __syncthreads();

        float sc[8][4];
        #pragma unroll
        for (int j = 0; j < 8; j++)
            #pragma unroll
            for (int e = 0; e < 4; e++) sc[j][e] = 0.f;
        #pragma unroll
        for (int ks16 = 0; ks16 < 8; ks16++) {
            uint32_t aq[4];
            ldsm4(aq, sb + ATT_Q_OFF +
                  (uint32_t)((wid * 16 + a_r) * AQ_STRB + (ks16 * 16 + a_k) * 2));
            #pragma unroll
            for (int j2 = 0; j2 < 4; j2++) {
                uint32_t bk[4];
                ldsm4(bk, sb + ATT_K_OFF +
                      (uint32_t)((j2 * 16 + b_r) * AQ_STRB + (ks16 * 16 + b_k) * 2));
                mma16816(sc[2*j2],   aq, bk[0], bk[1]);
                mma16816(sc[2*j2+1], aq, bk[2], bk[3]);
            }
        }

        const float w0 = __expf(fminf(c0s[st] - gt0, 80.f));
        const float w1 = __expf(fminf(c0s[st] - gt1, 80.f));
        const bool diag = (st == nst - 1);
        const int tg0 = t0 + r0, tg1 = t0 + r1;
        uint32_t pa[8][2];
        #pragma unroll
        for (int j = 0; j < 8; j++) {
            int cb = s0 + j * 8 + 2 * (lane & 3);
            float wc0 = wcol[cb];
            float wc1 = wcol[cb + 1];
            float v00 = sc[j][0] * wc0 * w0, v01 = sc[j][1] * wc1 * w0;
            float v10 = sc[j][2] * wc0 * w1, v11 = sc[j][3] * wc1 * w1;
            if (diag) {
                if (cb     > tg0) v00 = 0.f;
                if (cb + 1 > tg0) v01 = 0.f;
                if (cb     > tg1) v10 = 0.f;
                if (cb + 1 > tg1) v11 = 0.f;
            }
            rsa0 += v00 + v01;
            rsa1 += v10 + v11;
            __half2 h0 = __floats2half2_rn(v00, v01);
            __half2 h1 = __floats2half2_rn(v10, v11);
            pa[j][0] = *(uint32_t*)&h0;
            pa[j][1] = *(uint32_t*)&h1;
        }

        #pragma unroll
        for (int kst = 0; kst < 4; kst++) {
            uint32_t af[4] = { pa[2*kst][0], pa[2*kst][1],
                               pa[2*kst+1][0], pa[2*kst+1][1] };
            #pragma unroll
            for (int n16 = 0; n16 < 16; n16++) {
                uint32_t bv[4];
                ldsm4t(bv, sb + ATT_V_OFF +
                       (uint32_t)((kst * 16 + v_k) * AV_STRB + (n16 * 16 + v_n) * 2));
                mma16816(acc[2*n16],   af, bv[0], bv[1]);
                mma16816(acc[2*n16+1], af, bv[2], bv[3]);
            }
        }
    }

    rsa0 += __shfl_xor_sync(0xffffffffu, rsa0, 1);
    rsa0 += __shfl_xor_sync(0xffffffffu, rsa0, 2);
    rsa1 += __shfl_xor_sync(0xffffffffu, rsa1, 1);
    rsa1 += __shfl_xor_sync(0xffffffffu, rsa1, 2);

    const float invn0 = 1.f / fmaxf(fabsf(rsa0), nfs[r0]);
    const float invn1 = 1.f / fmaxf(fabsf(rsa1), nfs[r1]);
    float* ho0 = hout + ((size_t)(bb * Sv + t0 + r0)) * Dv + hh * DVv;
    float* ho1 = hout + ((size_t)(bb * Sv + t0 + r1)) * Dv + hh * DVv;
    #pragma unroll
    for (int f = 0; f < 32; f++) {
        int col = f * 8 + 2 * (lane & 3);
        *(float2*)(ho0 + col) = make_float2(acc[f][0] * invn0, acc[f][1] * invn0);
        *(float2*)(ho1 + col) = make_float2(acc[f][2] * invn1, acc[f][3] * invn1);
    }
}

// ----------------- per-head RMSNorm + output gate (-> fp16) ----------------
__global__ void headnorm_kernel(const float* __restrict__ h, const float* __restrict__ opre,
                                const float* __restrict__ mh_w,
                                __half* __restrict__ oh)
{
    int row = blockIdx.x;
    int tid = threadIdx.x;
    int wp = tid >> 5, lane = tid & 31;
    const float* hr = h + (size_t)row * Dv + wp * DVv;
    float vv[8];
    float ss = 0.f;
    #pragma unroll
    for (int j = 0; j < 8; j++) { vv[j] = hr[lane + 32 * j]; ss += vv[j] * vv[j]; }
    #pragma unroll
    for (int o = 16; o > 0; o >>= 1) ss += __shfl_xor_sync(0xffffffffu, ss, o);
    float inv = rsqrtf(ss * (1.f / DVv) + 1e-6f);
    const float* op = opre + (size_t)row * Dv + wp * DVv;
    const float* mw = mh_w + wp * DVv;
    __half* outh = oh + (size_t)row * Dv + wp * DVv;
    #pragma unroll
    for (int j = 0; j < 8; j++) {
        int c = lane + 32 * j;
        float o = op[c];
        float sg = 1.f / (1.f + expf(-o));
        outh[c] = __float2half_rn(sg * vv[j] * inv * mw[c]);
    }
}

// --------------------------- launch ----------------------------------------
extern "C" void kernel_launch(void* const* d_in, const int* in_sizes, int n_in,
                              void* d_out, int out_size)
{
    const float* x       = (const float*)d_in[0];
    const float* norm1_w = (const float*)d_in[1];
    const float* wq      = (const float*)d_in[2];
    const float* wk      = (const float*)d_in[3];
    const float* wv      = (const float*)d_in[4];
    const float* w_ig    = (const float*)d_in[5];
    const float* b_ig    = (const float*)d_in[6];
    const float* w_fg    = (const float*)d_in[7];
    const float* b_fg    = (const float*)d_in[8];
    const float* w_og    = (const float*)d_in[9];
    const float* mh_w    = (const float*)d_in[10];
    const float* w_out   = (const float*)d_in[11];
    const float* norm2_w = (const float*)d_in[12];
    const float* w_gate  = (const float*)d_in[13];
    const float* w_up    = (const float*)d_in[14];
    const float* w_down  = (const float*)d_in[15];
    float* out = (float*)d_out;

    void* fp = nullptr; cudaGetSymbolAddress(&fp, g_f32);
    void* hp = nullptr; cudaGetSymbolAddress(&hp, g_fp16);
    float* F = (float*)fp;
    __half* Hh = (__half*)hp;

    float *hin = F+F_HIN, *opre = F+F_OPRE, *hb = F+F_H, *x1 = F+F_X1, *gate = F+F_GATE;
    float *ipre = F+F_IPRE, *fpre = F+F_FPRE, *ab = F+F_A, *Gb = F+F_G, *nfl = F+F_NFL;

    __half *hinP=Hh+P_HIN, *houtP=Hh+P_HOUT, *h2P=Hh+P_H2, *actP=Hh+P_ACT;
    __half *wqh=Hh+P_WQ, *wkh=Hh+P_WK, *wvh=Hh+P_WV, *wogh=Hh+P_WOG;
    __half *wouth=Hh+P_WOUT, *wgh=Hh+P_WG, *wuh=Hh+P_WU, *wdh=Hh+P_WD;
    __half *qhB=Hh+P_QH, *khB=Hh+P_KH, *vhB=Hh+P_VH;

    cudaFuncSetAttribute(attn_kernel, cudaFuncAttributeMaxDynamicSharedMemorySize, ATT_BYTES);
    cudaFuncSetAttribute(tgemm_kernel<0>, cudaFuncAttributeMaxDynamicSharedMemorySize, GSMEM);
    cudaFuncSetAttribute(tgemm_kernel<1>, cudaFuncAttributeMaxDynamicSharedMemorySize, GSMEM);
    cudaFuncSetAttribute(tgemm_kernel<2>, cudaFuncAttributeMaxDynamicSharedMemorySize, GSMEM);
    cudaFuncSetAttribute(tgemm_kernel<3>, cudaFuncAttributeMaxDynamicSharedMemorySize, GSMEM);

    dim3 tb(32, 8);
    wsplit_kernel<<<dim3(QKv/32, Dv/32), tb>>>(wq, wqh, Dv, QKv);
    wsplit_kernel<<<dim3(QKv/32, Dv/32), tb>>>(wk, wkh, Dv, QKv);
    wsplit_kernel<<<dim3(Dv/32,  Dv/32), tb>>>(wv, wvh, Dv, Dv);
    wsplit_kernel<<<dim3(Dv/32,  Dv/32), tb>>>(w_og, wogh, Dv, Dv);
    wsplit_kernel<<<dim3(Dv/32,  Dv/32), tb>>>(w_out, wouth, Dv, Dv);
    wsplit_kernel<<<dim3(FFv/32, Dv/32), tb>>>(w_gate, wgh, Dv, FFv);
    wsplit_kernel<<<dim3(FFv/32, Dv/32), tb>>>(w_up, wuh, Dv, FFv);
    wsplit_kernel<<<dim3(Dv/32, FFv/32), tb>>>(w_down, wdh, FFv, Dv);

    rmsnorm_kernel<1><<<Mv, 256>>>(x, norm1_w, hin, hinP);

    tgemm_kernel<3><<<dim3(QKv/128, Mv/256), 256, GSMEM>>>(hinP, wqh, nullptr, nullptr, qhB, QKv, Dv);
    tgemm_kernel<3><<<dim3(QKv/128, Mv/256), 256, GSMEM>>>(hinP, wkh, nullptr, nullptr, khB, QKv, Dv);
    tgemm_kernel<3><<<dim3(Dv/128,  Mv/256), 256, GSMEM>>>(hinP, wvh, nullptr, nullptr, vhB, Dv, Dv);
    tgemm_kernel<0><<<dim3(Dv/128,  Mv/256), 256, GSMEM>>>(hinP, wogh, nullptr, opre, nullptr, Dv, Dv);

    gates_kernel<<<Mv, 256>>>(hin, w_ig, b_ig, w_fg, b_fg, ipre, fpre);
    scan_kernel<<<BHv, 1024>>>(ipre, fpre, ab, Gb, nfl);
    attn_kernel<<<dim3(Sv/64, BHv), 128, ATT_BYTES>>>(qhB, khB, vhB, ab, Gb, nfl, hb);
    headnorm_kernel<<<Mv, 256>>>(hb, opre, mh_w, houtP);

    tgemm_kernel<1><<<dim3(Dv/128, Mv/256), 256, GSMEM>>>(houtP, wouth, x, x1, nullptr, Dv, Dv);

    rmsnorm_kernel<0><<<Mv, 256>>>(x1, norm2_w, nullptr, h2P);

    tgemm_kernel<0><<<dim3(FFv/128, Mv/256), 256, GSMEM>>>(h2P, wgh, nullptr, gate, nullptr, FFv, Dv);
    tgemm_kernel<2><<<dim3(FFv/128, Mv/256), 256, GSMEM>>>(h2P, wuh, gate, nullptr, actP, FFv, Dv);

    tgemm_kernel<1><<<dim3(Dv/128, Mv/256), 256, GSMEM>>>(actP, wdh, x1, out, nullptr, Dv, FFv);

    (void)in_sizes; (void)n_in; (void)out_size;
}

// round 9
// speedup vs baseline: 7.1204x; 1.0392x over previous
#include <cuda_runtime.h>
#include <cuda_fp16.h>
#include <math.h>
#include <stdint.h>

// ---------------------------------------------------------------------------
// BolmoLocalLayer: xLSTM mixer + SwiGLU MLP.  B=2, S=2048, D=2048, H=8.
// Round 9: R8 kernels + multi-stream overlap (wsplit / gates+scan / og GEMM
// run concurrently with the main chain via capturable fork-join events).
// ---------------------------------------------------------------------------

#define Bv   2
#define Sv   2048
#define Dv   2048
#define Hv   8
#define QKv  1024
#define DQK  128
#define DVv  256
#define FFv  8192
#define Mv   (Bv*Sv)      // 4096
#define BHv  (Bv*Hv)      // 16

// ----------------------------- fp32 scratch --------------------------------
#define F_HIN   ((size_t)0)
#define F_OPRE  (F_HIN  + (size_t)Mv*Dv)
#define F_H     (F_OPRE + (size_t)Mv*Dv)
#define F_X1    (F_H    + (size_t)Mv*Dv)
#define F_GATE  (F_X1   + (size_t)Mv*Dv)
#define F_IPRE  (F_GATE + (size_t)Mv*FFv)
#define F_FPRE  (F_IPRE + (size_t)BHv*Sv)
#define F_A     (F_FPRE + (size_t)BHv*Sv)
#define F_G     (F_A    + (size_t)BHv*Sv)
#define F_NFL   (F_G    + (size_t)BHv*Sv)
#define F_TOTAL (F_NFL  + (size_t)BHv*Sv)
__device__ __align__(256) float g_f32[F_TOTAL];

// ----------------------------- fp16 scratch --------------------------------
#define P_HIN   ((size_t)0)
#define P_HOUT  (P_HIN   + (size_t)Mv*Dv)
#define P_H2    (P_HOUT  + (size_t)Mv*Dv)
#define P_ACT   (P_H2    + (size_t)Mv*Dv)
#define P_WQ    (P_ACT   + (size_t)Mv*FFv)
#define P_WK    (P_WQ    + (size_t)QKv*Dv)
#define P_WV    (P_WK    + (size_t)QKv*Dv)
#define P_WOG   (P_WV    + (size_t)Dv*Dv)
#define P_WOUT  (P_WOG   + (size_t)Dv*Dv)
#define P_WG    (P_WOUT  + (size_t)Dv*Dv)
#define P_WU    (P_WG    + (size_t)FFv*Dv)
#define P_WD    (P_WU    + (size_t)FFv*Dv)
#define P_QH    (P_WD    + (size_t)Dv*FFv)
#define P_KH    (P_QH    + (size_t)Mv*QKv)
#define P_VH    (P_KH    + (size_t)Mv*QKv)
#define P_TOTAL (P_VH    + (size_t)Mv*Dv)
__device__ __align__(256) __half g_fp16[P_TOTAL];

// ----------------------------- helpers -------------------------------------
__device__ __forceinline__ uint32_t smem_u32(const void* p) {
    uint32_t a;
    asm("{ .reg .u64 t; cvta.to.shared.u64 t, %1; cvt.u32.u64 %0, t; }"
        : "=r"(a) : "l"(p));
    return a;
}

__device__ __forceinline__ void cp16(uint32_t sa, const void* g) {
    asm volatile("cp.async.ca.shared.global [%0], [%1], 16;"
                 :: "r"(sa), "l"(g) : "memory");
}
#define CP_COMMIT() asm volatile("cp.async.commit_group;" ::: "memory")
#define CP_WAIT1()  asm volatile("cp.async.wait_group 1;" ::: "memory")
#define CP_WAIT0()  asm volatile("cp.async.wait_group 0;" ::: "memory")

__device__ __forceinline__ void ldsm4(uint32_t* r, uint32_t addr) {
    asm volatile("ldmatrix.sync.aligned.m8n8.x4.shared.b16 {%0,%1,%2,%3}, [%4];"
                 : "=r"(r[0]), "=r"(r[1]), "=r"(r[2]), "=r"(r[3]) : "r"(addr));
}
__device__ __forceinline__ void ldsm4t(uint32_t* r, uint32_t addr) {
    asm volatile("ldmatrix.sync.aligned.m8n8.x4.trans.shared.b16 {%0,%1,%2,%3}, [%4];"
                 : "=r"(r[0]), "=r"(r[1]), "=r"(r[2]), "=r"(r[3]) : "r"(addr));
}

__device__ __forceinline__ void mma16816(float* c, const uint32_t* a,
                                         uint32_t b0, uint32_t b1) {
    asm volatile(
        "mma.sync.aligned.m16n8k16.row.col.f32.f16.f16.f32 "
        "{%0,%1,%2,%3}, {%4,%5,%6,%7}, {%8,%9}, {%0,%1,%2,%3};"
        : "+f"(c[0]), "+f"(c[1]), "+f"(c[2]), "+f"(c[3])
        : "r"(a[0]), "r"(a[1]), "r"(a[2]), "r"(a[3]), "r"(b0), "r"(b1));
}

// --------------------------- HMMA GEMM (1-pass fp16) ------------------------
// CTA tile 256x128, warp tile 64x64 (wm 0..3, wn 0..1).
// EPI 0: C fp32 = acc.   EPI 1: C fp32 = aux + acc.
// EPI 2: CH fp16 = silu(aux) * acc.   EPI 3: CH fp16 = acc.
#define KCH    64
#define RSTRB  144
#define ATILEB (256*RSTRB)
#define BTILEB (128*RSTRB)
#define NSTG   3
#define STAGEB (ATILEB + BTILEB)
#define GSMEM  (NSTG*STAGEB)

template<int EPI>
__global__ void __launch_bounds__(256) tgemm_kernel(
    const __half* __restrict__ AH, const __half* __restrict__ BH,
    const float* __restrict__ aux, float* __restrict__ C,
    __half* __restrict__ CH, int N, int K)
{
    extern __shared__ char smem[];
    const uint32_t sb = smem_u32(smem);
    const int tid = threadIdx.x;
    const int lane = tid & 31;
    const int wid = tid >> 5;
    const int wm = wid & 3;
    const int wn = wid >> 2;
    const int m0 = blockIdx.y * 256;
    const int n0 = blockIdx.x * 128;

    const __half* srcA = AH + (size_t)m0 * K;
    const __half* srcB = BH + (size_t)n0 * K;

    float acc[4][8][4];
    #pragma unroll
    for (int i = 0; i < 4; i++)
        #pragma unroll
        for (int j = 0; j < 8; j++)
            #pragma unroll
            for (int e = 0; e < 4; e++) acc[i][j][e] = 0.f;

    const int NC = K / KCH;

    auto load_chunk = [&](int c, int s) {
        const __half* ga = srcA + c * KCH;
        uint32_t abase = sb + (uint32_t)(s * STAGEB);
        #pragma unroll
        for (int i = 0; i < 8; i++) {
            int seg = tid + 256 * i;
            int row = seg >> 3, s8 = seg & 7;
            cp16(abase + (uint32_t)(row * RSTRB + s8 * 16),
                 ga + (size_t)row * K + s8 * 8);
        }
        const __half* gb = srcB + c * KCH;
        uint32_t bbase = abase + ATILEB;
        #pragma unroll
        for (int i = 0; i < 4; i++) {
            int seg = tid + 256 * i;
            int row = seg >> 3, s8 = seg & 7;
            cp16(bbase + (uint32_t)(row * RSTRB + s8 * 16),
                 gb + (size_t)row * K + s8 * 8);
        }
    };

    load_chunk(0, 0); CP_COMMIT();
    load_chunk(1, 1); CP_COMMIT();

    const int a_r = (lane & 15);
    const int a_k = (lane >> 4) * 8;
    const int b_r = (lane & 7) + (lane >> 4) * 8;
    const int b_k = ((lane >> 3) & 1) * 8;

    for (int c = 0; c < NC; c++) {
        const int s = c % NSTG;
        if (c + 1 < NC) CP_WAIT1(); else CP_WAIT0();
        __syncthreads();
        if (c + 2 < NC) { load_chunk(c + 2, (c + 2) % NSTG); CP_COMMIT(); }

        const uint32_t bA = sb + s * STAGEB;
        const uint32_t bB = bA + ATILEB;

        #pragma unroll
        for (int kk = 0; kk < KCH; kk += 16) {
            uint32_t aH[4][4], bf[4][4];
            #pragma unroll
            for (int mt = 0; mt < 4; mt++) {
                int row = wm * 64 + mt * 16 + a_r;
                ldsm4(aH[mt], bA + (uint32_t)(row * RSTRB + (kk + a_k) * 2));
            }
            #pragma unroll
            for (int j = 0; j < 4; j++) {
                int row = wn * 64 + j * 16 + b_r;
                ldsm4(bf[j], bB + (uint32_t)(row * RSTRB + (kk + b_k) * 2));
            }
            #pragma unroll
            for (int mt = 0; mt < 4; mt++)
                #pragma unroll
                for (int j = 0; j < 4; j++) {
                    mma16816(acc[mt][2*j],   aH[mt], bf[j][0], bf[j][1]);
                    mma16816(acc[mt][2*j+1], aH[mt], bf[j][2], bf[j][3]);
                }
        }
    }

    const int mrow = m0 + wm * 64;
    const int ncol = n0 + wn * 64;
    #pragma unroll
    for (int mt = 0; mt < 4; mt++) {
        #pragma unroll
        for (int nt = 0; nt < 8; nt++) {
            int r0 = mrow + mt * 16 + (lane >> 2);
            int r1 = r0 + 8;
            int cc = ncol + nt * 8 + (lane & 3) * 2;
            float* a = acc[mt][nt];
            size_t i0 = (size_t)r0 * N + cc;
            size_t i1 = (size_t)r1 * N + cc;
            if (EPI == 0) {
                *(float2*)(C + i0) = make_float2(a[0], a[1]);
                *(float2*)(C + i1) = make_float2(a[2], a[3]);
            } else if (EPI == 1) {
                float2 x0 = *(const float2*)(aux + i0);
                float2 x1 = *(const float2*)(aux + i1);
                *(float2*)(C + i0) = make_float2(a[0] + x0.x, a[1] + x0.y);
                *(float2*)(C + i1) = make_float2(a[2] + x1.x, a[3] + x1.y);
            } else if (EPI == 2) {
                float2 g0 = *(const float2*)(aux + i0);
                float2 g1 = *(const float2*)(aux + i1);
                float v00 = a[0] * (g0.x / (1.f + __expf(-g0.x)));
                float v01 = a[1] * (g0.y / (1.f + __expf(-g0.y)));
                float v10 = a[2] * (g1.x / (1.f + __expf(-g1.x)));
                float v11 = a[3] * (g1.y / (1.f + __expf(-g1.y)));
                *(__half2*)(CH + i0) = __floats2half2_rn(v00, v01);
                *(__half2*)(CH + i1) = __floats2half2_rn(v10, v11);
            } else {
                *(__half2*)(CH + i0) = __floats2half2_rn(a[0], a[1]);
                *(__half2*)(CH + i1) = __floats2half2_rn(a[2], a[3]);
            }
        }
    }
}

// ---------------- weight transpose -> fp16 ---------------------------------
__global__ void wsplit_kernel(const float* __restrict__ W,
                              __half* __restrict__ TH, int K, int N)
{
    __shared__ float t[32][33];
    int tx = threadIdx.x, ty = threadIdx.y;
    int n0 = blockIdx.x * 32, k0 = blockIdx.y * 32;
    #pragma unroll
    for (int j = 0; j < 4; j++)
        t[ty + 8 * j][tx] = W[(size_t)(k0 + ty + 8 * j) * N + n0 + tx];
    __syncthreads();
    #pragma unroll
    for (int j = 0; j < 4; j++) {
        float v = t[tx][ty + 8 * j];
        TH[(size_t)(n0 + ty + 8 * j) * K + k0 + tx] = __float2half_rn(v);
    }
}

// --------------------------- RMSNorm (-> fp16, optional fp32) ---------------
template<int WRITE_F32>
__global__ void rmsnorm_kernel(const float* __restrict__ x, const float* __restrict__ w,
                               float* __restrict__ out, __half* __restrict__ oh)
{
    int row = blockIdx.x;
    int tid = threadIdx.x;
    const float4* xr = (const float4*)(x + (size_t)row * Dv);
    float4 v0 = xr[tid];
    float4 v1 = xr[tid + 256];
    float ss = v0.x*v0.x + v0.y*v0.y + v0.z*v0.z + v0.w*v0.w
             + v1.x*v1.x + v1.y*v1.y + v1.z*v1.z + v1.w*v1.w;
    #pragma unroll
    for (int o = 16; o > 0; o >>= 1) ss += __shfl_xor_sync(0xffffffffu, ss, o);
    __shared__ float red[8];
    int wp = tid >> 5, lane = tid & 31;
    if (lane == 0) red[wp] = ss;
    __syncthreads();
    float tot = 0.f;
    #pragma unroll
    for (int i = 0; i < 8; i++) tot += red[i];
    float inv = rsqrtf(tot * (1.f / Dv) + 1e-6f);
    const float4* wr = (const float4*)w;
    #pragma unroll
    for (int half_ = 0; half_ < 2; half_++) {
        float4 v = half_ ? v1 : v0;
        float4 ww = wr[tid + 256 * half_];
        float r[4] = { v.x*inv*ww.x, v.y*inv*ww.y, v.z*inv*ww.z, v.w*inv*ww.w };
        size_t idx = (size_t)row * Dv + (tid + 256 * half_) * 4;
        if (WRITE_F32) *(float4*)(out + idx) = make_float4(r[0], r[1], r[2], r[3]);
        __half2 h0 = __floats2half2_rn(r[0], r[1]);
        __half2 h1 = __floats2half2_rn(r[2], r[3]);
        *(__half2*)(oh + idx) = h0;
        *(__half2*)(oh + idx + 2) = h1;
    }
}

// --------------------------- i/f gate projections ---------------------------
__device__ __forceinline__ float softcap15(float x) {
    return 15.f * tanhf(x * (1.f / 15.f));
}

__global__ void gates_kernel(const float* __restrict__ hin,
                             const float* __restrict__ w_ig, const float* __restrict__ b_ig,
                             const float* __restrict__ w_fg, const float* __restrict__ b_fg,
                             float* __restrict__ ipre, float* __restrict__ fpre)
{
    int row = blockIdx.x;
    int tid = threadIdx.x;
    float pi[8], pf[8];
    #pragma unroll
    for (int h = 0; h < 8; h++) { pi[h] = 0.f; pf[h] = 0.f; }
    const float* xr = hin + (size_t)row * Dv;
    for (int d = tid; d < Dv; d += 256) {
        float xv = xr[d];
        #pragma unroll
        for (int h = 0; h < 8; h++) {
            pi[h] += xv * w_ig[d * 8 + h];
            pf[h] += xv * w_fg[d * 8 + h];
        }
    }
    #pragma unroll
    for (int h = 0; h < 8; h++) {
        #pragma unroll
        for (int o = 16; o > 0; o >>= 1) {
            pi[h] += __shfl_xor_sync(0xffffffffu, pi[h], o);
            pf[h] += __shfl_xor_sync(0xffffffffu, pf[h], o);
        }
    }
    __shared__ float sred[8][16];
    int wp = tid >> 5, lane = tid & 31;
    if (lane == 0) {
        #pragma unroll
        for (int h = 0; h < 8; h++) { sred[wp][h] = pi[h]; sred[wp][8 + h] = pf[h]; }
    }
    __syncthreads();
    if (tid < 16) {
        float s = 0.f;
        #pragma unroll
        for (int w8 = 0; w8 < 8; w8++) s += sred[w8][tid];
        int h = tid & 7;
        bool isf = (tid >= 8);
        float bias = isf ? b_fg[h] : b_ig[h];
        float val = softcap15(s + bias);
        int b = row >> 11;
        int sp = row & (Sv - 1);
        int bh = b * Hv + h;
        (isf ? fpre : ipre)[bh * Sv + sp] = val;
    }
}

// --------------------------- gate scans ------------------------------------
__global__ void scan_kernel(const float* __restrict__ ipre, const float* __restrict__ fpre,
                            float* __restrict__ aout, float* __restrict__ Gout,
                            float* __restrict__ nflout)
{
    int bh = blockIdx.x;
    int tid = threadIdx.x;
    __shared__ float bufA[2048], bufB[2048], fc[2048];

    for (int i = tid; i < 2048; i += 1024) {
        float f = fpre[bh * Sv + i];
        bufA[i] = fminf(f, 0.f) - log1pf(expf(-fabsf(f)));
    }
    __syncthreads();
    float* src = bufA; float* dst = bufB;
    for (int off = 1; off < 2048; off <<= 1) {
        for (int i = tid; i < 2048; i += 1024)
            dst[i] = src[i] + ((i >= off) ? src[i - off] : 0.f);
        __syncthreads();
        float* t = src; src = dst; dst = t;
    }
    for (int i = tid; i < 2048; i += 1024) fc[i] = src[i];
    __syncthreads();
    for (int i = tid; i < 2048; i += 1024) {
        float a = ipre[bh * Sv + i] - fc[i];
        aout[bh * Sv + i] = a;
        dst[i] = a;
    }
    __syncthreads();
    { float* t = src; src = dst; dst = t; }
    for (int off = 1; off < 2048; off <<= 1) {
        for (int i = tid; i < 2048; i += 1024)
            dst[i] = fmaxf(src[i], (i >= off) ? src[i - off] : -1e30f);
        __syncthreads();
        float* t = src; src = dst; dst = t;
    }
    for (int i = tid; i < 2048; i += 1024) {
        float G = src[i];
        Gout[bh * Sv + i] = G;
        nflout[bh * Sv + i] = expf(-(fc[i] + G));
    }
}

// --------------------------- HMMA mLSTM attention ---------------------------
#define AQ_STRB 272
#define AV_STRB 528
#define ATT_Q_OFF   0
#define ATT_K_OFF   (64*AQ_STRB)
#define ATT_V_OFF   (ATT_K_OFF + 64*AQ_STRB)
#define ATT_WCOL    (ATT_V_OFF + 64*AV_STRB)
#define ATT_C0      (ATT_WCOL + 2048*4)
#define ATT_GT      (ATT_C0 + 32*4)
#define ATT_NF      (ATT_GT + 64*4)
#define ATT_BYTES   (ATT_NF + 64*4)

__global__ void __launch_bounds__(128, 2) attn_kernel(
    const __half* __restrict__ qh, const __half* __restrict__ kh,
    const __half* __restrict__ vh,
    const float* __restrict__ av, const float* __restrict__ Gv,
    const float* __restrict__ nfv, float* __restrict__ hout)
{
    extern __shared__ char smem[];
    const uint32_t sb = smem_u32(smem);
    float* wcol = (float*)(smem + ATT_WCOL);
    float* c0s  = (float*)(smem + ATT_C0);
    float* gts  = (float*)(smem + ATT_GT);
    float* nfs  = (float*)(smem + ATT_NF);

    const int bh = blockIdx.y;
    const int bb = bh >> 3, hh = bh & 7;
    const int t0 = ((int)gridDim.x - 1 - (int)blockIdx.x) * 64;
    const int tid = threadIdx.x, lane = tid & 31, wid = tid >> 5;
    const int nst = (t0 >> 6) + 1;
    const int nS = t0 + 64;

    const __half* qbase = qh + ((size_t)(bb * Sv + t0)) * QKv + hh * DQK;
    #pragma unroll
    for (int i = 0; i < 8; i++) {
        int seg = tid + 128 * i;
        int row = seg >> 4, s16 = seg & 15;
        cp16(sb + ATT_Q_OFF + (uint32_t)(row * AQ_STRB + s16 * 16),
             qbase + (size_t)row * QKv + s16 * 8);
    }
    CP_COMMIT();

    for (int s = tid; s < nS; s += 128) wcol[s] = av[(size_t)bh * Sv + s];
    if (tid < 64) {
        gts[tid] = Gv[(size_t)bh * Sv + t0 + tid];
        nfs[tid] = nfv[(size_t)bh * Sv + t0 + tid];
    }
    __syncthreads();
    if (tid < nst) {
        float m = -1e30f;
        #pragma unroll 8
        for (int i = 0; i < 64; i++) m = fmaxf(m, wcol[tid * 64 + i]);
        c0s[tid] = m;
    }
    __syncthreads();
    const float invsq = 0.08838834764831845f;
    for (int s = tid; s < nS; s += 128)
        wcol[s] = __expf(wcol[s] - c0s[s >> 6]) * invsq;
    __syncthreads();

    const int qr = lane >> 2;
    const int r0 = wid * 16 + qr, r1 = r0 + 8;
    const float gt0 = gts[r0], gt1 = gts[r1];

    const int a_r = lane & 15, a_k = (lane >> 4) * 8;
    const int b_r = (lane & 7) + (lane >> 4) * 8;
    const int b_k = ((lane >> 3) & 1) * 8;
    const int v_k = (lane & 7) + ((lane >> 3) & 1) * 8;
    const int v_n = (lane >> 4) * 8;

    float acc[32][4];
    #pragma unroll
    for (int f = 0; f < 32; f++)
        #pragma unroll
        for (int e = 0; e < 4; e++) acc[f][e] = 0.f;
    float rsa0 = 0.f, rsa1 = 0.f;

    for (int st = 0; st < nst; st++) {
        const int s0 = st << 6;
        __syncthreads();
        const __half* kbase = kh + ((size_t)(bb * Sv + s0)) * QKv + hh * DQK;
        #pragma unroll
        for (int i = 0; i < 8; i++) {
            int seg = tid + 128 * i;
            int row = seg >> 4, s16 = seg & 15;
            cp16(sb + ATT_K_OFF + (uint32_t)(row * AQ_STRB + s16 * 16),
                 kbase + (size_t)row * QKv + s16 * 8);
        }
        const __half* vbase = vh + ((size_t)(bb * Sv + s0)) * Dv + hh * DVv;
        #pragma unroll
        for (int i = 0; i < 16; i++) {
            int seg = tid + 128 * i;
            int row = seg >> 5, s16 = seg & 31;
            cp16(sb + ATT_V_OFF + (uint32_t)(row * AV_STRB + s16 * 16),
                 vbase + (size_t)row * Dv + s16 * 8);
        }
        CP_COMMIT(); CP_WAIT0();
        __syncthreads();

        float sc[8][4];
        #pragma unroll
        for (int j = 0; j < 8; j++)
            #pragma unroll
            for (int e = 0; e < 4; e++) sc[j][e] = 0.f;
        #pragma unroll
        for (int ks16 = 0; ks16 < 8; ks16++) {
            uint32_t aq[4];
            ldsm4(aq, sb + ATT_Q_OFF +
                  (uint32_t)((wid * 16 + a_r) * AQ_STRB + (ks16 * 16 + a_k) * 2));
            #pragma unroll
            for (int j2 = 0; j2 < 4; j2++) {
                uint32_t bk[4];
                ldsm4(bk, sb + ATT_K_OFF +
                      (uint32_t)((j2 * 16 + b_r) * AQ_STRB + (ks16 * 16 + b_k) * 2));
                mma16816(sc[2*j2],   aq, bk[0], bk[1]);
                mma16816(sc[2*j2+1], aq, bk[2], bk[3]);
            }
        }

        const float w0 = __expf(fminf(c0s[st] - gt0, 80.f));
        const float w1 = __expf(fminf(c0s[st] - gt1, 80.f));
        const bool diag = (st == nst - 1);
        const int tg0 = t0 + r0, tg1 = t0 + r1;
        uint32_t pa[8][2];
        #pragma unroll
        for (int j = 0; j < 8; j++) {
            int cb = s0 + j * 8 + 2 * (lane & 3);
            float wc0 = wcol[cb];
            float wc1 = wcol[cb + 1];
            float v00 = sc[j][0] * wc0 * w0, v01 = sc[j][1] * wc1 * w0;
            float v10 = sc[j][2] * wc0 * w1, v11 = sc[j][3] * wc1 * w1;
            if (diag) {
                if (cb     > tg0) v00 = 0.f;
                if (cb + 1 > tg0) v01 = 0.f;
                if (cb     > tg1) v10 = 0.f;
                if (cb + 1 > tg1) v11 = 0.f;
            }
            rsa0 += v00 + v01;
            rsa1 += v10 + v11;
            __half2 h0 = __floats2half2_rn(v00, v01);
            __half2 h1 = __floats2half2_rn(v10, v11);
            pa[j][0] = *(uint32_t*)&h0;
            pa[j][1] = *(uint32_t*)&h1;
        }

        #pragma unroll
        for (int kst = 0; kst < 4; kst++) {
            uint32_t af[4] = { pa[2*kst][0], pa[2*kst][1],
                               pa[2*kst+1][0], pa[2*kst+1][1] };
            #pragma unroll
            for (int n16 = 0; n16 < 16; n16++) {
                uint32_t bv[4];
                ldsm4t(bv, sb + ATT_V_OFF +
                       (uint32_t)((kst * 16 + v_k) * AV_STRB + (n16 * 16 + v_n) * 2));
                mma16816(acc[2*n16],   af, bv[0], bv[1]);
                mma16816(acc[2*n16+1], af, bv[2], bv[3]);
            }
        }
    }

    rsa0 += __shfl_xor_sync(0xffffffffu, rsa0, 1);
    rsa0 += __shfl_xor_sync(0xffffffffu, rsa0, 2);
    rsa1 += __shfl_xor_sync(0xffffffffu, rsa1, 1);
    rsa1 += __shfl_xor_sync(0xffffffffu, rsa1, 2);

    const float invn0 = 1.f / fmaxf(fabsf(rsa0), nfs[r0]);
    const float invn1 = 1.f / fmaxf(fabsf(rsa1), nfs[r1]);
    float* ho0 = hout + ((size_t)(bb * Sv + t0 + r0)) * Dv + hh * DVv;
    float* ho1 = hout + ((size_t)(bb * Sv + t0 + r1)) * Dv + hh * DVv;
    #pragma unroll
    for (int f = 0; f < 32; f++) {
        int col = f * 8 + 2 * (lane & 3);
        *(float2*)(ho0 + col) = make_float2(acc[f][0] * invn0, acc[f][1] * invn0);
        *(float2*)(ho1 + col) = make_float2(acc[f][2] * invn1, acc[f][3] * invn1);
    }
}

// ----------------- per-head RMSNorm + output gate (-> fp16) ----------------
__global__ void headnorm_kernel(const float* __restrict__ h, const float* __restrict__ opre,
                                const float* __restrict__ mh_w,
                                __half* __restrict__ oh)
{
    int row = blockIdx.x;
    int tid = threadIdx.x;
    int wp = tid >> 5, lane = tid & 31;
    const float* hr = h + (size_t)row * Dv + wp * DVv;
    float vv[8];
    float ss = 0.f;
    #pragma unroll
    for (int j = 0; j < 8; j++) { vv[j] = hr[lane + 32 * j]; ss += vv[j] * vv[j]; }
    #pragma unroll
    for (int o = 16; o > 0; o >>= 1) ss += __shfl_xor_sync(0xffffffffu, ss, o);
    float inv = rsqrtf(ss * (1.f / DVv) + 1e-6f);
    const float* op = opre + (size_t)row * Dv + wp * DVv;
    const float* mw = mh_w + wp * DVv;
    __half* outh = oh + (size_t)row * Dv + wp * DVv;
    #pragma unroll
    for (int j = 0; j < 8; j++) {
        int c = lane + 32 * j;
        float o = op[c];
        float sg = 1.f / (1.f + expf(-o));
        outh[c] = __float2half_rn(sg * vv[j] * inv * mw[c]);
    }
}

// --------------------------- launch ----------------------------------------
extern "C" void kernel_launch(void* const* d_in, const int* in_sizes, int n_in,
                              void* d_out, int out_size)
{
    const float* x       = (const float*)d_in[0];
    const float* norm1_w = (const float*)d_in[1];
    const float* wq      = (const float*)d_in[2];
    const float* wk      = (const float*)d_in[3];
    const float* wv      = (const float*)d_in[4];
    const float* w_ig    = (const float*)d_in[5];
    const float* b_ig    = (const float*)d_in[6];
    const float* w_fg    = (const float*)d_in[7];
    const float* b_fg    = (const float*)d_in[8];
    const float* w_og    = (const float*)d_in[9];
    const float* mh_w    = (const float*)d_in[10];
    const float* w_out   = (const float*)d_in[11];
    const float* norm2_w = (const float*)d_in[12];
    const float* w_gate  = (const float*)d_in[13];
    const float* w_up    = (const float*)d_in[14];
    const float* w_down  = (const float*)d_in[15];
    float* out = (float*)d_out;

    void* fp = nullptr; cudaGetSymbolAddress(&fp, g_f32);
    void* hp = nullptr; cudaGetSymbolAddress(&hp, g_fp16);
    float* F = (float*)fp;
    __half* Hh = (__half*)hp;

    float *hin = F+F_HIN, *opre = F+F_OPRE, *hb = F+F_H, *x1 = F+F_X1, *gate = F+F_GATE;
    float *ipre = F+F_IPRE, *fpre = F+F_FPRE, *ab = F+F_A, *Gb = F+F_G, *nfl = F+F_NFL;

    __half *hinP=Hh+P_HIN, *houtP=Hh+P_HOUT, *h2P=Hh+P_H2, *actP=Hh+P_ACT;
    __half *wqh=Hh+P_WQ, *wkh=Hh+P_WK, *wvh=Hh+P_WV, *wogh=Hh+P_WOG;
    __half *wouth=Hh+P_WOUT, *wgh=Hh+P_WG, *wuh=Hh+P_WU, *wdh=Hh+P_WD;
    __half *qhB=Hh+P_QH, *khB=Hh+P_KH, *vhB=Hh+P_VH;

    // one-time resources (created OUTSIDE graph capture, on first call)
    static cudaStream_t s1 = nullptr, s2 = nullptr;
    static cudaEvent_t evStart, evH, evW1, evW2, evOg, evScan;
    if (s1 == nullptr) {
        cudaStreamCreateWithFlags(&s1, cudaStreamNonBlocking);
        cudaStreamCreateWithFlags(&s2, cudaStreamNonBlocking);
        cudaEventCreateWithFlags(&evStart, cudaEventDisableTiming);
        cudaEventCreateWithFlags(&evH,     cudaEventDisableTiming);
        cudaEventCreateWithFlags(&evW1,    cudaEventDisableTiming);
        cudaEventCreateWithFlags(&evW2,    cudaEventDisableTiming);
        cudaEventCreateWithFlags(&evOg,    cudaEventDisableTiming);
        cudaEventCreateWithFlags(&evScan,  cudaEventDisableTiming);

        cudaFuncSetAttribute(attn_kernel, cudaFuncAttributeMaxDynamicSharedMemorySize, ATT_BYTES);
        cudaFuncSetAttribute(tgemm_kernel<0>, cudaFuncAttributeMaxDynamicSharedMemorySize, GSMEM);
        cudaFuncSetAttribute(tgemm_kernel<1>, cudaFuncAttributeMaxDynamicSharedMemorySize, GSMEM);
        cudaFuncSetAttribute(tgemm_kernel<2>, cudaFuncAttributeMaxDynamicSharedMemorySize, GSMEM);
        cudaFuncSetAttribute(tgemm_kernel<3>, cudaFuncAttributeMaxDynamicSharedMemorySize, GSMEM);
    }

    dim3 tb(32, 8);

    // fork side streams from capture origin
    cudaEventRecord(evStart, 0);
    cudaStreamWaitEvent(s1, evStart, 0);
    cudaStreamWaitEvent(s2, evStart, 0);

    // s1: small weight transposes (needed by projections)
    wsplit_kernel<<<dim3(QKv/32, Dv/32), tb, 0, s1>>>(wq, wqh, Dv, QKv);
    wsplit_kernel<<<dim3(QKv/32, Dv/32), tb, 0, s1>>>(wk, wkh, Dv, QKv);
    wsplit_kernel<<<dim3(Dv/32,  Dv/32), tb, 0, s1>>>(wv, wvh, Dv, Dv);
    wsplit_kernel<<<dim3(Dv/32,  Dv/32), tb, 0, s1>>>(w_og, wogh, Dv, Dv);
    cudaEventRecord(evW1, s1);

    // s0: pre-norm 1 (concurrent with the small wsplits)
    rmsnorm_kernel<1><<<Mv, 256>>>(x, norm1_w, hin, hinP);
    cudaEventRecord(evH, 0);

    // s2: gate projections + scans (overlap with q/k/v GEMMs)
    cudaStreamWaitEvent(s2, evH, 0);
    gates_kernel<<<Mv, 256, 0, s2>>>(hin, w_ig, b_ig, w_fg, b_fg, ipre, fpre);
    scan_kernel<<<BHv, 1024, 0, s2>>>(ipre, fpre, ab, Gb, nfl);
    cudaEventRecord(evScan, s2);

    // s1: og GEMM concurrent with q/k/v GEMMs on s0
    cudaStreamWaitEvent(s1, evH, 0);
    tgemm_kernel<0><<<dim3(Dv/128, Mv/256), 256, GSMEM, s1>>>(hinP, wogh, nullptr, opre, nullptr, Dv, Dv);
    cudaEventRecord(evOg, s1);
    // s1: big weight transposes (overlap with attention on s0)
    wsplit_kernel<<<dim3(Dv/32,  Dv/32), tb, 0, s1>>>(w_out, wouth, Dv, Dv);
    wsplit_kernel<<<dim3(FFv/32, Dv/32), tb, 0, s1>>>(w_gate, wgh, Dv, FFv);
    wsplit_kernel<<<dim3(FFv/32, Dv/32), tb, 0, s1>>>(w_up, wuh, Dv, FFv);
    wsplit_kernel<<<dim3(Dv/32, FFv/32), tb, 0, s1>>>(w_down, wdh, FFv, Dv);
    cudaEventRecord(evW2, s1);

    // s0: q/k/v projections
    cudaStreamWaitEvent(0, evW1, 0);
    tgemm_kernel<3><<<dim3(QKv/128, Mv/256), 256, GSMEM>>>(hinP, wqh, nullptr, nullptr, qhB, QKv, Dv);
    tgemm_kernel<3><<<dim3(QKv/128, Mv/256), 256, GSMEM>>>(hinP, wkh, nullptr, nullptr, khB, QKv, Dv);
    tgemm_kernel<3><<<dim3(Dv/128,  Mv/256), 256, GSMEM>>>(hinP, wvh, nullptr, nullptr, vhB, Dv, Dv);

    // s0: attention (needs scans + q/k/v)
    cudaStreamWaitEvent(0, evScan, 0);
    attn_kernel<<<dim3(Sv/64, BHv), 128, ATT_BYTES>>>(qhB, khB, vhB, ab, Gb, nfl, hb);

    // s0: head-norm (needs og GEMM) + rest of chain
    cudaStreamWaitEvent(0, evOg, 0);
    headnorm_kernel<<<Mv, 256>>>(hb, opre, mh_w, houtP);

    cudaStreamWaitEvent(0, evW2, 0);
    tgemm_kernel<1><<<dim3(Dv/128, Mv/256), 256, GSMEM>>>(houtP, wouth, x, x1, nullptr, Dv, Dv);

    rmsnorm_kernel<0><<<Mv, 256>>>(x1, norm2_w, nullptr, h2P);

    tgemm_kernel<0><<<dim3(FFv/128, Mv/256), 256, GSMEM>>>(h2P, wgh, nullptr, gate, nullptr, FFv, Dv);
    tgemm_kernel<2><<<dim3(FFv/128, Mv/256), 256, GSMEM>>>(h2P, wuh, gate, nullptr, actP, FFv, Dv);

    tgemm_kernel<1><<<dim3(Dv/128, Mv/256), 256, GSMEM>>>(actP, wdh, x1, out, nullptr, Dv, FFv);

    (void)in_sizes; (void)n_in; (void)out_size;
}